// round 2
// baseline (speedup 1.0000x reference)
#include <cuda_runtime.h>
#include <cuda_bf16.h>

#define Bq 2048
#define Tq 128
#define Nq (Bq*Tq)

// ---------------- scratch (no allocations allowed) ----------------
__device__ float g_air[(size_t)Nq * 32];
__device__ float g_m1 [(size_t)Nq * 32];
__device__ float g_m2 [(size_t)Nq * 32];
__device__ float g_fusion[(size_t)Nq * 64];

__device__ __forceinline__ float fsig(float x) {
    return __fdividef(1.0f, 1.0f + __expf(-x));
}
__device__ __forceinline__ float ftanh(float x) {
    x = fminf(fmaxf(x, -12.0f), 12.0f);
    float e = __expf(-2.0f * x);
    return __fdividef(1.0f - e, 1.0f + e);
}
__device__ __forceinline__ float dot4(float4 a, float4 b) {
    return fmaf(a.x, b.x, fmaf(a.y, b.y, fmaf(a.z, b.z, a.w * b.w)));
}

// ================= GRU: one warp per batch lane =================
template<int KIN>
__device__ __forceinline__ void gru_warp(
    const float* __restrict__ obs_row, int xoff,
    const float* __restrict__ encW, const float* __restrict__ encB,
    const float* __restrict__ Wih,  const float* __restrict__ bih,
    const float* __restrict__ Whh,  const float* __restrict__ bhh,
    float h, float* __restrict__ feat, float* __restrict__ nexth,
    int la, volatile float* sm)
{
    // composed input weights Wc = Wih @ encW, bc = Wih @ encB + bih
    float wc0[KIN], wc1[KIN], wc2[KIN];
    float bc0 = 0.f, bc1 = 0.f, bc2 = 0.f;
    #pragma unroll
    for (int g = 0; g < 3; g++) {
        int j = la + 32 * g;
        float wrow[32];
        const float4* wp = (const float4*)(Wih + j * 32);
        #pragma unroll
        for (int q = 0; q < 8; q++) {
            float4 v = wp[q];
            wrow[q*4+0]=v.x; wrow[q*4+1]=v.y; wrow[q*4+2]=v.z; wrow[q*4+3]=v.w;
        }
        #pragma unroll
        for (int k = 0; k < KIN; k++) {
            float s = 0.0f;
            #pragma unroll
            for (int m = 0; m < 32; m++) s = fmaf(wrow[m], __ldg(encW + m * KIN + k), s);
            if (g == 0) wc0[k] = s; else if (g == 1) wc1[k] = s; else wc2[k] = s;
        }
        float sb = __ldg(bih + j);
        #pragma unroll
        for (int m = 0; m < 32; m++) sb = fmaf(wrow[m], __ldg(encB + m), sb);
        if (g == 0) bc0 = sb; else if (g == 1) bc1 = sb; else bc2 = sb;
    }
    // Whh rows (la, la+32, la+64) in registers
    float wh0[32], wh1[32], wh2[32];
    {
        const float4* p0 = (const float4*)(Whh + (la     ) * 32);
        const float4* p1 = (const float4*)(Whh + (la + 32) * 32);
        const float4* p2 = (const float4*)(Whh + (la + 64) * 32);
        #pragma unroll
        for (int q = 0; q < 8; q++) {
            float4 a=p0[q]; wh0[q*4]=a.x; wh0[q*4+1]=a.y; wh0[q*4+2]=a.z; wh0[q*4+3]=a.w;
            float4 b=p1[q]; wh1[q*4]=b.x; wh1[q*4+1]=b.y; wh1[q*4+2]=b.z; wh1[q*4+3]=b.w;
            float4 c=p2[q]; wh2[q*4]=c.x; wh2[q*4+1]=c.y; wh2[q*4+2]=c.z; wh2[q*4+3]=c.w;
        }
    }
    float bcr = bc0 + __ldg(bhh + la);        // r gate combined bias
    float bcz = bc1 + __ldg(bhh + la + 32);   // z gate combined bias
    float bgn = __ldg(bhh + la + 64);         // hidden-side n bias (stays inside r*(...))

    #pragma unroll 1
    for (int t = 0; t < Tq; t++) {
        float ov = (la < 15) ? obs_row[t * 15 + la] : 0.0f;
        sm[la] = h;
        if (la < 15) sm[32 + la] = ov;
        __syncwarp();
        float xr = bcr, xz = bcz, xn = bc2, gn = bgn;
        #pragma unroll
        for (int k = 0; k < KIN; k++) {
            float xk = sm[32 + xoff + k];
            xr = fmaf(xk, wc0[k], xr);
            xz = fmaf(xk, wc1[k], xz);
            xn = fmaf(xk, wc2[k], xn);
        }
        #pragma unroll
        for (int k = 0; k < 32; k++) {
            float hk = sm[k];
            xr = fmaf(hk, wh0[k], xr);
            xz = fmaf(hk, wh1[k], xz);
            gn = fmaf(hk, wh2[k], gn);
        }
        float r = fsig(xr);
        float z = fsig(xz);
        float n = ftanh(fmaf(r, gn, xn));
        h = n + z * (h - n);
        feat[t * 32 + la] = h;
        __syncwarp();
    }
    *nexth = h;
}

__global__ void __launch_bounds__(128) k_gru(
    const float* __restrict__ obs, const float* __restrict__ rnn,
    const float* __restrict__ eAW, const float* __restrict__ eAb,
    const float* __restrict__ eMW, const float* __restrict__ eMb,
    const float* __restrict__ aWih, const float* __restrict__ aWhh,
    const float* __restrict__ abih, const float* __restrict__ abhh,
    const float* __restrict__ mWih, const float* __restrict__ mWhh,
    const float* __restrict__ mbih, const float* __restrict__ mbhh,
    float* __restrict__ next_h)
{
    __shared__ float sm[4][64];
    int w  = blockIdx.x * 4 + (threadIdx.x >> 5);
    int la = threadIdx.x & 31;
    int wi = threadIdx.x >> 5;
    if (w < Bq) {
        int b = w;
        float h = rnn[b * 96 + la];
        gru_warp<7>(obs + (size_t)b * Tq * 15, 8, eAW, eAb, aWih, abih, aWhh, abhh,
                    h, g_air + (size_t)b * Tq * 32, next_h + b * 96 + la, la, sm[wi]);
    } else {
        int i = w - Bq;                 // m-GRU instance 0..2B-1
        int b = (i < Bq) ? i : i - Bq;  // obs batch
        int xoff = (i < Bq) ? 0 : 4;
        // h0 = rnn[i>>1, 32 + 32*(i&1)]  (per reference reshape)
        float h = rnn[(i >> 1) * 96 + 32 + 32 * (i & 1) + la];
        float* feat = (i < Bq) ? (g_m1 + (size_t)i * Tq * 32)
                               : (g_m2 + (size_t)(i - Bq) * Tq * 32);
        gru_warp<4>(obs + (size_t)b * Tq * 15, xoff, eMW, eMb, mWih, mbih, mWhh, mbhh,
                    h, feat, next_h + (i >> 1) * 96 + 32 + 32 * (i & 1) + la, la, sm[wi]);
    }
}

// ================= attention + fusion: lane = row =================
__global__ void __launch_bounds__(256) k_attn(
    const float* __restrict__ obs,
    const float* __restrict__ Win, const float* __restrict__ bin,
    const float* __restrict__ Wout, const float* __restrict__ bout)
{
    __shared__ float Ws[96 * 32];   // rows 0..31 Wq, 32..63 Wk, 64..95 Wv
    __shared__ float Wo[32 * 32];
    __shared__ float bs[96], bo[32];
    int t = threadIdx.x;
    for (int i = t; i < 96 * 32; i += 256) Ws[i] = Win[i];
    for (int i = t; i < 32 * 32; i += 256) Wo[i] = Wout[i];
    if (t < 96) bs[t] = bin[t];
    if (t < 32) bo[t] = bout[t];
    __syncthreads();

    int warp = blockIdx.x * 8 + (t >> 5);
    int la = t & 31;
    int n = warp * 32 + la;   // this lane's row

    float4 A[8], M1[8], M2[8];
    const float4* ap = (const float4*)(g_air + (size_t)n * 32);
    const float4* p1 = (const float4*)(g_m1 + (size_t)n * 32);
    const float4* p2 = (const float4*)(g_m2 + (size_t)n * 32);
    #pragma unroll
    for (int i = 0; i < 8; i++) { A[i] = ap[i]; M1[i] = p1[i]; M2[i] = p2[i]; }

    // masks: jnp.isclose(obs[:,0:4],[1,0,1,0]) all; same for [:,4:8]
    const float* op = obs + (size_t)n * 15;
    float o0=op[0],o1=op[1],o2=op[2],o3=op[3],o4=op[4],o5=op[5],o6=op[6],o7=op[7];
    const float T1 = 1.001e-5f, T0 = 1e-8f;
    bool mk0 = (fabsf(o0-1.f)<=T1) && (fabsf(o1)<=T0) && (fabsf(o2-1.f)<=T1) && (fabsf(o3)<=T0);
    bool mk1 = (fabsf(o4-1.f)<=T1) && (fabsf(o5)<=T0) && (fabsf(o6-1.f)<=T1) && (fabsf(o7)<=T0);

    // q = air @ Wq^T + bq
    float q[32];
    #pragma unroll
    for (int c = 0; c < 32; c++) {
        float s = bs[c];
        const float4* w = (const float4*)(Ws + c * 32);
        #pragma unroll
        for (int k = 0; k < 8; k++) s += dot4(A[k], w[k]);
        q[c] = s;
    }
    // scores
    float s1[2] = {0.f, 0.f}, s2[2] = {0.f, 0.f};
    #pragma unroll
    for (int c = 0; c < 32; c++) {
        const float4* w = (const float4*)(Ws + (32 + c) * 32);
        float k1 = bs[32 + c], k2 = k1;
        #pragma unroll
        for (int k = 0; k < 8; k++) { k1 += dot4(M1[k], w[k]); k2 += dot4(M2[k], w[k]); }
        int hh = c >> 4;
        s1[hh] = fmaf(q[c], k1, s1[hh]);
        s2[hh] = fmaf(q[c], k2, s2[hh]);
    }
    float w1[2], w2[2];
    #pragma unroll
    for (int hh = 0; hh < 2; hh++) {
        float a = s1[hh] * 0.25f + (mk0 ? -1e9f : 0.f);
        float b = s2[hh] * 0.25f + (mk1 ? -1e9f : 0.f);
        float m = fmaxf(a, b);
        float e1 = __expf(a - m), e2 = __expf(b - m);
        float inv = __fdividef(1.0f, e1 + e2);
        w1[hh] = e1 * inv; w2[hh] = e2 * inv;
    }
    // ctx
    float ctx[32];
    #pragma unroll
    for (int c = 0; c < 32; c++) {
        const float4* w = (const float4*)(Ws + (64 + c) * 32);
        float v1 = bs[64 + c], v2 = v1;
        #pragma unroll
        for (int k = 0; k < 8; k++) { v1 += dot4(M1[k], w[k]); v2 += dot4(M2[k], w[k]); }
        int hh = c >> 4;
        ctx[c] = w1[hh] * v1 + w2[hh] * v2;
    }
    // attn = ctx @ Wout^T + b, zeroed if both masked
    bool allm = mk0 && mk1;
    float at[32];
    #pragma unroll
    for (int o = 0; o < 32; o++) {
        float s = bo[o];
        const float* w = Wo + o * 32;
        #pragma unroll
        for (int c = 0; c < 32; c++) s = fmaf(ctx[c], w[c], s);
        at[o] = allm ? 0.0f : s;
    }
    float4* fr = (float4*)(g_fusion + (size_t)n * 64);
    #pragma unroll
    for (int i = 0; i < 8; i++) fr[i] = A[i];
    #pragma unroll
    for (int i = 0; i < 8; i++)
        fr[8 + i] = make_float4(at[4*i], at[4*i+1], at[4*i+2], at[4*i+3]);
}

// ================= fused MLP: 64 rows/block, H1 stays in smem =================
// smem: Xs[64][17]f4 | Ws[256][17]f4 (W0, then W1 chunks) | H1[64][260]f | b0s,b1s,ows
#define MLP_SMEM ((64*17 + 256*17) * 16 + 64*260*4 + 3*256*4)

__global__ void __launch_bounds__(256) k_mlp(
    const float* __restrict__ W0, const float* __restrict__ b0,
    const float* __restrict__ W1, const float* __restrict__ b1,
    const float* __restrict__ oW, const float* __restrict__ ob,
    float* __restrict__ val)
{
    extern __shared__ float smem[];
    float4* Xs = (float4*)smem;            // 64*17
    float4* Ws = Xs + 64 * 17;             // 256*17
    float*  H1 = (float*)(Ws + 256 * 17);  // 64*260
    float*  b0s = H1 + 64 * 260;
    float*  b1s = b0s + 256;
    float*  ows = b1s + 256;

    int t = threadIdx.x;
    int tx = t & 15, ty = t >> 4;
    int row0 = blockIdx.x * 64;

    const float4* Fg = (const float4*)g_fusion;
    #pragma unroll
    for (int q = 0; q < 4; q++) {
        int id = t + 256 * q;
        Xs[(id >> 4) * 17 + (id & 15)] = Fg[(size_t)(row0 + (id >> 4)) * 16 + (id & 15)];
    }
    const float4* W0g = (const float4*)W0;
    #pragma unroll
    for (int q = 0; q < 16; q++) {
        int id = t + 256 * q;
        Ws[(id >> 4) * 17 + (id & 15)] = W0g[(id >> 4) * 16 + (id & 15)];
    }
    b0s[t] = b0[t]; b1s[t] = b1[t]; ows[t] = oW[t];
    __syncthreads();

    // ---- layer 0: 64x64 @ 64x256 ----
    float acc[4][16];
    #pragma unroll
    for (int j = 0; j < 4; j++)
        #pragma unroll
        for (int i = 0; i < 16; i++) acc[j][i] = 0.f;
    #pragma unroll
    for (int k4 = 0; k4 < 16; k4++) {
        float4 xv[4];
        #pragma unroll
        for (int j = 0; j < 4; j++) xv[j] = Xs[(ty * 4 + j) * 17 + k4];
        #pragma unroll
        for (int i = 0; i < 16; i++) {
            float4 w = Ws[(tx + 16 * i) * 17 + k4];
            #pragma unroll
            for (int j = 0; j < 4; j++) {
                acc[j][i] = fmaf(xv[j].x, w.x, acc[j][i]);
                acc[j][i] = fmaf(xv[j].y, w.y, acc[j][i]);
                acc[j][i] = fmaf(xv[j].z, w.z, acc[j][i]);
                acc[j][i] = fmaf(xv[j].w, w.w, acc[j][i]);
            }
        }
    }
    #pragma unroll
    for (int i = 0; i < 16; i++) {
        int c = tx + 16 * i;
        float bb = b0s[c];
        #pragma unroll
        for (int j = 0; j < 4; j++) {
            float v = acc[j][i] + bb;
            v = (v > 0.f) ? v : 0.01f * v;
            H1[(ty * 4 + j) * 260 + c] = v;
        }
    }

    // ---- layer 1: 64x256 @ 256x256, W1 streamed in 4 chunks of k=64 ----
    float a2[4][16];
    #pragma unroll
    for (int j = 0; j < 4; j++)
        #pragma unroll
        for (int i = 0; i < 16; i++) a2[j][i] = 0.f;
    const float4* W1g = (const float4*)W1;
    for (int chunk = 0; chunk < 4; chunk++) {
        __syncthreads();
        int k0f4 = chunk * 16;
        #pragma unroll
        for (int q = 0; q < 16; q++) {
            int id = t + 256 * q;
            Ws[(id >> 4) * 17 + (id & 15)] = W1g[(id >> 4) * 64 + k0f4 + (id & 15)];
        }
        __syncthreads();
        #pragma unroll
        for (int k4 = 0; k4 < 16; k4++) {
            float4 hv[4];
            #pragma unroll
            for (int j = 0; j < 4; j++)
                hv[j] = *(const float4*)&H1[(ty * 4 + j) * 260 + chunk * 64 + k4 * 4];
            #pragma unroll
            for (int i = 0; i < 16; i++) {
                float4 w = Ws[(tx + 16 * i) * 17 + k4];
                #pragma unroll
                for (int j = 0; j < 4; j++) {
                    a2[j][i] = fmaf(hv[j].x, w.x, a2[j][i]);
                    a2[j][i] = fmaf(hv[j].y, w.y, a2[j][i]);
                    a2[j][i] = fmaf(hv[j].z, w.z, a2[j][i]);
                    a2[j][i] = fmaf(hv[j].w, w.w, a2[j][i]);
                }
            }
        }
    }

    // ---- layer 2: leaky + dot with out_W, reduce across tx ----
    float p[4] = {0.f, 0.f, 0.f, 0.f};
    #pragma unroll
    for (int i = 0; i < 16; i++) {
        int c = tx + 16 * i;
        float bb = b1s[c], wo = ows[c];
        #pragma unroll
        for (int j = 0; j < 4; j++) {
            float v = a2[j][i] + bb;
            v = (v > 0.f) ? v : 0.01f * v;
            p[j] = fmaf(v, wo, p[j]);
        }
    }
    #pragma unroll
    for (int off = 8; off >= 1; off >>= 1)
        #pragma unroll
        for (int j = 0; j < 4; j++)
            p[j] += __shfl_down_sync(0xffffffffu, p[j], off);
    if (tx == 0) {
        float obv = ob[0];
        #pragma unroll
        for (int j = 0; j < 4; j++)
            val[row0 + ty * 4 + j] = p[j] + obv;
    }
}

extern "C" void kernel_launch(void* const* d_in, const int* in_sizes, int n_in,
                              void* d_out, int out_size) {
    const float* obs   = (const float*)d_in[0];
    const float* rnn   = (const float*)d_in[1];
    const float* eAW   = (const float*)d_in[2];
    const float* eAb   = (const float*)d_in[3];
    const float* eMW   = (const float*)d_in[4];
    const float* eMb   = (const float*)d_in[5];
    const float* aWih  = (const float*)d_in[6];
    const float* aWhh  = (const float*)d_in[7];
    const float* abih  = (const float*)d_in[8];
    const float* abhh  = (const float*)d_in[9];
    const float* mWih  = (const float*)d_in[10];
    const float* mWhh  = (const float*)d_in[11];
    const float* mbih  = (const float*)d_in[12];
    const float* mbhh  = (const float*)d_in[13];
    const float* Win   = (const float*)d_in[14];
    const float* bin   = (const float*)d_in[15];
    const float* Wout  = (const float*)d_in[16];
    const float* bout  = (const float*)d_in[17];
    const float* W0    = (const float*)d_in[18];
    const float* b0    = (const float*)d_in[19];
    const float* W1    = (const float*)d_in[20];
    const float* b1    = (const float*)d_in[21];
    const float* oW    = (const float*)d_in[22];
    const float* ob    = (const float*)d_in[23];

    float* out_val = (float*)d_out;          // val: N floats
    float* out_h   = (float*)d_out + Nq;     // next_h: B*96 floats

    k_gru<<<(Bq + 2 * Bq) / 4, 128>>>(obs, rnn, eAW, eAb, eMW, eMb,
                                      aWih, aWhh, abih, abhh,
                                      mWih, mWhh, mbih, mbhh, out_h);
    k_attn<<<Nq / 32 / 8, 256>>>(obs, Win, bin, Wout, bout);
    cudaFuncSetAttribute(k_mlp, cudaFuncAttributeMaxDynamicSharedMemorySize, MLP_SMEM);
    k_mlp<<<Nq / 64, 256, MLP_SMEM>>>(W0, b0, W1, b1, oW, ob, out_val);
}

// round 3
// speedup vs baseline: 1.3331x; 1.3331x over previous
#include <cuda_runtime.h>
#include <cuda_bf16.h>

#define Bq 2048
#define Tq 128
#define Nq (Bq*Tq)

// ---------------- scratch (no allocations allowed) ----------------
__device__ float g_air[(size_t)Nq * 32];
__device__ float g_m1 [(size_t)Nq * 32];
__device__ float g_m2 [(size_t)Nq * 32];
__device__ float g_fusion[(size_t)Nq * 64];

__device__ __forceinline__ float fsig(float x) {
    return __fdividef(1.0f, 1.0f + __expf(-x));
}
__device__ __forceinline__ float ftanh(float x) {
    x = fminf(fmaxf(x, -12.0f), 12.0f);
    float e = __expf(-2.0f * x);
    return __fdividef(1.0f - e, 1.0f + e);
}
__device__ __forceinline__ float dot4(float4 a, float4 b) {
    return fmaf(a.x, b.x, fmaf(a.y, b.y, fmaf(a.z, b.z, a.w * b.w)));
}

// packed 2xfp32 FMA (Blackwell f32x2 pipe — 2 lane-MACs per issue slot)
union F2U { float2 f; unsigned long long u; };
__device__ __forceinline__ float2 ffma2(float2 a, float2 b, float2 c) {
    F2U A, B, C, D;
    A.f = a; B.f = b; C.f = c;
    asm("fma.rn.f32x2 %0, %1, %2, %3;" : "=l"(D.u) : "l"(A.u), "l"(B.u), "l"(C.u));
    return D.f;
}

// ================= GRU: one warp per batch lane =================
template<int KIN>
__device__ __forceinline__ void gru_warp(
    const float* __restrict__ obs_row, int xoff,
    const float* __restrict__ encW, const float* __restrict__ encB,
    const float* __restrict__ Wih,  const float* __restrict__ bih,
    const float* __restrict__ Whh,  const float* __restrict__ bhh,
    float h, float* __restrict__ feat, float* __restrict__ nexth,
    int la, volatile float* sm)
{
    // composed input weights Wc = Wih @ encW, bc = Wih @ encB + bih
    float wc0[KIN], wc1[KIN], wc2[KIN];
    float bc0 = 0.f, bc1 = 0.f, bc2 = 0.f;
    #pragma unroll
    for (int g = 0; g < 3; g++) {
        int j = la + 32 * g;
        float wrow[32];
        const float4* wp = (const float4*)(Wih + j * 32);
        #pragma unroll
        for (int q = 0; q < 8; q++) {
            float4 v = wp[q];
            wrow[q*4+0]=v.x; wrow[q*4+1]=v.y; wrow[q*4+2]=v.z; wrow[q*4+3]=v.w;
        }
        #pragma unroll
        for (int k = 0; k < KIN; k++) {
            float s = 0.0f;
            #pragma unroll
            for (int m = 0; m < 32; m++) s = fmaf(wrow[m], __ldg(encW + m * KIN + k), s);
            if (g == 0) wc0[k] = s; else if (g == 1) wc1[k] = s; else wc2[k] = s;
        }
        float sb = __ldg(bih + j);
        #pragma unroll
        for (int m = 0; m < 32; m++) sb = fmaf(wrow[m], __ldg(encB + m), sb);
        if (g == 0) bc0 = sb; else if (g == 1) bc1 = sb; else bc2 = sb;
    }
    // Whh rows (la, la+32, la+64) in registers, as float2 k-pairs
    float2 wh0[16], wh1[16], wh2[16];
    {
        const float4* p0 = (const float4*)(Whh + (la     ) * 32);
        const float4* p1 = (const float4*)(Whh + (la + 32) * 32);
        const float4* p2 = (const float4*)(Whh + (la + 64) * 32);
        #pragma unroll
        for (int q = 0; q < 8; q++) {
            float4 a=p0[q]; wh0[q*2]=make_float2(a.x,a.y); wh0[q*2+1]=make_float2(a.z,a.w);
            float4 b=p1[q]; wh1[q*2]=make_float2(b.x,b.y); wh1[q*2+1]=make_float2(b.z,b.w);
            float4 c=p2[q]; wh2[q*2]=make_float2(c.x,c.y); wh2[q*2+1]=make_float2(c.z,c.w);
        }
    }
    float bcr = bc0 + __ldg(bhh + la);        // r gate combined bias
    float bcz = bc1 + __ldg(bhh + la + 32);   // z gate combined bias
    float bgn = __ldg(bhh + la + 64);         // hidden-side n bias

    #pragma unroll 1
    for (int t = 0; t < Tq; t++) {
        float ov = (la < 15) ? obs_row[t * 15 + la] : 0.0f;
        sm[la] = h;
        if (la < 15) sm[32 + la] = ov;
        __syncwarp();
        float xr = bcr, xz = bcz, xn = bc2;
        #pragma unroll
        for (int k = 0; k < KIN; k++) {
            float xk = sm[32 + xoff + k];
            xr = fmaf(xk, wc0[k], xr);
            xz = fmaf(xk, wc1[k], xz);
            xn = fmaf(xk, wc2[k], xn);
        }
        float2 r2 = make_float2(xr, 0.f);
        float2 z2 = make_float2(xz, 0.f);
        float2 n2 = make_float2(bgn, 0.f);
        #pragma unroll
        for (int k = 0; k < 16; k++) {
            float2 h2 = make_float2(sm[2*k], sm[2*k+1]);
            r2 = ffma2(h2, wh0[k], r2);
            z2 = ffma2(h2, wh1[k], z2);
            n2 = ffma2(h2, wh2[k], n2);
        }
        float r = fsig(r2.x + r2.y);
        float z = fsig(z2.x + z2.y);
        float n = ftanh(fmaf(r, n2.x + n2.y, xn));
        h = n + z * (h - n);
        feat[t * 32 + la] = h;
        __syncwarp();
    }
    *nexth = h;
}

__global__ void __launch_bounds__(128) k_gru(
    const float* __restrict__ obs, const float* __restrict__ rnn,
    const float* __restrict__ eAW, const float* __restrict__ eAb,
    const float* __restrict__ eMW, const float* __restrict__ eMb,
    const float* __restrict__ aWih, const float* __restrict__ aWhh,
    const float* __restrict__ abih, const float* __restrict__ abhh,
    const float* __restrict__ mWih, const float* __restrict__ mWhh,
    const float* __restrict__ mbih, const float* __restrict__ mbhh,
    float* __restrict__ next_h)
{
    __shared__ float sm[4][64];
    int w  = blockIdx.x * 4 + (threadIdx.x >> 5);
    int la = threadIdx.x & 31;
    int wi = threadIdx.x >> 5;
    if (w < Bq) {
        int b = w;
        float h = rnn[b * 96 + la];
        gru_warp<7>(obs + (size_t)b * Tq * 15, 8, eAW, eAb, aWih, abih, aWhh, abhh,
                    h, g_air + (size_t)b * Tq * 32, next_h + b * 96 + la, la, sm[wi]);
    } else {
        int i = w - Bq;                 // m-GRU instance 0..2B-1
        int b = (i < Bq) ? i : i - Bq;  // obs batch
        int xoff = (i < Bq) ? 0 : 4;
        float h = rnn[(i >> 1) * 96 + 32 + 32 * (i & 1) + la];
        float* feat = (i < Bq) ? (g_m1 + (size_t)i * Tq * 32)
                               : (g_m2 + (size_t)(i - Bq) * Tq * 32);
        gru_warp<4>(obs + (size_t)b * Tq * 15, xoff, eMW, eMb, mWih, mbih, mWhh, mbhh,
                    h, feat, next_h + (i >> 1) * 96 + 32 + 32 * (i & 1) + la, la, sm[wi]);
    }
}

// ================= attention + fusion: lane = row =================
__global__ void __launch_bounds__(256) k_attn(
    const float* __restrict__ obs,
    const float* __restrict__ Win, const float* __restrict__ bin,
    const float* __restrict__ Wout, const float* __restrict__ bout)
{
    __shared__ float Ws[96 * 32];
    __shared__ float Wo[32 * 32];
    __shared__ float bs[96], bo[32];
    int t = threadIdx.x;
    for (int i = t; i < 96 * 32; i += 256) Ws[i] = Win[i];
    for (int i = t; i < 32 * 32; i += 256) Wo[i] = Wout[i];
    if (t < 96) bs[t] = bin[t];
    if (t < 32) bo[t] = bout[t];
    __syncthreads();

    int warp = blockIdx.x * 8 + (t >> 5);
    int la = t & 31;
    int n = warp * 32 + la;

    float4 A[8], M1[8], M2[8];
    const float4* ap = (const float4*)(g_air + (size_t)n * 32);
    const float4* p1 = (const float4*)(g_m1 + (size_t)n * 32);
    const float4* p2 = (const float4*)(g_m2 + (size_t)n * 32);
    #pragma unroll
    for (int i = 0; i < 8; i++) { A[i] = ap[i]; M1[i] = p1[i]; M2[i] = p2[i]; }

    const float* op = obs + (size_t)n * 15;
    float o0=op[0],o1=op[1],o2=op[2],o3=op[3],o4=op[4],o5=op[5],o6=op[6],o7=op[7];
    const float T1 = 1.001e-5f, T0 = 1e-8f;
    bool mk0 = (fabsf(o0-1.f)<=T1) && (fabsf(o1)<=T0) && (fabsf(o2-1.f)<=T1) && (fabsf(o3)<=T0);
    bool mk1 = (fabsf(o4-1.f)<=T1) && (fabsf(o5)<=T0) && (fabsf(o6-1.f)<=T1) && (fabsf(o7)<=T0);

    float q[32];
    #pragma unroll
    for (int c = 0; c < 32; c++) {
        float s = bs[c];
        const float4* w = (const float4*)(Ws + c * 32);
        #pragma unroll
        for (int k = 0; k < 8; k++) s += dot4(A[k], w[k]);
        q[c] = s;
    }
    float s1[2] = {0.f, 0.f}, s2[2] = {0.f, 0.f};
    #pragma unroll
    for (int c = 0; c < 32; c++) {
        const float4* w = (const float4*)(Ws + (32 + c) * 32);
        float k1 = bs[32 + c], k2 = k1;
        #pragma unroll
        for (int k = 0; k < 8; k++) { k1 += dot4(M1[k], w[k]); k2 += dot4(M2[k], w[k]); }
        int hh = c >> 4;
        s1[hh] = fmaf(q[c], k1, s1[hh]);
        s2[hh] = fmaf(q[c], k2, s2[hh]);
    }
    float w1[2], w2[2];
    #pragma unroll
    for (int hh = 0; hh < 2; hh++) {
        float a = s1[hh] * 0.25f + (mk0 ? -1e9f : 0.f);
        float b = s2[hh] * 0.25f + (mk1 ? -1e9f : 0.f);
        float m = fmaxf(a, b);
        float e1 = __expf(a - m), e2 = __expf(b - m);
        float inv = __fdividef(1.0f, e1 + e2);
        w1[hh] = e1 * inv; w2[hh] = e2 * inv;
    }
    float ctx[32];
    #pragma unroll
    for (int c = 0; c < 32; c++) {
        const float4* w = (const float4*)(Ws + (64 + c) * 32);
        float v1 = bs[64 + c], v2 = v1;
        #pragma unroll
        for (int k = 0; k < 8; k++) { v1 += dot4(M1[k], w[k]); v2 += dot4(M2[k], w[k]); }
        int hh = c >> 4;
        ctx[c] = w1[hh] * v1 + w2[hh] * v2;
    }
    bool allm = mk0 && mk1;
    float at[32];
    #pragma unroll
    for (int o = 0; o < 32; o++) {
        float s = bo[o];
        const float* w = Wo + o * 32;
        #pragma unroll
        for (int c = 0; c < 32; c++) s = fmaf(ctx[c], w[c], s);
        at[o] = allm ? 0.0f : s;
    }
    float4* fr = (float4*)(g_fusion + (size_t)n * 64);
    #pragma unroll
    for (int i = 0; i < 8; i++) fr[i] = A[i];
    #pragma unroll
    for (int i = 0; i < 8; i++)
        fr[8 + i] = make_float4(at[4*i], at[4*i+1], at[4*i+2], at[4*i+3]);
}

// ================= fused MLP: 64 rows/block, H1 stays in smem =================
#define MLP_SMEM ((64*17 + 256*17) * 16 + 64*260*4 + 3*256*4)

__global__ void __launch_bounds__(256) k_mlp(
    const float* __restrict__ W0, const float* __restrict__ b0,
    const float* __restrict__ W1, const float* __restrict__ b1,
    const float* __restrict__ oW, const float* __restrict__ ob,
    float* __restrict__ val)
{
    extern __shared__ float smem[];
    float4* Xs = (float4*)smem;            // 64*17
    float4* Ws = Xs + 64 * 17;             // 256*17
    float*  H1 = (float*)(Ws + 256 * 17);  // 64*260
    float*  b0s = H1 + 64 * 260;
    float*  b1s = b0s + 256;
    float*  ows = b1s + 256;

    int t = threadIdx.x;
    int tx = t & 15, ty = t >> 4;
    int row0 = blockIdx.x * 64;

    const float4* Fg = (const float4*)g_fusion;
    #pragma unroll
    for (int q = 0; q < 4; q++) {
        int id = t + 256 * q;
        Xs[(id >> 4) * 17 + (id & 15)] = Fg[(size_t)(row0 + (id >> 4)) * 16 + (id & 15)];
    }
    const float4* W0g = (const float4*)W0;
    #pragma unroll
    for (int q = 0; q < 16; q++) {
        int id = t + 256 * q;
        Ws[(id >> 4) * 17 + (id & 15)] = W0g[(id >> 4) * 16 + (id & 15)];
    }
    b0s[t] = b0[t]; b1s[t] = b1[t]; ows[t] = oW[t];
    __syncthreads();

    // ---- layer 0: 64x64 @ 64x256, packed f32x2 over k ----
    float2 acc[4][16];
    #pragma unroll
    for (int j = 0; j < 4; j++)
        #pragma unroll
        for (int i = 0; i < 16; i++) acc[j][i] = make_float2(0.f, 0.f);
    #pragma unroll
    for (int k4 = 0; k4 < 16; k4++) {
        float2 xlo[4], xhi[4];
        #pragma unroll
        for (int j = 0; j < 4; j++) {
            float4 xv = Xs[(ty * 4 + j) * 17 + k4];
            xlo[j] = make_float2(xv.x, xv.y);
            xhi[j] = make_float2(xv.z, xv.w);
        }
        #pragma unroll
        for (int i = 0; i < 16; i++) {
            float4 w = Ws[(tx + 16 * i) * 17 + k4];
            float2 wlo = make_float2(w.x, w.y);
            float2 whi = make_float2(w.z, w.w);
            #pragma unroll
            for (int j = 0; j < 4; j++) {
                acc[j][i] = ffma2(xlo[j], wlo, acc[j][i]);
                acc[j][i] = ffma2(xhi[j], whi, acc[j][i]);
            }
        }
    }
    #pragma unroll
    for (int i = 0; i < 16; i++) {
        int c = tx + 16 * i;
        float bb = b0s[c];
        #pragma unroll
        for (int j = 0; j < 4; j++) {
            float v = acc[j][i].x + acc[j][i].y + bb;
            v = (v > 0.f) ? v : 0.01f * v;
            H1[(ty * 4 + j) * 260 + c] = v;
        }
    }

    // ---- layer 1: 64x256 @ 256x256, W1 streamed in 4 chunks of k=64 ----
    float2 a2[4][16];
    #pragma unroll
    for (int j = 0; j < 4; j++)
        #pragma unroll
        for (int i = 0; i < 16; i++) a2[j][i] = make_float2(0.f, 0.f);
    const float4* W1g = (const float4*)W1;
    for (int chunk = 0; chunk < 4; chunk++) {
        __syncthreads();
        int k0f4 = chunk * 16;
        #pragma unroll
        for (int q = 0; q < 16; q++) {
            int id = t + 256 * q;
            Ws[(id >> 4) * 17 + (id & 15)] = W1g[(id >> 4) * 64 + k0f4 + (id & 15)];
        }
        __syncthreads();
        #pragma unroll
        for (int k4 = 0; k4 < 16; k4++) {
            float2 hlo[4], hhi[4];
            #pragma unroll
            for (int j = 0; j < 4; j++) {
                float4 hv = *(const float4*)&H1[(ty * 4 + j) * 260 + chunk * 64 + k4 * 4];
                hlo[j] = make_float2(hv.x, hv.y);
                hhi[j] = make_float2(hv.z, hv.w);
            }
            #pragma unroll
            for (int i = 0; i < 16; i++) {
                float4 w = Ws[(tx + 16 * i) * 17 + k4];
                float2 wlo = make_float2(w.x, w.y);
                float2 whi = make_float2(w.z, w.w);
                #pragma unroll
                for (int j = 0; j < 4; j++) {
                    a2[j][i] = ffma2(hlo[j], wlo, a2[j][i]);
                    a2[j][i] = ffma2(hhi[j], whi, a2[j][i]);
                }
            }
        }
    }

    // ---- layer 2: leaky + dot with out_W, reduce across tx ----
    float p[4] = {0.f, 0.f, 0.f, 0.f};
    #pragma unroll
    for (int i = 0; i < 16; i++) {
        int c = tx + 16 * i;
        float bb = b1s[c], wo = ows[c];
        #pragma unroll
        for (int j = 0; j < 4; j++) {
            float v = a2[j][i].x + a2[j][i].y + bb;
            v = (v > 0.f) ? v : 0.01f * v;
            p[j] = fmaf(v, wo, p[j]);
        }
    }
    #pragma unroll
    for (int off = 8; off >= 1; off >>= 1)
        #pragma unroll
        for (int j = 0; j < 4; j++)
            p[j] += __shfl_down_sync(0xffffffffu, p[j], off);
    if (tx == 0) {
        float obv = ob[0];
        #pragma unroll
        for (int j = 0; j < 4; j++)
            val[row0 + ty * 4 + j] = p[j] + obv;
    }
}

extern "C" void kernel_launch(void* const* d_in, const int* in_sizes, int n_in,
                              void* d_out, int out_size) {
    const float* obs   = (const float*)d_in[0];
    const float* rnn   = (const float*)d_in[1];
    const float* eAW   = (const float*)d_in[2];
    const float* eAb   = (const float*)d_in[3];
    const float* eMW   = (const float*)d_in[4];
    const float* eMb   = (const float*)d_in[5];
    const float* aWih  = (const float*)d_in[6];
    const float* aWhh  = (const float*)d_in[7];
    const float* abih  = (const float*)d_in[8];
    const float* abhh  = (const float*)d_in[9];
    const float* mWih  = (const float*)d_in[10];
    const float* mWhh  = (const float*)d_in[11];
    const float* mbih  = (const float*)d_in[12];
    const float* mbhh  = (const float*)d_in[13];
    const float* Win   = (const float*)d_in[14];
    const float* bin   = (const float*)d_in[15];
    const float* Wout  = (const float*)d_in[16];
    const float* bout  = (const float*)d_in[17];
    const float* W0    = (const float*)d_in[18];
    const float* b0    = (const float*)d_in[19];
    const float* W1    = (const float*)d_in[20];
    const float* b1    = (const float*)d_in[21];
    const float* oW    = (const float*)d_in[22];
    const float* ob    = (const float*)d_in[23];

    float* out_val = (float*)d_out;
    float* out_h   = (float*)d_out + Nq;

    k_gru<<<(Bq + 2 * Bq) / 4, 128>>>(obs, rnn, eAW, eAb, eMW, eMb,
                                      aWih, aWhh, abih, abhh,
                                      mWih, mWhh, mbih, mbhh, out_h);
    k_attn<<<Nq / 32 / 8, 256>>>(obs, Win, bin, Wout, bout);
    cudaFuncSetAttribute(k_mlp, cudaFuncAttributeMaxDynamicSharedMemorySize, MLP_SMEM);
    k_mlp<<<Nq / 64, 256, MLP_SMEM>>>(W0, b0, W1, b1, oW, ob, out_val);
}

// round 5
// speedup vs baseline: 2.1421x; 1.6069x over previous
#include <cuda_runtime.h>
#include <cuda_bf16.h>
#include <cstdint>

#define Bq 2048
#define Tq 128
#define Nq (Bq*Tq)

// ---------------- scratch (no allocations allowed) ----------------
__device__ float g_air[(size_t)Nq * 32];
__device__ float g_m1 [(size_t)Nq * 32];
__device__ float g_m2 [(size_t)Nq * 32];
__device__ float g_fusion[(size_t)Nq * 64];
// prepacked bf16 hi/lo weights, plain row-major [n][k]
__device__ __nv_bfloat16 g_W0h[256 * 64];
__device__ __nv_bfloat16 g_W0l[256 * 64];
__device__ __nv_bfloat16 g_W1h[256 * 256];
__device__ __nv_bfloat16 g_W1l[256 * 256];

__device__ __forceinline__ float fsig(float x) {
    return __fdividef(1.0f, 1.0f + __expf(-x));
}
__device__ __forceinline__ float ftanh(float x) {
    x = fminf(fmaxf(x, -12.0f), 12.0f);
    float e = __expf(-2.0f * x);
    return __fdividef(1.0f - e, 1.0f + e);
}
__device__ __forceinline__ float dot4(float4 a, float4 b) {
    return fmaf(a.x, b.x, fmaf(a.y, b.y, fmaf(a.z, b.z, a.w * b.w)));
}

// packed 2xfp32 FMA
union F2U { float2 f; unsigned long long u; };
__device__ __forceinline__ float2 ffma2(float2 a, float2 b, float2 c) {
    F2U A, B, C, D;
    A.f = a; B.f = b; C.f = c;
    asm("fma.rn.f32x2 %0, %1, %2, %3;" : "=l"(D.u) : "l"(A.u), "l"(B.u), "l"(C.u));
    return D.f;
}

// ---------------- mma.sync helpers (arch-portable, sm_80-level PTX) -------
__device__ __forceinline__ uint32_t smem_u32(const void* p) {
    uint32_t a;
    asm("{ .reg .u64 t; cvta.to.shared.u64 t, %1; cvt.u32.u64 %0, t; }" : "=r"(a) : "l"(p));
    return a;
}
__device__ __forceinline__ void ldsm4(uint32_t* a, uint32_t addr) {
    asm volatile("ldmatrix.sync.aligned.m8n8.x4.shared.b16 {%0,%1,%2,%3}, [%4];"
        : "=r"(a[0]), "=r"(a[1]), "=r"(a[2]), "=r"(a[3]) : "r"(addr));
}
__device__ __forceinline__ void ldsm2(uint32_t* b, uint32_t addr) {
    asm volatile("ldmatrix.sync.aligned.m8n8.x2.shared.b16 {%0,%1}, [%2];"
        : "=r"(b[0]), "=r"(b[1]) : "r"(addr));
}
__device__ __forceinline__ void mma16816(float* c, const uint32_t* a, const uint32_t* b) {
    asm volatile("mma.sync.aligned.m16n8k16.row.col.f32.bf16.bf16.f32 "
        "{%0,%1,%2,%3}, {%4,%5,%6,%7}, {%8,%9}, {%0,%1,%2,%3};"
        : "+f"(c[0]), "+f"(c[1]), "+f"(c[2]), "+f"(c[3])
        : "r"(a[0]), "r"(a[1]), "r"(a[2]), "r"(a[3]), "r"(b[0]), "r"(b[1]));
}

__device__ __forceinline__ __nv_bfloat162 split_hi(float a, float b) {
    __nv_bfloat162 h; h.x = __float2bfloat16(a); h.y = __float2bfloat16(b); return h;
}
__device__ __forceinline__ __nv_bfloat162 split_lo(float a, float b, __nv_bfloat162 h) {
    __nv_bfloat162 l;
    l.x = __float2bfloat16(a - __bfloat162float(h.x));
    l.y = __float2bfloat16(b - __bfloat162float(h.y));
    return l;
}

// ================= weight prepack: fp32 -> bf16 hi/lo =================
__global__ void k_pack(const float* __restrict__ W0, const float* __restrict__ W1) {
    int i = blockIdx.x * 256 + threadIdx.x;
    if (i < 16384) {
        float w = W0[i];
        __nv_bfloat16 h = __float2bfloat16(w);
        g_W0h[i] = h;
        g_W0l[i] = __float2bfloat16(w - __bfloat162float(h));
    } else if (i < 16384 + 65536) {
        int j = i - 16384;
        float w = W1[j];
        __nv_bfloat16 h = __float2bfloat16(w);
        g_W1h[j] = h;
        g_W1l[j] = __float2bfloat16(w - __bfloat162float(h));
    }
}

// ================= GRU: one warp per batch lane (unchanged) =================
template<int KIN>
__device__ __forceinline__ void gru_warp(
    const float* __restrict__ obs_row, int xoff,
    const float* __restrict__ encW, const float* __restrict__ encB,
    const float* __restrict__ Wih,  const float* __restrict__ bih,
    const float* __restrict__ Whh,  const float* __restrict__ bhh,
    float h, float* __restrict__ feat, float* __restrict__ nexth,
    int la, volatile float* sm)
{
    float wc0[KIN], wc1[KIN], wc2[KIN];
    float bc0 = 0.f, bc1 = 0.f, bc2 = 0.f;
    #pragma unroll
    for (int g = 0; g < 3; g++) {
        int j = la + 32 * g;
        float wrow[32];
        const float4* wp = (const float4*)(Wih + j * 32);
        #pragma unroll
        for (int q = 0; q < 8; q++) {
            float4 v = wp[q];
            wrow[q*4+0]=v.x; wrow[q*4+1]=v.y; wrow[q*4+2]=v.z; wrow[q*4+3]=v.w;
        }
        #pragma unroll
        for (int k = 0; k < KIN; k++) {
            float s = 0.0f;
            #pragma unroll
            for (int m = 0; m < 32; m++) s = fmaf(wrow[m], __ldg(encW + m * KIN + k), s);
            if (g == 0) wc0[k] = s; else if (g == 1) wc1[k] = s; else wc2[k] = s;
        }
        float sb = __ldg(bih + j);
        #pragma unroll
        for (int m = 0; m < 32; m++) sb = fmaf(wrow[m], __ldg(encB + m), sb);
        if (g == 0) bc0 = sb; else if (g == 1) bc1 = sb; else bc2 = sb;
    }
    float2 wh0[16], wh1[16], wh2[16];
    {
        const float4* p0 = (const float4*)(Whh + (la     ) * 32);
        const float4* p1 = (const float4*)(Whh + (la + 32) * 32);
        const float4* p2 = (const float4*)(Whh + (la + 64) * 32);
        #pragma unroll
        for (int q = 0; q < 8; q++) {
            float4 a=p0[q]; wh0[q*2]=make_float2(a.x,a.y); wh0[q*2+1]=make_float2(a.z,a.w);
            float4 b=p1[q]; wh1[q*2]=make_float2(b.x,b.y); wh1[q*2+1]=make_float2(b.z,b.w);
            float4 c=p2[q]; wh2[q*2]=make_float2(c.x,c.y); wh2[q*2+1]=make_float2(c.z,c.w);
        }
    }
    float bcr = bc0 + __ldg(bhh + la);
    float bcz = bc1 + __ldg(bhh + la + 32);
    float bgn = __ldg(bhh + la + 64);

    #pragma unroll 1
    for (int t = 0; t < Tq; t++) {
        float ov = (la < 15) ? obs_row[t * 15 + la] : 0.0f;
        sm[la] = h;
        if (la < 15) sm[32 + la] = ov;
        __syncwarp();
        float xr = bcr, xz = bcz, xn = bc2;
        #pragma unroll
        for (int k = 0; k < KIN; k++) {
            float xk = sm[32 + xoff + k];
            xr = fmaf(xk, wc0[k], xr);
            xz = fmaf(xk, wc1[k], xz);
            xn = fmaf(xk, wc2[k], xn);
        }
        float2 r2 = make_float2(xr, 0.f);
        float2 z2 = make_float2(xz, 0.f);
        float2 n2 = make_float2(bgn, 0.f);
        #pragma unroll
        for (int k = 0; k < 16; k++) {
            float2 h2 = make_float2(sm[2*k], sm[2*k+1]);
            r2 = ffma2(h2, wh0[k], r2);
            z2 = ffma2(h2, wh1[k], z2);
            n2 = ffma2(h2, wh2[k], n2);
        }
        float r = fsig(r2.x + r2.y);
        float z = fsig(z2.x + z2.y);
        float n = ftanh(fmaf(r, n2.x + n2.y, xn));
        h = n + z * (h - n);
        feat[t * 32 + la] = h;
        __syncwarp();
    }
    *nexth = h;
}

__global__ void __launch_bounds__(128) k_gru(
    const float* __restrict__ obs, const float* __restrict__ rnn,
    const float* __restrict__ eAW, const float* __restrict__ eAb,
    const float* __restrict__ eMW, const float* __restrict__ eMb,
    const float* __restrict__ aWih, const float* __restrict__ aWhh,
    const float* __restrict__ abih, const float* __restrict__ abhh,
    const float* __restrict__ mWih, const float* __restrict__ mWhh,
    const float* __restrict__ mbih, const float* __restrict__ mbhh,
    float* __restrict__ next_h)
{
    __shared__ float sm[4][64];
    int w  = blockIdx.x * 4 + (threadIdx.x >> 5);
    int la = threadIdx.x & 31;
    int wi = threadIdx.x >> 5;
    if (w < Bq) {
        int b = w;
        float h = rnn[b * 96 + la];
        gru_warp<7>(obs + (size_t)b * Tq * 15, 8, eAW, eAb, aWih, abih, aWhh, abhh,
                    h, g_air + (size_t)b * Tq * 32, next_h + b * 96 + la, la, sm[wi]);
    } else {
        int i = w - Bq;
        int b = (i < Bq) ? i : i - Bq;
        int xoff = (i < Bq) ? 0 : 4;
        float h = rnn[(i >> 1) * 96 + 32 + 32 * (i & 1) + la];
        float* feat = (i < Bq) ? (g_m1 + (size_t)i * Tq * 32)
                               : (g_m2 + (size_t)(i - Bq) * Tq * 32);
        gru_warp<4>(obs + (size_t)b * Tq * 15, xoff, eMW, eMb, mWih, mbih, mWhh, mbhh,
                    h, feat, next_h + (i >> 1) * 96 + 32 + 32 * (i & 1) + la, la, sm[wi]);
    }
}

// ================= attention + fusion (unchanged) =================
__global__ void __launch_bounds__(256) k_attn(
    const float* __restrict__ obs,
    const float* __restrict__ Win, const float* __restrict__ bin,
    const float* __restrict__ Wout, const float* __restrict__ bout)
{
    __shared__ float Ws[96 * 32];
    __shared__ float Wo[32 * 32];
    __shared__ float bs[96], bo[32];
    int t = threadIdx.x;
    for (int i = t; i < 96 * 32; i += 256) Ws[i] = Win[i];
    for (int i = t; i < 32 * 32; i += 256) Wo[i] = Wout[i];
    if (t < 96) bs[t] = bin[t];
    if (t < 32) bo[t] = bout[t];
    __syncthreads();

    int warp = blockIdx.x * 8 + (t >> 5);
    int la = t & 31;
    int n = warp * 32 + la;

    float4 A[8], M1[8], M2[8];
    const float4* ap = (const float4*)(g_air + (size_t)n * 32);
    const float4* p1 = (const float4*)(g_m1 + (size_t)n * 32);
    const float4* p2 = (const float4*)(g_m2 + (size_t)n * 32);
    #pragma unroll
    for (int i = 0; i < 8; i++) { A[i] = ap[i]; M1[i] = p1[i]; M2[i] = p2[i]; }

    const float* op = obs + (size_t)n * 15;
    float o0=op[0],o1=op[1],o2=op[2],o3=op[3],o4=op[4],o5=op[5],o6=op[6],o7=op[7];
    const float T1 = 1.001e-5f, T0 = 1e-8f;
    bool mk0 = (fabsf(o0-1.f)<=T1) && (fabsf(o1)<=T0) && (fabsf(o2-1.f)<=T1) && (fabsf(o3)<=T0);
    bool mk1 = (fabsf(o4-1.f)<=T1) && (fabsf(o5)<=T0) && (fabsf(o6-1.f)<=T1) && (fabsf(o7)<=T0);

    float q[32];
    #pragma unroll
    for (int c = 0; c < 32; c++) {
        float s = bs[c];
        const float4* w = (const float4*)(Ws + c * 32);
        #pragma unroll
        for (int k = 0; k < 8; k++) s += dot4(A[k], w[k]);
        q[c] = s;
    }
    float s1[2] = {0.f, 0.f}, s2[2] = {0.f, 0.f};
    #pragma unroll
    for (int c = 0; c < 32; c++) {
        const float4* w = (const float4*)(Ws + (32 + c) * 32);
        float k1 = bs[32 + c], k2 = k1;
        #pragma unroll
        for (int k = 0; k < 8; k++) { k1 += dot4(M1[k], w[k]); k2 += dot4(M2[k], w[k]); }
        int hh = c >> 4;
        s1[hh] = fmaf(q[c], k1, s1[hh]);
        s2[hh] = fmaf(q[c], k2, s2[hh]);
    }
    float w1[2], w2[2];
    #pragma unroll
    for (int hh = 0; hh < 2; hh++) {
        float a = s1[hh] * 0.25f + (mk0 ? -1e9f : 0.f);
        float b = s2[hh] * 0.25f + (mk1 ? -1e9f : 0.f);
        float m = fmaxf(a, b);
        float e1 = __expf(a - m), e2 = __expf(b - m);
        float inv = __fdividef(1.0f, e1 + e2);
        w1[hh] = e1 * inv; w2[hh] = e2 * inv;
    }
    float ctx[32];
    #pragma unroll
    for (int c = 0; c < 32; c++) {
        const float4* w = (const float4*)(Ws + (64 + c) * 32);
        float v1 = bs[64 + c], v2 = v1;
        #pragma unroll
        for (int k = 0; k < 8; k++) { v1 += dot4(M1[k], w[k]); v2 += dot4(M2[k], w[k]); }
        int hh = c >> 4;
        ctx[c] = w1[hh] * v1 + w2[hh] * v2;
    }
    bool allm = mk0 && mk1;
    float at[32];
    #pragma unroll
    for (int o = 0; o < 32; o++) {
        float s = bo[o];
        const float* w = Wo + o * 32;
        #pragma unroll
        for (int c = 0; c < 32; c++) s = fmaf(ctx[c], w[c], s);
        at[o] = allm ? 0.0f : s;
    }
    float4* fr = (float4*)(g_fusion + (size_t)n * 64);
    #pragma unroll
    for (int i = 0; i < 8; i++) fr[i] = A[i];
    #pragma unroll
    for (int i = 0; i < 8; i++)
        fr[8 + i] = make_float4(at[4*i], at[4*i+1], at[4*i+2], at[4*i+3]);
}

// ================= HMMA MLP: 128 rows/CTA, split-bf16 3xMMA =================
// Warp w owns cols 32w..32w+31 (4 n-tiles) x rows 0..127 (8 m-tiles).
// smem: red | b0 | b1 | ow | A1h | A1l | Wbufh | Wbufl
// A0h/A0l alias into A1h region; W0 aliases Wbuf.
#define PA0 144   // A0 row pitch bytes (64 bf16 + 8 pad)
#define PW  144   // weight tile row pitch bytes (64 bf16 + 8 pad)
#define PA1 528   // A1 row pitch bytes (256 bf16 + 8 pad)
#define SM_RED 0
#define SM_B0  4096
#define SM_B1  5120
#define SM_OW  6144
#define SM_A1H 7168                       // 128*528 = 67584
#define SM_A1L (SM_A1H + 67584)           // 74752
#define SM_WBH (SM_A1L + 67584)           // 142336, 256*144 = 36864
#define SM_WBL (SM_WBH + 36864)           // 179200
#define SM_TOTAL (SM_WBL + 36864)         // 216064
#define SM_A0H SM_A1H
#define SM_A0L (SM_A1H + 18432)

__global__ void __launch_bounds__(256) k_mlp_h(
    const float* __restrict__ b0, const float* __restrict__ b1,
    const float* __restrict__ oW, const float* __restrict__ ob,
    float* __restrict__ val)
{
    extern __shared__ char smem[];
    uint32_t smb = smem_u32(smem);
    int tid = threadIdx.x, wid = tid >> 5, lane = tid & 31;
    int g = lane >> 2, tq = lane & 3;
    int row0 = blockIdx.x * 128;
    int n0w = wid * 32;

    float* red = (float*)(smem + SM_RED);
    float* b0s = (float*)(smem + SM_B0);
    float* b1s = (float*)(smem + SM_B1);
    float* ows = (float*)(smem + SM_OW);
    b0s[tid] = b0[tid]; b1s[tid] = b1[tid]; ows[tid] = oW[tid];

    // ldmatrix lane address components
    int aro = lane & 15;                 // A frag row offset
    int aco = (lane >> 1) & 8;           // A frag col offset (+8 for hi tiles)
    int bro = lane & 7;                  // B frag row offset
    int bco = lane & 8;                  // B frag col offset

    // ---- phase A: split fusion tile -> A0h/A0l; copy W0 -> Wbuf ----
    {
        const float4* Fg = (const float4*)g_fusion + (size_t)row0 * 16;
        #pragma unroll
        for (int q = 0; q < 8; q++) {
            int id = tid + 256 * q;
            int r = id >> 4, c4 = id & 15;
            float4 v = Fg[id];
            __nv_bfloat162 h0 = split_hi(v.x, v.y), l0 = split_lo(v.x, v.y, h0);
            __nv_bfloat162 h1 = split_hi(v.z, v.w), l1 = split_lo(v.z, v.w, h1);
            char* pH = smem + SM_A0H + r * PA0 + c4 * 8;
            char* pL = smem + SM_A0L + r * PA0 + c4 * 8;
            *(__nv_bfloat162*)(pH)     = h0;
            *(__nv_bfloat162*)(pH + 4) = h1;
            *(__nv_bfloat162*)(pL)     = l0;
            *(__nv_bfloat162*)(pL + 4) = l1;
        }
        const uint4* sh = (const uint4*)g_W0h;
        const uint4* sl = (const uint4*)g_W0l;
        #pragma unroll
        for (int q = 0; q < 8; q++) {
            int id = tid + 256 * q;
            int nn = id >> 3, j = id & 7;
            *(uint4*)(smem + SM_WBH + nn * PW + j * 16) = sh[id];
            *(uint4*)(smem + SM_WBL + nn * PW + j * 16) = sl[id];
        }
    }
    __syncthreads();

    // ---- phase B: layer 0 (k=64) ----
    float acc[8][4][4];
    #pragma unroll
    for (int m = 0; m < 8; m++)
        #pragma unroll
        for (int nt = 0; nt < 4; nt++)
            #pragma unroll
            for (int r = 0; r < 4; r++) acc[m][nt][r] = 0.f;
    #pragma unroll 1
    for (int k16 = 0; k16 < 4; k16++) {
        int kc = k16 * 16;
        uint32_t bh[4][2], bl[4][2];
        #pragma unroll
        for (int nt = 0; nt < 4; nt++) {
            uint32_t ba = (uint32_t)((n0w + 8 * nt + bro) * PW + (kc + bco) * 2);
            ldsm2(bh[nt], smb + SM_WBH + ba);
            ldsm2(bl[nt], smb + SM_WBL + ba);
        }
        #pragma unroll
        for (int mh = 0; mh < 2; mh++) {
            uint32_t ah[4][4], al[4][4];
            #pragma unroll
            for (int m = 0; m < 4; m++) {
                uint32_t aa = (uint32_t)(((mh * 4 + m) * 16 + aro) * PA0 + (kc + aco) * 2);
                ldsm4(ah[m], smb + SM_A0H + aa);
                ldsm4(al[m], smb + SM_A0L + aa);
            }
            #pragma unroll
            for (int m = 0; m < 4; m++)
                #pragma unroll
                for (int nt = 0; nt < 4; nt++) {
                    mma16816(acc[mh*4+m][nt], ah[m], bh[nt]);
                    mma16816(acc[mh*4+m][nt], ah[m], bl[nt]);
                    mma16816(acc[mh*4+m][nt], al[m], bh[nt]);
                }
        }
    }
    __syncthreads();   // all L0 reads of A0/W0 done before overwrite

    // ---- phase C: bias+leaky -> split -> A1h/A1l ----
    #pragma unroll
    for (int m = 0; m < 8; m++)
        #pragma unroll
        for (int nt = 0; nt < 4; nt++) {
            int c0 = n0w + 8 * nt + 2 * tq;
            float v0 = acc[m][nt][0] + b0s[c0];
            float v1 = acc[m][nt][1] + b0s[c0 + 1];
            float v2 = acc[m][nt][2] + b0s[c0];
            float v3 = acc[m][nt][3] + b0s[c0 + 1];
            v0 = v0 > 0.f ? v0 : 0.01f * v0;
            v1 = v1 > 0.f ? v1 : 0.01f * v1;
            v2 = v2 > 0.f ? v2 : 0.01f * v2;
            v3 = v3 > 0.f ? v3 : 0.01f * v3;
            int r0 = 16 * m + g, r1 = r0 + 8;
            __nv_bfloat162 h01 = split_hi(v0, v1), l01 = split_lo(v0, v1, h01);
            __nv_bfloat162 h23 = split_hi(v2, v3), l23 = split_lo(v2, v3, h23);
            *(__nv_bfloat162*)(smem + SM_A1H + r0 * PA1 + c0 * 2) = h01;
            *(__nv_bfloat162*)(smem + SM_A1L + r0 * PA1 + c0 * 2) = l01;
            *(__nv_bfloat162*)(smem + SM_A1H + r1 * PA1 + c0 * 2) = h23;
            *(__nv_bfloat162*)(smem + SM_A1L + r1 * PA1 + c0 * 2) = l23;
        }

    // ---- phase D: layer 1 (k=256), W1 streamed in 4 k-chunks of 64 ----
    float a2[8][4][4];
    #pragma unroll
    for (int m = 0; m < 8; m++)
        #pragma unroll
        for (int nt = 0; nt < 4; nt++)
            #pragma unroll
            for (int r = 0; r < 4; r++) a2[m][nt][r] = 0.f;
    const uint4* W1h4 = (const uint4*)g_W1h;   // row pitch 32 uint4
    const uint4* W1l4 = (const uint4*)g_W1l;
    #pragma unroll 1
    for (int c = 0; c < 4; c++) {
        __syncthreads();   // prior reads of Wbuf / A1 writes visible
        #pragma unroll
        for (int q = 0; q < 8; q++) {
            int id = tid + 256 * q;
            int nn = id >> 3, j = id & 7;
            *(uint4*)(smem + SM_WBH + nn * PW + j * 16) = W1h4[nn * 32 + c * 8 + j];
            *(uint4*)(smem + SM_WBL + nn * PW + j * 16) = W1l4[nn * 32 + c * 8 + j];
        }
        __syncthreads();
        #pragma unroll 1
        for (int k16 = 0; k16 < 4; k16++) {
            int kcA = c * 64 + k16 * 16;
            int kcW = k16 * 16;
            uint32_t bh[4][2], bl[4][2];
            #pragma unroll
            for (int nt = 0; nt < 4; nt++) {
                uint32_t ba = (uint32_t)((n0w + 8 * nt + bro) * PW + (kcW + bco) * 2);
                ldsm2(bh[nt], smb + SM_WBH + ba);
                ldsm2(bl[nt], smb + SM_WBL + ba);
            }
            #pragma unroll
            for (int mh = 0; mh < 2; mh++) {
                uint32_t ah[4][4], al[4][4];
                #pragma unroll
                for (int m = 0; m < 4; m++) {
                    uint32_t aa = (uint32_t)(((mh * 4 + m) * 16 + aro) * PA1 + (kcA + aco) * 2);
                    ldsm4(ah[m], smb + SM_A1H + aa);
                    ldsm4(al[m], smb + SM_A1L + aa);
                }
                #pragma unroll
                for (int m = 0; m < 4; m++)
                    #pragma unroll
                    for (int nt = 0; nt < 4; nt++) {
                        mma16816(a2[mh*4+m][nt], ah[m], bh[nt]);
                        mma16816(a2[mh*4+m][nt], ah[m], bl[nt]);
                        mma16816(a2[mh*4+m][nt], al[m], bh[nt]);
                    }
            }
        }
    }

    // ---- phase E: bias+leaky, dot out_W, reduce ----
    float p[8][2];
    #pragma unroll
    for (int m = 0; m < 8; m++) { p[m][0] = 0.f; p[m][1] = 0.f; }
    #pragma unroll
    for (int m = 0; m < 8; m++)
        #pragma unroll
        for (int nt = 0; nt < 4; nt++) {
            int c0 = n0w + 8 * nt + 2 * tq;
            float w0v = ows[c0], w1v = ows[c0 + 1];
            float bb0 = b1s[c0], bb1 = b1s[c0 + 1];
            float v0 = a2[m][nt][0] + bb0;
            float v1 = a2[m][nt][1] + bb1;
            float v2 = a2[m][nt][2] + bb0;
            float v3 = a2[m][nt][3] + bb1;
            v0 = v0 > 0.f ? v0 : 0.01f * v0;
            v1 = v1 > 0.f ? v1 : 0.01f * v1;
            v2 = v2 > 0.f ? v2 : 0.01f * v2;
            v3 = v3 > 0.f ? v3 : 0.01f * v3;
            p[m][0] = fmaf(v0, w0v, p[m][0]);
            p[m][0] = fmaf(v1, w1v, p[m][0]);
            p[m][1] = fmaf(v2, w0v, p[m][1]);
            p[m][1] = fmaf(v3, w1v, p[m][1]);
        }
    #pragma unroll
    for (int off = 1; off <= 2; off <<= 1)
        #pragma unroll
        for (int m = 0; m < 8; m++) {
            p[m][0] += __shfl_xor_sync(0xffffffffu, p[m][0], off);
            p[m][1] += __shfl_xor_sync(0xffffffffu, p[m][1], off);
        }
    if (tq == 0) {
        #pragma unroll
        for (int m = 0; m < 8; m++) {
            red[wid * 128 + 16 * m + g]     = p[m][0];
            red[wid * 128 + 16 * m + g + 8] = p[m][1];
        }
    }
    __syncthreads();
    if (tid < 128) {
        float s = __ldg(ob);
        #pragma unroll
        for (int w8 = 0; w8 < 8; w8++) s += red[w8 * 128 + tid];
        val[row0 + tid] = s;
    }
}

extern "C" void kernel_launch(void* const* d_in, const int* in_sizes, int n_in,
                              void* d_out, int out_size) {
    const float* obs   = (const float*)d_in[0];
    const float* rnn   = (const float*)d_in[1];
    const float* eAW   = (const float*)d_in[2];
    const float* eAb   = (const float*)d_in[3];
    const float* eMW   = (const float*)d_in[4];
    const float* eMb   = (const float*)d_in[5];
    const float* aWih  = (const float*)d_in[6];
    const float* aWhh  = (const float*)d_in[7];
    const float* abih  = (const float*)d_in[8];
    const float* abhh  = (const float*)d_in[9];
    const float* mWih  = (const float*)d_in[10];
    const float* mWhh  = (const float*)d_in[11];
    const float* mbih  = (const float*)d_in[12];
    const float* mbhh  = (const float*)d_in[13];
    const float* Win   = (const float*)d_in[14];
    const float* bin   = (const float*)d_in[15];
    const float* Wout  = (const float*)d_in[16];
    const float* bout  = (const float*)d_in[17];
    const float* W0    = (const float*)d_in[18];
    const float* b0    = (const float*)d_in[19];
    const float* W1    = (const float*)d_in[20];
    const float* b1    = (const float*)d_in[21];
    const float* oW    = (const float*)d_in[22];
    const float* ob    = (const float*)d_in[23];

    float* out_val = (float*)d_out;
    float* out_h   = (float*)d_out + Nq;

    k_pack<<<320, 256>>>(W0, W1);
    k_gru<<<(Bq + 2 * Bq) / 4, 128>>>(obs, rnn, eAW, eAb, eMW, eMb,
                                      aWih, aWhh, abih, abhh,
                                      mWih, mWhh, mbih, mbhh, out_h);
    k_attn<<<Nq / 32 / 8, 256>>>(obs, Win, bin, Wout, bout);
    cudaFuncSetAttribute(k_mlp_h, cudaFuncAttributeMaxDynamicSharedMemorySize, SM_TOTAL);
    k_mlp_h<<<Nq / 128, 256, SM_TOTAL>>>(b0, b1, oW, ob, out_val);
}

// round 6
// speedup vs baseline: 2.4700x; 1.1531x over previous
#include <cuda_runtime.h>
#include <cuda_bf16.h>
#include <cstdint>

#define Bq 2048
#define Tq 128
#define Nq (Bq*Tq)

// ---------------- scratch (no allocations allowed) ----------------
__device__ float g_air[(size_t)Nq * 32];
__device__ float g_m1 [(size_t)Nq * 32];
__device__ float g_m2 [(size_t)Nq * 32];
__device__ float g_fusion[(size_t)Nq * 64];
// prepacked bf16 hi/lo weights, plain row-major [n][k]
__device__ __nv_bfloat16 g_W0h[256 * 64];
__device__ __nv_bfloat16 g_W0l[256 * 64];
__device__ __nv_bfloat16 g_W1h[256 * 256];
__device__ __nv_bfloat16 g_W1l[256 * 256];

__device__ __forceinline__ float fsig(float x) {
    return __fdividef(1.0f, 1.0f + __expf(-x));
}
__device__ __forceinline__ float ftanh(float x) {
    x = fminf(fmaxf(x, -12.0f), 12.0f);
    float e = __expf(-2.0f * x);
    return __fdividef(1.0f - e, 1.0f + e);
}

// packed 2xfp32 FMA
union F2U { float2 f; unsigned long long u; };
__device__ __forceinline__ float2 ffma2(float2 a, float2 b, float2 c) {
    F2U A, B, C, D;
    A.f = a; B.f = b; C.f = c;
    asm("fma.rn.f32x2 %0, %1, %2, %3;" : "=l"(D.u) : "l"(A.u), "l"(B.u), "l"(C.u));
    return D.f;
}
// float4 . float4 accumulated into float2 via two ffma2
__device__ __forceinline__ float2 dot4_2(float4 a, float4 b, float2 acc) {
    acc = ffma2(make_float2(a.x, a.y), make_float2(b.x, b.y), acc);
    acc = ffma2(make_float2(a.z, a.w), make_float2(b.z, b.w), acc);
    return acc;
}

// ---------------- mma.sync / cp.async helpers ----------------
__device__ __forceinline__ uint32_t smem_u32(const void* p) {
    uint32_t a;
    asm("{ .reg .u64 t; cvta.to.shared.u64 t, %1; cvt.u32.u64 %0, t; }" : "=r"(a) : "l"(p));
    return a;
}
__device__ __forceinline__ void ldsm4(uint32_t* a, uint32_t addr) {
    asm volatile("ldmatrix.sync.aligned.m8n8.x4.shared.b16 {%0,%1,%2,%3}, [%4];"
        : "=r"(a[0]), "=r"(a[1]), "=r"(a[2]), "=r"(a[3]) : "r"(addr));
}
__device__ __forceinline__ void ldsm2(uint32_t* b, uint32_t addr) {
    asm volatile("ldmatrix.sync.aligned.m8n8.x2.shared.b16 {%0,%1}, [%2];"
        : "=r"(b[0]), "=r"(b[1]) : "r"(addr));
}
__device__ __forceinline__ void mma16816(float* c, const uint32_t* a, const uint32_t* b) {
    asm volatile("mma.sync.aligned.m16n8k16.row.col.f32.bf16.bf16.f32 "
        "{%0,%1,%2,%3}, {%4,%5,%6,%7}, {%8,%9}, {%0,%1,%2,%3};"
        : "+f"(c[0]), "+f"(c[1]), "+f"(c[2]), "+f"(c[3])
        : "r"(a[0]), "r"(a[1]), "r"(a[2]), "r"(a[3]), "r"(b[0]), "r"(b[1]));
}
__device__ __forceinline__ void cpa16(uint32_t dst, const void* src) {
    asm volatile("cp.async.cg.shared.global [%0], [%1], 16;" :: "r"(dst), "l"(src));
}
#define CPA_COMMIT() asm volatile("cp.async.commit_group;" ::: "memory")

__device__ __forceinline__ __nv_bfloat162 split_hi(float a, float b) {
    __nv_bfloat162 h; h.x = __float2bfloat16(a); h.y = __float2bfloat16(b); return h;
}
__device__ __forceinline__ __nv_bfloat162 split_lo(float a, float b, __nv_bfloat162 h) {
    __nv_bfloat162 l;
    l.x = __float2bfloat16(a - __bfloat162float(h.x));
    l.y = __float2bfloat16(b - __bfloat162float(h.y));
    return l;
}

// ================= weight prepack: fp32 -> bf16 hi/lo =================
__global__ void k_pack(const float* __restrict__ W0, const float* __restrict__ W1) {
    int i = blockIdx.x * 256 + threadIdx.x;
    if (i < 16384) {
        float w = W0[i];
        __nv_bfloat16 h = __float2bfloat16(w);
        g_W0h[i] = h;
        g_W0l[i] = __float2bfloat16(w - __bfloat162float(h));
    } else if (i < 16384 + 65536) {
        int j = i - 16384;
        float w = W1[j];
        __nv_bfloat16 h = __float2bfloat16(w);
        g_W1h[j] = h;
        g_W1l[j] = __float2bfloat16(w - __bfloat162float(h));
    }
}

// ================= GRU: one warp per batch lane =================
// Double-buffered h/x parity slots -> one syncwarp per step.
// ffma2 chains split into two 8-deep halves (6 independent accumulators).
template<int KIN>
__device__ __forceinline__ void gru_warp(
    const float* __restrict__ obs_row, int xoff,
    const float* __restrict__ encW, const float* __restrict__ encB,
    const float* __restrict__ Wih,  const float* __restrict__ bih,
    const float* __restrict__ Whh,  const float* __restrict__ bhh,
    float h, float* __restrict__ feat, float* __restrict__ nexth,
    int la, volatile float* sm)   // sm: 2 x 48 floats
{
    float wc0[KIN], wc1[KIN], wc2[KIN];
    float bc0 = 0.f, bc1 = 0.f, bc2 = 0.f;
    #pragma unroll
    for (int g = 0; g < 3; g++) {
        int j = la + 32 * g;
        float wrow[32];
        const float4* wp = (const float4*)(Wih + j * 32);
        #pragma unroll
        for (int q = 0; q < 8; q++) {
            float4 v = wp[q];
            wrow[q*4+0]=v.x; wrow[q*4+1]=v.y; wrow[q*4+2]=v.z; wrow[q*4+3]=v.w;
        }
        #pragma unroll
        for (int k = 0; k < KIN; k++) {
            float s = 0.0f;
            #pragma unroll
            for (int m = 0; m < 32; m++) s = fmaf(wrow[m], __ldg(encW + m * KIN + k), s);
            if (g == 0) wc0[k] = s; else if (g == 1) wc1[k] = s; else wc2[k] = s;
        }
        float sb = __ldg(bih + j);
        #pragma unroll
        for (int m = 0; m < 32; m++) sb = fmaf(wrow[m], __ldg(encB + m), sb);
        if (g == 0) bc0 = sb; else if (g == 1) bc1 = sb; else bc2 = sb;
    }
    float2 wh0[16], wh1[16], wh2[16];
    {
        const float4* p0 = (const float4*)(Whh + (la     ) * 32);
        const float4* p1 = (const float4*)(Whh + (la + 32) * 32);
        const float4* p2 = (const float4*)(Whh + (la + 64) * 32);
        #pragma unroll
        for (int q = 0; q < 8; q++) {
            float4 a=p0[q]; wh0[q*2]=make_float2(a.x,a.y); wh0[q*2+1]=make_float2(a.z,a.w);
            float4 b=p1[q]; wh1[q*2]=make_float2(b.x,b.y); wh1[q*2+1]=make_float2(b.z,b.w);
            float4 c=p2[q]; wh2[q*2]=make_float2(c.x,c.y); wh2[q*2+1]=make_float2(c.z,c.w);
        }
    }
    float bcr = bc0 + __ldg(bhh + la);
    float bcz = bc1 + __ldg(bhh + la + 32);
    float bgn = __ldg(bhh + la + 64);

    // prologue: h0 and x0 into parity slot 0
    sm[la] = h;
    if (la < 15) sm[33 + la] = obs_row[la];
    __syncwarp();

    #pragma unroll 1
    for (int t = 0; t < Tq; t++) {
        volatile float* bp = sm + (t & 1) * 48;
        volatile float* bn = sm + ((t + 1) & 1) * 48;
        float xr = bcr, xz = bcz, xn = bc2;
        #pragma unroll
        for (int k = 0; k < KIN; k++) {
            float xk = bp[33 + xoff + k];
            xr = fmaf(xk, wc0[k], xr);
            xz = fmaf(xk, wc1[k], xz);
            xn = fmaf(xk, wc2[k], xn);
        }
        // two independent 8-deep chains per gate
        float2 r2a = make_float2(xr, 0.f), r2b = make_float2(0.f, 0.f);
        float2 z2a = make_float2(xz, 0.f), z2b = make_float2(0.f, 0.f);
        float2 n2a = make_float2(bgn, 0.f), n2b = make_float2(0.f, 0.f);
        #pragma unroll
        for (int k = 0; k < 8; k++) {
            float2 hA = make_float2(bp[2*k],      bp[2*k+1]);
            float2 hB = make_float2(bp[16+2*k],   bp[16+2*k+1]);
            r2a = ffma2(hA, wh0[k],   r2a);
            r2b = ffma2(hB, wh0[k+8], r2b);
            z2a = ffma2(hA, wh1[k],   z2a);
            z2b = ffma2(hB, wh1[k+8], z2b);
            n2a = ffma2(hA, wh2[k],   n2a);
            n2b = ffma2(hB, wh2[k+8], n2b);
        }
        // prefetch next x into the next parity slot (hidden under MUFUs)
        if (t + 1 < Tq && la < 15) bn[33 + la] = obs_row[(t + 1) * 15 + la];
        float r = fsig(r2a.x + r2a.y + r2b.x + r2b.y);
        float z = fsig(z2a.x + z2a.y + z2b.x + z2b.y);
        float n = ftanh(fmaf(r, n2a.x + n2a.y + n2b.x + n2b.y, xn));
        h = n + z * (h - n);
        bn[la] = h;
        feat[t * 32 + la] = h;
        __syncwarp();
    }
    *nexth = h;
}

__global__ void __launch_bounds__(128) k_gru(
    const float* __restrict__ obs, const float* __restrict__ rnn,
    const float* __restrict__ eAW, const float* __restrict__ eAb,
    const float* __restrict__ eMW, const float* __restrict__ eMb,
    const float* __restrict__ aWih, const float* __restrict__ aWhh,
    const float* __restrict__ abih, const float* __restrict__ abhh,
    const float* __restrict__ mWih, const float* __restrict__ mWhh,
    const float* __restrict__ mbih, const float* __restrict__ mbhh,
    float* __restrict__ next_h)
{
    __shared__ float sm[4][96];
    int w  = blockIdx.x * 4 + (threadIdx.x >> 5);
    int la = threadIdx.x & 31;
    int wi = threadIdx.x >> 5;
    if (w < Bq) {
        int b = w;
        float h = rnn[b * 96 + la];
        gru_warp<7>(obs + (size_t)b * Tq * 15, 8, eAW, eAb, aWih, abih, aWhh, abhh,
                    h, g_air + (size_t)b * Tq * 32, next_h + b * 96 + la, la, sm[wi]);
    } else {
        int i = w - Bq;
        int b = (i < Bq) ? i : i - Bq;
        int xoff = (i < Bq) ? 0 : 4;
        float h = rnn[(i >> 1) * 96 + 32 + 32 * (i & 1) + la];
        float* feat = (i < Bq) ? (g_m1 + (size_t)i * Tq * 32)
                               : (g_m2 + (size_t)(i - Bq) * Tq * 32);
        gru_warp<4>(obs + (size_t)b * Tq * 15, xoff, eMW, eMb, mWih, mbih, mWhh, mbhh,
                    h, feat, next_h + (i >> 1) * 96 + 32 + 32 * (i & 1) + la, la, sm[wi]);
    }
}

// ================= attention + fusion: lane = row, ffma2 dots =================
__global__ void __launch_bounds__(256) k_attn(
    const float* __restrict__ obs,
    const float* __restrict__ Win, const float* __restrict__ bin,
    const float* __restrict__ Wout, const float* __restrict__ bout)
{
    __shared__ float Ws[96 * 32];
    __shared__ float Wo[32 * 32];
    __shared__ float bs[96], bo[32];
    int t = threadIdx.x;
    for (int i = t; i < 96 * 32; i += 256) Ws[i] = Win[i];
    for (int i = t; i < 32 * 32; i += 256) Wo[i] = Wout[i];
    if (t < 96) bs[t] = bin[t];
    if (t < 32) bo[t] = bout[t];
    __syncthreads();

    int warp = blockIdx.x * 8 + (t >> 5);
    int la = t & 31;
    int n = warp * 32 + la;

    float4 A[8], M1[8], M2[8];
    const float4* ap = (const float4*)(g_air + (size_t)n * 32);
    const float4* p1 = (const float4*)(g_m1 + (size_t)n * 32);
    const float4* p2 = (const float4*)(g_m2 + (size_t)n * 32);
    #pragma unroll
    for (int i = 0; i < 8; i++) { A[i] = ap[i]; M1[i] = p1[i]; M2[i] = p2[i]; }

    const float* op = obs + (size_t)n * 15;
    float o0=op[0],o1=op[1],o2=op[2],o3=op[3],o4=op[4],o5=op[5],o6=op[6],o7=op[7];
    const float T1 = 1.001e-5f, T0 = 1e-8f;
    bool mk0 = (fabsf(o0-1.f)<=T1) && (fabsf(o1)<=T0) && (fabsf(o2-1.f)<=T1) && (fabsf(o3)<=T0);
    bool mk1 = (fabsf(o4-1.f)<=T1) && (fabsf(o5)<=T0) && (fabsf(o6-1.f)<=T1) && (fabsf(o7)<=T0);

    float q[32];
    #pragma unroll
    for (int c = 0; c < 32; c++) {
        float2 a = make_float2(bs[c], 0.f);
        const float4* w = (const float4*)(Ws + c * 32);
        #pragma unroll
        for (int k = 0; k < 8; k++) a = dot4_2(A[k], w[k], a);
        q[c] = a.x + a.y;
    }
    float s1[2] = {0.f, 0.f}, s2[2] = {0.f, 0.f};
    #pragma unroll
    for (int c = 0; c < 32; c++) {
        const float4* w = (const float4*)(Ws + (32 + c) * 32);
        float2 k1 = make_float2(bs[32 + c], 0.f), k2 = make_float2(0.f, 0.f);
        #pragma unroll
        for (int k = 0; k < 8; k++) { k1 = dot4_2(M1[k], w[k], k1); k2 = dot4_2(M2[k], w[k], k2); }
        int hh = c >> 4;
        s1[hh] = fmaf(q[c], k1.x + k1.y, s1[hh]);
        s2[hh] = fmaf(q[c], k2.x + k2.y + bs[32 + c], s2[hh]);
    }
    float w1[2], w2[2];
    #pragma unroll
    for (int hh = 0; hh < 2; hh++) {
        float a = s1[hh] * 0.25f + (mk0 ? -1e9f : 0.f);
        float b = s2[hh] * 0.25f + (mk1 ? -1e9f : 0.f);
        float m = fmaxf(a, b);
        float e1 = __expf(a - m), e2 = __expf(b - m);
        float inv = __fdividef(1.0f, e1 + e2);
        w1[hh] = e1 * inv; w2[hh] = e2 * inv;
    }
    float ctx[32];
    #pragma unroll
    for (int c = 0; c < 32; c++) {
        const float4* w = (const float4*)(Ws + (64 + c) * 32);
        float2 v1 = make_float2(bs[64 + c], 0.f), v2 = make_float2(0.f, 0.f);
        #pragma unroll
        for (int k = 0; k < 8; k++) { v1 = dot4_2(M1[k], w[k], v1); v2 = dot4_2(M2[k], w[k], v2); }
        int hh = c >> 4;
        ctx[c] = w1[hh] * (v1.x + v1.y) + w2[hh] * (v2.x + v2.y + bs[64 + c]);
    }
    bool allm = mk0 && mk1;
    float at[32];
    #pragma unroll
    for (int o = 0; o < 32; o++) {
        float2 a = make_float2(bo[o], 0.f);
        const float4* w = (const float4*)(Wo + o * 32);
        #pragma unroll
        for (int c4 = 0; c4 < 8; c4++) {
            float4 cv = make_float4(ctx[4*c4], ctx[4*c4+1], ctx[4*c4+2], ctx[4*c4+3]);
            a = dot4_2(cv, w[c4], a);
        }
        at[o] = allm ? 0.0f : (a.x + a.y);
    }
    float4* fr = (float4*)(g_fusion + (size_t)n * 64);
    #pragma unroll
    for (int i = 0; i < 8; i++) fr[i] = A[i];
    #pragma unroll
    for (int i = 0; i < 8; i++)
        fr[8 + i] = make_float4(at[4*i], at[4*i+1], at[4*i+2], at[4*i+3]);
}

// ================= HMMA MLP with cp.async double-buffered W1 =================
#define PA0 144   // A0 row pitch (64 bf16 + pad)
#define PW0 144   // W0 row pitch (64 bf16 + pad)
#define PW1 80    // W1 chunk row pitch (32 bf16 + 16B pad), 16B-aligned rows
#define PA1 528   // A1 row pitch (256 bf16 + pad)
#define SM_RED 0
#define SM_B0  4096
#define SM_B1  5120
#define SM_OW  6144
#define SM_A1H 7168                       // 128*528 = 67584
#define SM_A1L (SM_A1H + 67584)           // 74752
#define SM_WB  (SM_A1L + 67584)           // 142336; two buffers of 40960
#define SM_TOTAL (SM_WB + 2 * 40960)      // 224256
#define SM_A0H SM_A1H
#define SM_A0L (SM_A1H + 18432)
#define SM_W0H SM_WB                      // W0 (pitch 144): h 36864 @WB
#define SM_W0L (SM_WB + 36864)            //                 l 36864

__global__ void __launch_bounds__(256) k_mlp_h(
    const float* __restrict__ b0, const float* __restrict__ b1,
    const float* __restrict__ oW, const float* __restrict__ ob,
    float* __restrict__ val)
{
    extern __shared__ char smem[];
    uint32_t smb = smem_u32(smem);
    int tid = threadIdx.x, wid = tid >> 5, lane = tid & 31;
    int g = lane >> 2, tq = lane & 3;
    int row0 = blockIdx.x * 128;
    int n0w = wid * 32;

    float* red = (float*)(smem + SM_RED);
    float* b0s = (float*)(smem + SM_B0);
    float* b1s = (float*)(smem + SM_B1);
    float* ows = (float*)(smem + SM_OW);
    b0s[tid] = b0[tid]; b1s[tid] = b1[tid]; ows[tid] = oW[tid];

    int aro = lane & 15;
    int aco = (lane >> 1) & 8;
    int bro = lane & 7;
    int bco = lane & 8;

    // ---- phase A: cp.async W0 behind the fusion split ----
    #pragma unroll
    for (int q = 0; q < 8; q++) {
        int id = tid + 256 * q;
        int nn = id >> 3, j = id & 7;
        cpa16(smb + SM_W0H + nn * PW0 + j * 16, g_W0h + nn * 64 + j * 8);
        cpa16(smb + SM_W0L + nn * PW0 + j * 16, g_W0l + nn * 64 + j * 8);
    }
    CPA_COMMIT();
    {
        const float4* Fg = (const float4*)g_fusion + (size_t)row0 * 16;
        #pragma unroll
        for (int q = 0; q < 8; q++) {
            int id = tid + 256 * q;
            int r = id >> 4, c4 = id & 15;
            float4 v = Fg[id];
            __nv_bfloat162 h0 = split_hi(v.x, v.y), l0 = split_lo(v.x, v.y, h0);
            __nv_bfloat162 h1 = split_hi(v.z, v.w), l1 = split_lo(v.z, v.w, h1);
            char* pH = smem + SM_A0H + r * PA0 + c4 * 8;
            char* pL = smem + SM_A0L + r * PA0 + c4 * 8;
            *(__nv_bfloat162*)(pH)     = h0;
            *(__nv_bfloat162*)(pH + 4) = h1;
            *(__nv_bfloat162*)(pL)     = l0;
            *(__nv_bfloat162*)(pL + 4) = l1;
        }
    }
    asm volatile("cp.async.wait_group 0;" ::: "memory");
    __syncthreads();

    // ---- phase B: layer 0 (k=64) ----
    float acc[8][4][4];
    #pragma unroll
    for (int m = 0; m < 8; m++)
        #pragma unroll
        for (int nt = 0; nt < 4; nt++)
            #pragma unroll
            for (int r = 0; r < 4; r++) acc[m][nt][r] = 0.f;
    #pragma unroll 1
    for (int k16 = 0; k16 < 4; k16++) {
        int kc = k16 * 16;
        uint32_t bh[4][2], bl[4][2];
        #pragma unroll
        for (int nt = 0; nt < 4; nt++) {
            uint32_t ba = (uint32_t)((n0w + 8 * nt + bro) * PW0 + (kc + bco) * 2);
            ldsm2(bh[nt], smb + SM_W0H + ba);
            ldsm2(bl[nt], smb + SM_W0L + ba);
        }
        #pragma unroll
        for (int mh = 0; mh < 2; mh++) {
            uint32_t ah[4][4], al[4][4];
            #pragma unroll
            for (int m = 0; m < 4; m++) {
                uint32_t aa = (uint32_t)(((mh * 4 + m) * 16 + aro) * PA0 + (kc + aco) * 2);
                ldsm4(ah[m], smb + SM_A0H + aa);
                ldsm4(al[m], smb + SM_A0L + aa);
            }
            #pragma unroll
            for (int m = 0; m < 4; m++)
                #pragma unroll
                for (int nt = 0; nt < 4; nt++) {
                    mma16816(acc[mh*4+m][nt], ah[m], bh[nt]);
                    mma16816(acc[mh*4+m][nt], ah[m], bl[nt]);
                    mma16816(acc[mh*4+m][nt], al[m], bh[nt]);
                }
        }
    }
    __syncthreads();   // L0 reads of A0/W0 done before overwrite

    // prefetch W1 chunks 0 and 1 into the two buffers (aliases W0 region, safe post-sync)
    #pragma unroll
    for (int cc = 0; cc < 2; cc++) {
        uint32_t dstb = smb + SM_WB + cc * 40960;
        #pragma unroll
        for (int q = 0; q < 8; q++) {
            int id = tid + 256 * q;          // 0..2047
            int part = id >> 10;             // 0=h,1=l
            int r = (id >> 2) & 255, j = id & 3;
            const __nv_bfloat16* src = (part ? g_W1l : g_W1h) + r * 256 + cc * 32 + j * 8;
            cpa16(dstb + part * 20480 + r * PW1 + j * 16, src);
        }
        CPA_COMMIT();
    }

    // ---- phase C: bias+leaky -> split -> A1h/A1l ----
    #pragma unroll
    for (int m = 0; m < 8; m++)
        #pragma unroll
        for (int nt = 0; nt < 4; nt++) {
            int c0 = n0w + 8 * nt + 2 * tq;
            float v0 = acc[m][nt][0] + b0s[c0];
            float v1 = acc[m][nt][1] + b0s[c0 + 1];
            float v2 = acc[m][nt][2] + b0s[c0];
            float v3 = acc[m][nt][3] + b0s[c0 + 1];
            v0 = v0 > 0.f ? v0 : 0.01f * v0;
            v1 = v1 > 0.f ? v1 : 0.01f * v1;
            v2 = v2 > 0.f ? v2 : 0.01f * v2;
            v3 = v3 > 0.f ? v3 : 0.01f * v3;
            int r0 = 16 * m + g, r1 = r0 + 8;
            __nv_bfloat162 h01 = split_hi(v0, v1), l01 = split_lo(v0, v1, h01);
            __nv_bfloat162 h23 = split_hi(v2, v3), l23 = split_lo(v2, v3, h23);
            *(__nv_bfloat162*)(smem + SM_A1H + r0 * PA1 + c0 * 2) = h01;
            *(__nv_bfloat162*)(smem + SM_A1L + r0 * PA1 + c0 * 2) = l01;
            *(__nv_bfloat162*)(smem + SM_A1H + r1 * PA1 + c0 * 2) = h23;
            *(__nv_bfloat162*)(smem + SM_A1L + r1 * PA1 + c0 * 2) = l23;
        }
    __syncthreads();   // A1 visible to all warps

    // ---- phase D: layer 1, 8 k=32 chunks, double-buffered cp.async ----
    float a2[8][4][4];
    #pragma unroll
    for (int m = 0; m < 8; m++)
        #pragma unroll
        for (int nt = 0; nt < 4; nt++)
            #pragma unroll
            for (int r = 0; r < 4; r++) a2[m][nt][r] = 0.f;
    #pragma unroll 1
    for (int c = 0; c < 8; c++) {
        if (c < 7) { asm volatile("cp.async.wait_group 1;" ::: "memory"); }
        else       { asm volatile("cp.async.wait_group 0;" ::: "memory"); }
        __syncthreads();
        uint32_t wb = smb + SM_WB + (c & 1) * 40960;
        #pragma unroll
        for (int k16 = 0; k16 < 2; k16++) {
            int kcA = c * 32 + k16 * 16;
            uint32_t bh[4][2], bl[4][2];
            #pragma unroll
            for (int nt = 0; nt < 4; nt++) {
                uint32_t ba = (uint32_t)((n0w + 8 * nt + bro) * PW1 + (k16 * 16 + bco) * 2);
                ldsm2(bh[nt], wb + ba);
                ldsm2(bl[nt], wb + 20480 + ba);
            }
            #pragma unroll
            for (int mh = 0; mh < 2; mh++) {
                uint32_t ah[4][4], al[4][4];
                #pragma unroll
                for (int m = 0; m < 4; m++) {
                    uint32_t aa = (uint32_t)(((mh * 4 + m) * 16 + aro) * PA1 + (kcA + aco) * 2);
                    ldsm4(ah[m], smb + SM_A1H + aa);
                    ldsm4(al[m], smb + SM_A1L + aa);
                }
                #pragma unroll
                for (int m = 0; m < 4; m++)
                    #pragma unroll
                    for (int nt = 0; nt < 4; nt++) {
                        mma16816(a2[mh*4+m][nt], ah[m], bh[nt]);
                        mma16816(a2[mh*4+m][nt], ah[m], bl[nt]);
                        mma16816(a2[mh*4+m][nt], al[m], bh[nt]);
                    }
            }
        }
        __syncthreads();   // all warps done reading buf (c&1)
        if (c + 2 < 8) {
            uint32_t dstb = smb + SM_WB + (c & 1) * 40960;
            #pragma unroll
            for (int q = 0; q < 8; q++) {
                int id = tid + 256 * q;
                int part = id >> 10;
                int r = (id >> 2) & 255, j = id & 3;
                const __nv_bfloat16* src = (part ? g_W1l : g_W1h) + r * 256 + (c + 2) * 32 + j * 8;
                cpa16(dstb + part * 20480 + r * PW1 + j * 16, src);
            }
            CPA_COMMIT();
        }
    }

    // ---- phase E: bias+leaky, dot out_W, reduce ----
    float p[8][2];
    #pragma unroll
    for (int m = 0; m < 8; m++) { p[m][0] = 0.f; p[m][1] = 0.f; }
    #pragma unroll
    for (int m = 0; m < 8; m++)
        #pragma unroll
        for (int nt = 0; nt < 4; nt++) {
            int c0 = n0w + 8 * nt + 2 * tq;
            float w0v = ows[c0], w1v = ows[c0 + 1];
            float bb0 = b1s[c0], bb1 = b1s[c0 + 1];
            float v0 = a2[m][nt][0] + bb0;
            float v1 = a2[m][nt][1] + bb1;
            float v2 = a2[m][nt][2] + bb0;
            float v3 = a2[m][nt][3] + bb1;
            v0 = v0 > 0.f ? v0 : 0.01f * v0;
            v1 = v1 > 0.f ? v1 : 0.01f * v1;
            v2 = v2 > 0.f ? v2 : 0.01f * v2;
            v3 = v3 > 0.f ? v3 : 0.01f * v3;
            p[m][0] = fmaf(v0, w0v, p[m][0]);
            p[m][0] = fmaf(v1, w1v, p[m][0]);
            p[m][1] = fmaf(v2, w0v, p[m][1]);
            p[m][1] = fmaf(v3, w1v, p[m][1]);
        }
    #pragma unroll
    for (int off = 1; off <= 2; off <<= 1)
        #pragma unroll
        for (int m = 0; m < 8; m++) {
            p[m][0] += __shfl_xor_sync(0xffffffffu, p[m][0], off);
            p[m][1] += __shfl_xor_sync(0xffffffffu, p[m][1], off);
        }
    if (tq == 0) {
        #pragma unroll
        for (int m = 0; m < 8; m++) {
            red[wid * 128 + 16 * m + g]     = p[m][0];
            red[wid * 128 + 16 * m + g + 8] = p[m][1];
        }
    }
    __syncthreads();
    if (tid < 128) {
        float s = __ldg(ob);
        #pragma unroll
        for (int w8 = 0; w8 < 8; w8++) s += red[w8 * 128 + tid];
        val[row0 + tid] = s;
    }
}

extern "C" void kernel_launch(void* const* d_in, const int* in_sizes, int n_in,
                              void* d_out, int out_size) {
    const float* obs   = (const float*)d_in[0];
    const float* rnn   = (const float*)d_in[1];
    const float* eAW   = (const float*)d_in[2];
    const float* eAb   = (const float*)d_in[3];
    const float* eMW   = (const float*)d_in[4];
    const float* eMb   = (const float*)d_in[5];
    const float* aWih  = (const float*)d_in[6];
    const float* aWhh  = (const float*)d_in[7];
    const float* abih  = (const float*)d_in[8];
    const float* abhh  = (const float*)d_in[9];
    const float* mWih  = (const float*)d_in[10];
    const float* mWhh  = (const float*)d_in[11];
    const float* mbih  = (const float*)d_in[12];
    const float* mbhh  = (const float*)d_in[13];
    const float* Win   = (const float*)d_in[14];
    const float* bin   = (const float*)d_in[15];
    const float* Wout  = (const float*)d_in[16];
    const float* bout  = (const float*)d_in[17];
    const float* W0    = (const float*)d_in[18];
    const float* b0    = (const float*)d_in[19];
    const float* W1    = (const float*)d_in[20];
    const float* b1    = (const float*)d_in[21];
    const float* oW    = (const float*)d_in[22];
    const float* ob    = (const float*)d_in[23];

    float* out_val = (float*)d_out;
    float* out_h   = (float*)d_out + Nq;

    k_pack<<<320, 256>>>(W0, W1);
    k_gru<<<(Bq + 2 * Bq) / 4, 128>>>(obs, rnn, eAW, eAb, eMW, eMb,
                                      aWih, aWhh, abih, abhh,
                                      mWih, mWhh, mbih, mbhh, out_h);
    k_attn<<<Nq / 32 / 8, 256>>>(obs, Win, bin, Wout, bout);
    cudaFuncSetAttribute(k_mlp_h, cudaFuncAttributeMaxDynamicSharedMemorySize, SM_TOTAL);
    k_mlp_h<<<Nq / 128, 256, SM_TOTAL>>>(b0, b1, oW, ob, out_val);
}

// round 7
// speedup vs baseline: 2.5088x; 1.0157x over previous
#include <cuda_runtime.h>
#include <cuda_bf16.h>
#include <cstdint>

#define Bq 2048
#define Tq 128
#define Nq (Bq*Tq)

// ---------------- scratch (no allocations allowed) ----------------
__device__ float g_air[(size_t)Nq * 32];
__device__ float g_m1 [(size_t)Nq * 32];
__device__ float g_m2 [(size_t)Nq * 32];
__device__ float g_fusion[(size_t)Nq * 64];
// prepacked bf16 hi/lo weights, plain row-major [n][k]
__device__ __nv_bfloat16 g_W0h[256 * 64];
__device__ __nv_bfloat16 g_W0l[256 * 64];
__device__ __nv_bfloat16 g_W1h[256 * 256];
__device__ __nv_bfloat16 g_W1l[256 * 256];

__device__ __forceinline__ float fsig(float x) {
    return __fdividef(1.0f, 1.0f + __expf(-x));
}
__device__ __forceinline__ float ftanh(float x) {
    x = fminf(fmaxf(x, -12.0f), 12.0f);
    float e = __expf(-2.0f * x);
    return __fdividef(1.0f - e, 1.0f + e);
}

// packed 2xfp32 FMA
union F2U { float2 f; unsigned long long u; };
__device__ __forceinline__ float2 ffma2(float2 a, float2 b, float2 c) {
    F2U A, B, C, D;
    A.f = a; B.f = b; C.f = c;
    asm("fma.rn.f32x2 %0, %1, %2, %3;" : "=l"(D.u) : "l"(A.u), "l"(B.u), "l"(C.u));
    return D.f;
}
__device__ __forceinline__ float2 dot4_2(float4 a, float4 b, float2 acc) {
    acc = ffma2(make_float2(a.x, a.y), make_float2(b.x, b.y), acc);
    acc = ffma2(make_float2(a.z, a.w), make_float2(b.z, b.w), acc);
    return acc;
}

// ---------------- mma.sync / cp.async helpers ----------------
__device__ __forceinline__ uint32_t smem_u32(const void* p) {
    uint32_t a;
    asm("{ .reg .u64 t; cvta.to.shared.u64 t, %1; cvt.u32.u64 %0, t; }" : "=r"(a) : "l"(p));
    return a;
}
__device__ __forceinline__ void ldsm4(uint32_t* a, uint32_t addr) {
    asm volatile("ldmatrix.sync.aligned.m8n8.x4.shared.b16 {%0,%1,%2,%3}, [%4];"
        : "=r"(a[0]), "=r"(a[1]), "=r"(a[2]), "=r"(a[3]) : "r"(addr));
}
__device__ __forceinline__ void ldsm2(uint32_t* b, uint32_t addr) {
    asm volatile("ldmatrix.sync.aligned.m8n8.x2.shared.b16 {%0,%1}, [%2];"
        : "=r"(b[0]), "=r"(b[1]) : "r"(addr));
}
__device__ __forceinline__ void mma16816(float* c, const uint32_t* a, const uint32_t* b) {
    asm volatile("mma.sync.aligned.m16n8k16.row.col.f32.bf16.bf16.f32 "
        "{%0,%1,%2,%3}, {%4,%5,%6,%7}, {%8,%9}, {%0,%1,%2,%3};"
        : "+f"(c[0]), "+f"(c[1]), "+f"(c[2]), "+f"(c[3])
        : "r"(a[0]), "r"(a[1]), "r"(a[2]), "r"(a[3]), "r"(b[0]), "r"(b[1]));
}
__device__ __forceinline__ void cpa16(uint32_t dst, const void* src) {
    asm volatile("cp.async.cg.shared.global [%0], [%1], 16;" :: "r"(dst), "l"(src));
}
#define CPA_COMMIT() asm volatile("cp.async.commit_group;" ::: "memory")
#define SWZ(x) ((x) ^ (((x) >> 3) & 0x70))

__device__ __forceinline__ __nv_bfloat162 split_hi(float a, float b) {
    __nv_bfloat162 h; h.x = __float2bfloat16(a); h.y = __float2bfloat16(b); return h;
}
__device__ __forceinline__ __nv_bfloat162 split_lo(float a, float b, __nv_bfloat162 h) {
    __nv_bfloat162 l;
    l.x = __float2bfloat16(a - __bfloat162float(h.x));
    l.y = __float2bfloat16(b - __bfloat162float(h.y));
    return l;
}

// ================= weight prepack: fp32 -> bf16 hi/lo =================
__global__ void k_pack(const float* __restrict__ W0, const float* __restrict__ W1) {
    int i = blockIdx.x * 256 + threadIdx.x;
    if (i < 16384) {
        float w = W0[i];
        __nv_bfloat16 h = __float2bfloat16(w);
        g_W0h[i] = h;
        g_W0l[i] = __float2bfloat16(w - __bfloat162float(h));
    } else if (i < 16384 + 65536) {
        int j = i - 16384;
        float w = W1[j];
        __nv_bfloat16 h = __float2bfloat16(w);
        g_W1h[j] = h;
        g_W1l[j] = __float2bfloat16(w - __bfloat162float(h));
    }
}

// ================= GRU: one warp per batch lane (R6, unchanged) ============
template<int KIN>
__device__ __forceinline__ void gru_warp(
    const float* __restrict__ obs_row, int xoff,
    const float* __restrict__ encW, const float* __restrict__ encB,
    const float* __restrict__ Wih,  const float* __restrict__ bih,
    const float* __restrict__ Whh,  const float* __restrict__ bhh,
    float h, float* __restrict__ feat, float* __restrict__ nexth,
    int la, volatile float* sm)
{
    float wc0[KIN], wc1[KIN], wc2[KIN];
    float bc0 = 0.f, bc1 = 0.f, bc2 = 0.f;
    #pragma unroll
    for (int g = 0; g < 3; g++) {
        int j = la + 32 * g;
        float wrow[32];
        const float4* wp = (const float4*)(Wih + j * 32);
        #pragma unroll
        for (int q = 0; q < 8; q++) {
            float4 v = wp[q];
            wrow[q*4+0]=v.x; wrow[q*4+1]=v.y; wrow[q*4+2]=v.z; wrow[q*4+3]=v.w;
        }
        #pragma unroll
        for (int k = 0; k < KIN; k++) {
            float s = 0.0f;
            #pragma unroll
            for (int m = 0; m < 32; m++) s = fmaf(wrow[m], __ldg(encW + m * KIN + k), s);
            if (g == 0) wc0[k] = s; else if (g == 1) wc1[k] = s; else wc2[k] = s;
        }
        float sb = __ldg(bih + j);
        #pragma unroll
        for (int m = 0; m < 32; m++) sb = fmaf(wrow[m], __ldg(encB + m), sb);
        if (g == 0) bc0 = sb; else if (g == 1) bc1 = sb; else bc2 = sb;
    }
    float2 wh0[16], wh1[16], wh2[16];
    {
        const float4* p0 = (const float4*)(Whh + (la     ) * 32);
        const float4* p1 = (const float4*)(Whh + (la + 32) * 32);
        const float4* p2 = (const float4*)(Whh + (la + 64) * 32);
        #pragma unroll
        for (int q = 0; q < 8; q++) {
            float4 a=p0[q]; wh0[q*2]=make_float2(a.x,a.y); wh0[q*2+1]=make_float2(a.z,a.w);
            float4 b=p1[q]; wh1[q*2]=make_float2(b.x,b.y); wh1[q*2+1]=make_float2(b.z,b.w);
            float4 c=p2[q]; wh2[q*2]=make_float2(c.x,c.y); wh2[q*2+1]=make_float2(c.z,c.w);
        }
    }
    float bcr = bc0 + __ldg(bhh + la);
    float bcz = bc1 + __ldg(bhh + la + 32);
    float bgn = __ldg(bhh + la + 64);

    sm[la] = h;
    if (la < 15) sm[33 + la] = obs_row[la];
    __syncwarp();

    #pragma unroll 1
    for (int t = 0; t < Tq; t++) {
        volatile float* bp = sm + (t & 1) * 48;
        volatile float* bn = sm + ((t + 1) & 1) * 48;
        float xr = bcr, xz = bcz, xn = bc2;
        #pragma unroll
        for (int k = 0; k < KIN; k++) {
            float xk = bp[33 + xoff + k];
            xr = fmaf(xk, wc0[k], xr);
            xz = fmaf(xk, wc1[k], xz);
            xn = fmaf(xk, wc2[k], xn);
        }
        float2 r2a = make_float2(xr, 0.f), r2b = make_float2(0.f, 0.f);
        float2 z2a = make_float2(xz, 0.f), z2b = make_float2(0.f, 0.f);
        float2 n2a = make_float2(bgn, 0.f), n2b = make_float2(0.f, 0.f);
        #pragma unroll
        for (int k = 0; k < 8; k++) {
            float2 hA = make_float2(bp[2*k],      bp[2*k+1]);
            float2 hB = make_float2(bp[16+2*k],   bp[16+2*k+1]);
            r2a = ffma2(hA, wh0[k],   r2a);
            r2b = ffma2(hB, wh0[k+8], r2b);
            z2a = ffma2(hA, wh1[k],   z2a);
            z2b = ffma2(hB, wh1[k+8], z2b);
            n2a = ffma2(hA, wh2[k],   n2a);
            n2b = ffma2(hB, wh2[k+8], n2b);
        }
        if (t + 1 < Tq && la < 15) bn[33 + la] = obs_row[(t + 1) * 15 + la];
        float r = fsig(r2a.x + r2a.y + r2b.x + r2b.y);
        float z = fsig(z2a.x + z2a.y + z2b.x + z2b.y);
        float n = ftanh(fmaf(r, n2a.x + n2a.y + n2b.x + n2b.y, xn));
        h = n + z * (h - n);
        bn[la] = h;
        feat[t * 32 + la] = h;
        __syncwarp();
    }
    *nexth = h;
}

__global__ void __launch_bounds__(128) k_gru(
    const float* __restrict__ obs, const float* __restrict__ rnn,
    const float* __restrict__ eAW, const float* __restrict__ eAb,
    const float* __restrict__ eMW, const float* __restrict__ eMb,
    const float* __restrict__ aWih, const float* __restrict__ aWhh,
    const float* __restrict__ abih, const float* __restrict__ abhh,
    const float* __restrict__ mWih, const float* __restrict__ mWhh,
    const float* __restrict__ mbih, const float* __restrict__ mbhh,
    float* __restrict__ next_h)
{
    __shared__ float sm[4][96];
    int w  = blockIdx.x * 4 + (threadIdx.x >> 5);
    int la = threadIdx.x & 31;
    int wi = threadIdx.x >> 5;
    if (w < Bq) {
        int b = w;
        float h = rnn[b * 96 + la];
        gru_warp<7>(obs + (size_t)b * Tq * 15, 8, eAW, eAb, aWih, abih, aWhh, abhh,
                    h, g_air + (size_t)b * Tq * 32, next_h + b * 96 + la, la, sm[wi]);
    } else {
        int i = w - Bq;
        int b = (i < Bq) ? i : i - Bq;
        int xoff = (i < Bq) ? 0 : 4;
        float h = rnn[(i >> 1) * 96 + 32 + 32 * (i & 1) + la];
        float* feat = (i < Bq) ? (g_m1 + (size_t)i * Tq * 32)
                               : (g_m2 + (size_t)(i - Bq) * Tq * 32);
        gru_warp<4>(obs + (size_t)b * Tq * 15, xoff, eMW, eMb, mWih, mbih, mWhh, mbhh,
                    h, feat, next_h + (i >> 1) * 96 + 32 + 32 * (i & 1) + la, la, sm[wi]);
    }
}

// ================= attention + fusion (R6, unchanged) =================
__global__ void __launch_bounds__(256) k_attn(
    const float* __restrict__ obs,
    const float* __restrict__ Win, const float* __restrict__ bin,
    const float* __restrict__ Wout, const float* __restrict__ bout)
{
    __shared__ float Ws[96 * 32];
    __shared__ float Wo[32 * 32];
    __shared__ float bs[96], bo[32];
    int t = threadIdx.x;
    for (int i = t; i < 96 * 32; i += 256) Ws[i] = Win[i];
    for (int i = t; i < 32 * 32; i += 256) Wo[i] = Wout[i];
    if (t < 96) bs[t] = bin[t];
    if (t < 32) bo[t] = bout[t];
    __syncthreads();

    int warp = blockIdx.x * 8 + (t >> 5);
    int la = t & 31;
    int n = warp * 32 + la;

    float4 A[8], M1[8], M2[8];
    const float4* ap = (const float4*)(g_air + (size_t)n * 32);
    const float4* p1 = (const float4*)(g_m1 + (size_t)n * 32);
    const float4* p2 = (const float4*)(g_m2 + (size_t)n * 32);
    #pragma unroll
    for (int i = 0; i < 8; i++) { A[i] = ap[i]; M1[i] = p1[i]; M2[i] = p2[i]; }

    const float* op = obs + (size_t)n * 15;
    float o0=op[0],o1=op[1],o2=op[2],o3=op[3],o4=op[4],o5=op[5],o6=op[6],o7=op[7];
    const float T1 = 1.001e-5f, T0 = 1e-8f;
    bool mk0 = (fabsf(o0-1.f)<=T1) && (fabsf(o1)<=T0) && (fabsf(o2-1.f)<=T1) && (fabsf(o3)<=T0);
    bool mk1 = (fabsf(o4-1.f)<=T1) && (fabsf(o5)<=T0) && (fabsf(o6-1.f)<=T1) && (fabsf(o7)<=T0);

    float q[32];
    #pragma unroll
    for (int c = 0; c < 32; c++) {
        float2 a = make_float2(bs[c], 0.f);
        const float4* w = (const float4*)(Ws + c * 32);
        #pragma unroll
        for (int k = 0; k < 8; k++) a = dot4_2(A[k], w[k], a);
        q[c] = a.x + a.y;
    }
    float s1[2] = {0.f, 0.f}, s2[2] = {0.f, 0.f};
    #pragma unroll
    for (int c = 0; c < 32; c++) {
        const float4* w = (const float4*)(Ws + (32 + c) * 32);
        float2 k1 = make_float2(bs[32 + c], 0.f), k2 = make_float2(0.f, 0.f);
        #pragma unroll
        for (int k = 0; k < 8; k++) { k1 = dot4_2(M1[k], w[k], k1); k2 = dot4_2(M2[k], w[k], k2); }
        int hh = c >> 4;
        s1[hh] = fmaf(q[c], k1.x + k1.y, s1[hh]);
        s2[hh] = fmaf(q[c], k2.x + k2.y + bs[32 + c], s2[hh]);
    }
    float w1[2], w2[2];
    #pragma unroll
    for (int hh = 0; hh < 2; hh++) {
        float a = s1[hh] * 0.25f + (mk0 ? -1e9f : 0.f);
        float b = s2[hh] * 0.25f + (mk1 ? -1e9f : 0.f);
        float m = fmaxf(a, b);
        float e1 = __expf(a - m), e2 = __expf(b - m);
        float inv = __fdividef(1.0f, e1 + e2);
        w1[hh] = e1 * inv; w2[hh] = e2 * inv;
    }
    float ctx[32];
    #pragma unroll
    for (int c = 0; c < 32; c++) {
        const float4* w = (const float4*)(Ws + (64 + c) * 32);
        float2 v1 = make_float2(bs[64 + c], 0.f), v2 = make_float2(0.f, 0.f);
        #pragma unroll
        for (int k = 0; k < 8; k++) { v1 = dot4_2(M1[k], w[k], v1); v2 = dot4_2(M2[k], w[k], v2); }
        int hh = c >> 4;
        ctx[c] = w1[hh] * (v1.x + v1.y) + w2[hh] * (v2.x + v2.y + bs[64 + c]);
    }
    bool allm = mk0 && mk1;
    float at[32];
    #pragma unroll
    for (int o = 0; o < 32; o++) {
        float2 a = make_float2(bo[o], 0.f);
        const float4* w = (const float4*)(Wo + o * 32);
        #pragma unroll
        for (int c4 = 0; c4 < 8; c4++) {
            float4 cv = make_float4(ctx[4*c4], ctx[4*c4+1], ctx[4*c4+2], ctx[4*c4+3]);
            a = dot4_2(cv, w[c4], a);
        }
        at[o] = allm ? 0.0f : (a.x + a.y);
    }
    float4* fr = (float4*)(g_fusion + (size_t)n * 64);
    #pragma unroll
    for (int i = 0; i < 8; i++) fr[i] = A[i];
    #pragma unroll
    for (int i = 0; i < 8; i++)
        fr[8 + i] = make_float4(at[4*i], at[4*i+1], at[4*i+2], at[4*i+3]);
}

// ======= HMMA MLP: M=64/CTA, 2 CTAs/SM, swizzled L0 tiles, 1-buf W1 =======
// smem map (bytes), total 111616 -> 2 CTAs/SM:
#define SM_B0  0
#define SM_B1  1024
#define SM_OW  2048
#define SM_A1H 3072                    // 64*528 = 33792
#define SM_A1L 36864                   // 33792
#define SM_WB  70656                   // 2 parts x 20480 (pitch 80) = 40960
#define SM_RED 70656                   // aliases WB (used after last chunk)
#define SM_TOT 111616
// L0 aliases (dead after phase B):
#define SM_A0H 3072                    // 64*128 swizzled = 8192
#define SM_A0L 11264
#define SM_W0H 19456                   // 256*128 swizzled = 32768
#define SM_W0L 52224                   // ends 84992
#define PA1 528
#define PW1 80

__global__ void __launch_bounds__(256, 2) k_mlp_h(
    const float* __restrict__ b0, const float* __restrict__ b1,
    const float* __restrict__ oW, const float* __restrict__ ob,
    float* __restrict__ val)
{
    extern __shared__ char smem[];
    uint32_t smb = smem_u32(smem);
    int tid = threadIdx.x, wid = tid >> 5, lane = tid & 31;
    int g = lane >> 2, tq = lane & 3;
    int row0 = blockIdx.x * 64;
    int n0w = wid * 32;

    float* b0s = (float*)(smem + SM_B0);
    float* b1s = (float*)(smem + SM_B1);
    float* ows = (float*)(smem + SM_OW);
    b0s[tid] = b0[tid]; b1s[tid] = b1[tid]; ows[tid] = oW[tid];

    int aro = lane & 15;
    int aco = (lane >> 1) & 8;
    int bro = lane & 7;
    int bco = lane & 8;

    // ---- phase A: cp.async W0 (swizzled), split fusion tile -> A0 ----
    #pragma unroll
    for (int q = 0; q < 16; q++) {
        int id = tid + 256 * q;                  // 0..4095
        int part = id >> 11;                     // 0=h, 1=l
        int u = id & 2047;
        int nn = u >> 3, j = u & 7;
        uint32_t dst = smb + (part ? SM_W0L : SM_W0H) + SWZ((uint32_t)(nn * 128 + j * 16));
        const __nv_bfloat16* src = (part ? g_W0l : g_W0h) + nn * 64 + j * 8;
        cpa16(dst, src);
    }
    CPA_COMMIT();
    {
        const float4* Fg = (const float4*)g_fusion + (size_t)row0 * 16;
        #pragma unroll
        for (int q = 0; q < 4; q++) {
            int id = tid + 256 * q;              // 0..1023 = 64 rows x 16
            int r = id >> 4, c4 = id & 15;
            float4 v = Fg[id];
            __nv_bfloat162 h0 = split_hi(v.x, v.y), l0 = split_lo(v.x, v.y, h0);
            __nv_bfloat162 h1 = split_hi(v.z, v.w), l1 = split_lo(v.z, v.w, h1);
            uint32_t o0 = SWZ((uint32_t)(r * 128 + c4 * 8));
            uint32_t o1 = SWZ((uint32_t)(r * 128 + c4 * 8 + 4));
            *(__nv_bfloat162*)(smem + SM_A0H + o0) = h0;
            *(__nv_bfloat162*)(smem + SM_A0H + o1) = h1;
            *(__nv_bfloat162*)(smem + SM_A0L + o0) = l0;
            *(__nv_bfloat162*)(smem + SM_A0L + o1) = l1;
        }
    }
    asm volatile("cp.async.wait_group 0;" ::: "memory");
    __syncthreads();

    // ---- phase B: layer 0 (k=64) ----
    float acc[4][4][4];
    #pragma unroll
    for (int m = 0; m < 4; m++)
        #pragma unroll
        for (int nt = 0; nt < 4; nt++)
            #pragma unroll
            for (int r = 0; r < 4; r++) acc[m][nt][r] = 0.f;
    #pragma unroll 1
    for (int k16 = 0; k16 < 4; k16++) {
        int kc = k16 * 16;
        uint32_t bh[4][2], bl[4][2];
        #pragma unroll
        for (int nt = 0; nt < 4; nt++) {
            uint32_t ba = SWZ((uint32_t)((n0w + 8 * nt + bro) * 128 + (kc + bco) * 2));
            ldsm2(bh[nt], smb + SM_W0H + ba);
            ldsm2(bl[nt], smb + SM_W0L + ba);
        }
        #pragma unroll
        for (int m = 0; m < 4; m++) {
            uint32_t ah[4], al[4];
            uint32_t aa = SWZ((uint32_t)((m * 16 + aro) * 128 + (kc + aco) * 2));
            ldsm4(ah, smb + SM_A0H + aa);
            ldsm4(al, smb + SM_A0L + aa);
            #pragma unroll
            for (int nt = 0; nt < 4; nt++) {
                mma16816(acc[m][nt], ah, bh[nt]);
                mma16816(acc[m][nt], ah, bl[nt]);
                mma16816(acc[m][nt], al, bh[nt]);
            }
        }
    }
    __syncthreads();   // all L0 reads done before A1/WB overwrite L0 regions

    // prefetch W1 chunk 0 into the single buffer (hidden under phase C)
    #pragma unroll
    for (int q = 0; q < 8; q++) {
        int id = tid + 256 * q;                  // 0..2047
        int part = id >> 10;
        int u = id & 1023;
        int r = u >> 2, j = u & 3;
        const __nv_bfloat16* src = (part ? g_W1l : g_W1h) + r * 256 + j * 8;
        cpa16(smb + SM_WB + part * 20480 + r * PW1 + j * 16, src);
    }
    CPA_COMMIT();

    // ---- phase C: bias+leaky -> split -> A1h/A1l ----
    #pragma unroll
    for (int m = 0; m < 4; m++)
        #pragma unroll
        for (int nt = 0; nt < 4; nt++) {
            int c0 = n0w + 8 * nt + 2 * tq;
            float v0 = acc[m][nt][0] + b0s[c0];
            float v1 = acc[m][nt][1] + b0s[c0 + 1];
            float v2 = acc[m][nt][2] + b0s[c0];
            float v3 = acc[m][nt][3] + b0s[c0 + 1];
            v0 = v0 > 0.f ? v0 : 0.01f * v0;
            v1 = v1 > 0.f ? v1 : 0.01f * v1;
            v2 = v2 > 0.f ? v2 : 0.01f * v2;
            v3 = v3 > 0.f ? v3 : 0.01f * v3;
            int r0 = 16 * m + g, r1 = r0 + 8;
            __nv_bfloat162 h01 = split_hi(v0, v1), l01 = split_lo(v0, v1, h01);
            __nv_bfloat162 h23 = split_hi(v2, v3), l23 = split_lo(v2, v3, h23);
            *(__nv_bfloat162*)(smem + SM_A1H + r0 * PA1 + c0 * 2) = h01;
            *(__nv_bfloat162*)(smem + SM_A1L + r0 * PA1 + c0 * 2) = l01;
            *(__nv_bfloat162*)(smem + SM_A1H + r1 * PA1 + c0 * 2) = h23;
            *(__nv_bfloat162*)(smem + SM_A1L + r1 * PA1 + c0 * 2) = l23;
        }

    // ---- phase D: layer 1, 8 k=32 chunks, single buffer ----
    float a2[4][4][4];
    #pragma unroll
    for (int m = 0; m < 4; m++)
        #pragma unroll
        for (int nt = 0; nt < 4; nt++)
            #pragma unroll
            for (int r = 0; r < 4; r++) a2[m][nt][r] = 0.f;
    #pragma unroll 1
    for (int c = 0; c < 8; c++) {
        asm volatile("cp.async.wait_group 0;" ::: "memory");
        __syncthreads();                         // chunk c data + A1 (c==0) visible
        uint32_t wb = smb + SM_WB;
        // B fragments for both k16 halves of this chunk
        uint32_t bh0[4][2], bl0[4][2], bh1[4][2], bl1[4][2];
        #pragma unroll
        for (int nt = 0; nt < 4; nt++) {
            uint32_t ba0 = (uint32_t)((n0w + 8 * nt + bro) * PW1 + (bco) * 2);
            uint32_t ba1 = ba0 + 32;
            ldsm2(bh0[nt], wb + ba0);
            ldsm2(bl0[nt], wb + 20480 + ba0);
            ldsm2(bh1[nt], wb + ba1);
            ldsm2(bl1[nt], wb + 20480 + ba1);
        }
        __syncthreads();                         // all warps done reading buffer
        if (c + 1 < 8) {
            #pragma unroll
            for (int q = 0; q < 8; q++) {
                int id = tid + 256 * q;
                int part = id >> 10;
                int u = id & 1023;
                int r = u >> 2, j = u & 3;
                const __nv_bfloat16* src = (part ? g_W1l : g_W1h) + r * 256 + (c + 1) * 32 + j * 8;
                cpa16(smb + SM_WB + part * 20480 + r * PW1 + j * 16, src);
            }
            CPA_COMMIT();
        }
        // MMAs for both k16 halves (A from persistent A1 region)
        #pragma unroll
        for (int m = 0; m < 4; m++) {
            uint32_t ah[4], al[4];
            uint32_t aa = (uint32_t)((m * 16 + aro) * PA1 + (c * 32 + aco) * 2);
            ldsm4(ah, smb + SM_A1H + aa);
            ldsm4(al, smb + SM_A1L + aa);
            #pragma unroll
            for (int nt = 0; nt < 4; nt++) {
                mma16816(a2[m][nt], ah, bh0[nt]);
                mma16816(a2[m][nt], ah, bl0[nt]);
                mma16816(a2[m][nt], al, bh0[nt]);
            }
            uint32_t aa1 = aa + 32;
            ldsm4(ah, smb + SM_A1H + aa1);
            ldsm4(al, smb + SM_A1L + aa1);
            #pragma unroll
            for (int nt = 0; nt < 4; nt++) {
                mma16816(a2[m][nt], ah, bh1[nt]);
                mma16816(a2[m][nt], ah, bl1[nt]);
                mma16816(a2[m][nt], al, bh1[nt]);
            }
        }
    }

    // ---- phase E: bias+leaky, dot out_W, reduce ----
    float* red = (float*)(smem + SM_RED);
    float p[4][2];
    #pragma unroll
    for (int m = 0; m < 4; m++) { p[m][0] = 0.f; p[m][1] = 0.f; }
    #pragma unroll
    for (int m = 0; m < 4; m++)
        #pragma unroll
        for (int nt = 0; nt < 4; nt++) {
            int c0 = n0w + 8 * nt + 2 * tq;
            float w0v = ows[c0], w1v = ows[c0 + 1];
            float bb0 = b1s[c0], bb1 = b1s[c0 + 1];
            float v0 = a2[m][nt][0] + bb0;
            float v1 = a2[m][nt][1] + bb1;
            float v2 = a2[m][nt][2] + bb0;
            float v3 = a2[m][nt][3] + bb1;
            v0 = v0 > 0.f ? v0 : 0.01f * v0;
            v1 = v1 > 0.f ? v1 : 0.01f * v1;
            v2 = v2 > 0.f ? v2 : 0.01f * v2;
            v3 = v3 > 0.f ? v3 : 0.01f * v3;
            p[m][0] = fmaf(v0, w0v, p[m][0]);
            p[m][0] = fmaf(v1, w1v, p[m][0]);
            p[m][1] = fmaf(v2, w0v, p[m][1]);
            p[m][1] = fmaf(v3, w1v, p[m][1]);
        }
    #pragma unroll
    for (int off = 1; off <= 2; off <<= 1)
        #pragma unroll
        for (int m = 0; m < 4; m++) {
            p[m][0] += __shfl_xor_sync(0xffffffffu, p[m][0], off);
            p[m][1] += __shfl_xor_sync(0xffffffffu, p[m][1], off);
        }
    if (tq == 0) {
        #pragma unroll
        for (int m = 0; m < 4; m++) {
            red[wid * 64 + 16 * m + g]     = p[m][0];
            red[wid * 64 + 16 * m + g + 8] = p[m][1];
        }
    }
    __syncthreads();
    if (tid < 64) {
        float s = __ldg(ob);
        #pragma unroll
        for (int w8 = 0; w8 < 8; w8++) s += red[w8 * 64 + tid];
        val[row0 + tid] = s;
    }
}

extern "C" void kernel_launch(void* const* d_in, const int* in_sizes, int n_in,
                              void* d_out, int out_size) {
    const float* obs   = (const float*)d_in[0];
    const float* rnn   = (const float*)d_in[1];
    const float* eAW   = (const float*)d_in[2];
    const float* eAb   = (const float*)d_in[3];
    const float* eMW   = (const float*)d_in[4];
    const float* eMb   = (const float*)d_in[5];
    const float* aWih  = (const float*)d_in[6];
    const float* aWhh  = (const float*)d_in[7];
    const float* abih  = (const float*)d_in[8];
    const float* abhh  = (const float*)d_in[9];
    const float* mWih  = (const float*)d_in[10];
    const float* mWhh  = (const float*)d_in[11];
    const float* mbih  = (const float*)d_in[12];
    const float* mbhh  = (const float*)d_in[13];
    const float* Win   = (const float*)d_in[14];
    const float* bin   = (const float*)d_in[15];
    const float* Wout  = (const float*)d_in[16];
    const float* bout  = (const float*)d_in[17];
    const float* W0    = (const float*)d_in[18];
    const float* b0    = (const float*)d_in[19];
    const float* W1    = (const float*)d_in[20];
    const float* b1    = (const float*)d_in[21];
    const float* oW    = (const float*)d_in[22];
    const float* ob    = (const float*)d_in[23];

    float* out_val = (float*)d_out;
    float* out_h   = (float*)d_out + Nq;

    k_pack<<<320, 256>>>(W0, W1);
    k_gru<<<(Bq + 2 * Bq) / 4, 128>>>(obs, rnn, eAW, eAb, eMW, eMb,
                                      aWih, aWhh, abih, abhh,
                                      mWih, mWhh, mbih, mbhh, out_h);
    k_attn<<<Nq / 32 / 8, 256>>>(obs, Win, bin, Wout, bout);
    cudaFuncSetAttribute(k_mlp_h, cudaFuncAttributeMaxDynamicSharedMemorySize, SM_TOT);
    k_mlp_h<<<Nq / 64, 256, SM_TOT>>>(b0, b1, oW, ob, out_val);
}

// round 8
// speedup vs baseline: 2.6904x; 1.0724x over previous
#include <cuda_runtime.h>
#include <cuda_bf16.h>
#include <cstdint>

#define Bq 2048
#define Tq 128
#define Nq (Bq*Tq)

// ---------------- scratch (no allocations allowed) ----------------
__device__ float g_air[(size_t)Nq * 32];
__device__ float g_m1 [(size_t)Nq * 32];
__device__ float g_m2 [(size_t)Nq * 32];
__device__ float g_fusion[(size_t)Nq * 64];
// prepacked bf16 hi/lo weights, plain row-major [n][k]
__device__ __nv_bfloat16 g_W0h[256 * 64];
__device__ __nv_bfloat16 g_W0l[256 * 64];
__device__ __nv_bfloat16 g_W1h[256 * 256];
__device__ __nv_bfloat16 g_W1l[256 * 256];

__device__ __forceinline__ float fsig(float x) {
    return __fdividef(1.0f, 1.0f + __expf(-x));
}
__device__ __forceinline__ float ftanh(float x) {
    x = fminf(fmaxf(x, -12.0f), 12.0f);
    float e = __expf(-2.0f * x);
    return __fdividef(1.0f - e, 1.0f + e);
}

// packed 2xfp32 FMA
union F2U { float2 f; unsigned long long u; };
__device__ __forceinline__ float2 ffma2(float2 a, float2 b, float2 c) {
    F2U A, B, C, D;
    A.f = a; B.f = b; C.f = c;
    asm("fma.rn.f32x2 %0, %1, %2, %3;" : "=l"(D.u) : "l"(A.u), "l"(B.u), "l"(C.u));
    return D.f;
}
__device__ __forceinline__ float2 dot4_2(float4 a, float4 b, float2 acc) {
    acc = ffma2(make_float2(a.x, a.y), make_float2(b.x, b.y), acc);
    acc = ffma2(make_float2(a.z, a.w), make_float2(b.z, b.w), acc);
    return acc;
}

// ---------------- mma.sync / cp.async helpers ----------------
__device__ __forceinline__ uint32_t smem_u32(const void* p) {
    uint32_t a;
    asm("{ .reg .u64 t; cvta.to.shared.u64 t, %1; cvt.u32.u64 %0, t; }" : "=r"(a) : "l"(p));
    return a;
}
__device__ __forceinline__ void ldsm4(uint32_t* a, uint32_t addr) {
    asm volatile("ldmatrix.sync.aligned.m8n8.x4.shared.b16 {%0,%1,%2,%3}, [%4];"
        : "=r"(a[0]), "=r"(a[1]), "=r"(a[2]), "=r"(a[3]) : "r"(addr));
}
__device__ __forceinline__ void ldsm2(uint32_t* b, uint32_t addr) {
    asm volatile("ldmatrix.sync.aligned.m8n8.x2.shared.b16 {%0,%1}, [%2];"
        : "=r"(b[0]), "=r"(b[1]) : "r"(addr));
}
__device__ __forceinline__ void mma16816(float* c, const uint32_t* a, const uint32_t* b) {
    asm volatile("mma.sync.aligned.m16n8k16.row.col.f32.bf16.bf16.f32 "
        "{%0,%1,%2,%3}, {%4,%5,%6,%7}, {%8,%9}, {%0,%1,%2,%3};"
        : "+f"(c[0]), "+f"(c[1]), "+f"(c[2]), "+f"(c[3])
        : "r"(a[0]), "r"(a[1]), "r"(a[2]), "r"(a[3]), "r"(b[0]), "r"(b[1]));
}
__device__ __forceinline__ void cpa16(uint32_t dst, const void* src) {
    asm volatile("cp.async.cg.shared.global [%0], [%1], 16;" :: "r"(dst), "l"(src));
}
#define CPA_COMMIT() asm volatile("cp.async.commit_group;" ::: "memory")
#define SWZ(x) ((x) ^ (((x) >> 3) & 0x70))

__device__ __forceinline__ __nv_bfloat162 split_hi(float a, float b) {
    __nv_bfloat162 h; h.x = __float2bfloat16(a); h.y = __float2bfloat16(b); return h;
}
__device__ __forceinline__ __nv_bfloat162 split_lo(float a, float b, __nv_bfloat162 h) {
    __nv_bfloat162 l;
    l.x = __float2bfloat16(a - __bfloat162float(h.x));
    l.y = __float2bfloat16(b - __bfloat162float(h.y));
    return l;
}

// ================= weight prepack: fp32 -> bf16 hi/lo =================
__global__ void k_pack(const float* __restrict__ W0, const float* __restrict__ W1) {
    int i = blockIdx.x * 256 + threadIdx.x;
    if (i < 16384) {
        float w = W0[i];
        __nv_bfloat16 h = __float2bfloat16(w);
        g_W0h[i] = h;
        g_W0l[i] = __float2bfloat16(w - __bfloat162float(h));
    } else if (i < 16384 + 65536) {
        int j = i - 16384;
        float w = W1[j];
        __nv_bfloat16 h = __float2bfloat16(w);
        g_W1h[j] = h;
        g_W1l[j] = __float2bfloat16(w - __bfloat162float(h));
    }
}

// ================= GRU: one warp per batch lane, shfl-based =================
// h broadcast via shfl (no smem, no syncwarp). obs prefetched 4 steps ahead
// in a rolling register buffer so the LDG never sits on the recurrence chain.
template<int KIN>
__device__ __forceinline__ void gru_warp(
    const float* __restrict__ obs_row, int xoff,
    const float* __restrict__ encW, const float* __restrict__ encB,
    const float* __restrict__ Wih,  const float* __restrict__ bih,
    const float* __restrict__ Whh,  const float* __restrict__ bhh,
    float h, float* __restrict__ feat, float* __restrict__ nexth,
    int la)
{
    const unsigned F = 0xffffffffu;
    float wc0[KIN], wc1[KIN], wc2[KIN];
    float bc0 = 0.f, bc1 = 0.f, bc2 = 0.f;
    #pragma unroll
    for (int g = 0; g < 3; g++) {
        int j = la + 32 * g;
        float wrow[32];
        const float4* wp = (const float4*)(Wih + j * 32);
        #pragma unroll
        for (int q = 0; q < 8; q++) {
            float4 v = wp[q];
            wrow[q*4+0]=v.x; wrow[q*4+1]=v.y; wrow[q*4+2]=v.z; wrow[q*4+3]=v.w;
        }
        #pragma unroll
        for (int k = 0; k < KIN; k++) {
            float s = 0.0f;
            #pragma unroll
            for (int m = 0; m < 32; m++) s = fmaf(wrow[m], __ldg(encW + m * KIN + k), s);
            if (g == 0) wc0[k] = s; else if (g == 1) wc1[k] = s; else wc2[k] = s;
        }
        float sb = __ldg(bih + j);
        #pragma unroll
        for (int m = 0; m < 32; m++) sb = fmaf(wrow[m], __ldg(encB + m), sb);
        if (g == 0) bc0 = sb; else if (g == 1) bc1 = sb; else bc2 = sb;
    }
    float2 wh0[16], wh1[16], wh2[16];
    {
        const float4* p0 = (const float4*)(Whh + (la     ) * 32);
        const float4* p1 = (const float4*)(Whh + (la + 32) * 32);
        const float4* p2 = (const float4*)(Whh + (la + 64) * 32);
        #pragma unroll
        for (int q = 0; q < 8; q++) {
            float4 a=p0[q]; wh0[q*2]=make_float2(a.x,a.y); wh0[q*2+1]=make_float2(a.z,a.w);
            float4 b=p1[q]; wh1[q*2]=make_float2(b.x,b.y); wh1[q*2+1]=make_float2(b.z,b.w);
            float4 c=p2[q]; wh2[q*2]=make_float2(c.x,c.y); wh2[q*2+1]=make_float2(c.z,c.w);
        }
    }
    float bcr = bc0 + __ldg(bhh + la);
    float bcz = bc1 + __ldg(bhh + la + 32);
    float bgn = __ldg(bhh + la + 64);

    // rolling 4-deep obs prefetch: xbuf[u] holds obs[(t+u)*15+la]
    float xbuf[4];
    #pragma unroll
    for (int u = 0; u < 4; u++)
        xbuf[u] = (la < 15) ? obs_row[u * 15 + la] : 0.0f;

    #pragma unroll 1
    for (int t = 0; t < Tq; t += 4) {
        #pragma unroll
        for (int u = 0; u < 4; u++) {
            float xcur = xbuf[u];
            // refill for step t+u+4 (long before its use)
            if (la < 15 && t + u + 4 < Tq) xbuf[u] = obs_row[(t + u + 4) * 15 + la];
            float xr = bcr, xz = bcz, xn = bc2;
            #pragma unroll
            for (int k = 0; k < KIN; k++) {
                float xk = __shfl_sync(F, xcur, xoff + k);
                xr = fmaf(xk, wc0[k], xr);
                xz = fmaf(xk, wc1[k], xz);
                xn = fmaf(xk, wc2[k], xn);
            }
            float2 r2a = make_float2(xr, 0.f), r2b = make_float2(0.f, 0.f);
            float2 z2a = make_float2(xz, 0.f), z2b = make_float2(0.f, 0.f);
            float2 n2a = make_float2(bgn, 0.f), n2b = make_float2(0.f, 0.f);
            #pragma unroll
            for (int k = 0; k < 8; k++) {
                float2 hA = make_float2(__shfl_sync(F, h, 2*k),
                                        __shfl_sync(F, h, 2*k + 1));
                float2 hB = make_float2(__shfl_sync(F, h, 16 + 2*k),
                                        __shfl_sync(F, h, 16 + 2*k + 1));
                r2a = ffma2(hA, wh0[k],   r2a);
                r2b = ffma2(hB, wh0[k+8], r2b);
                z2a = ffma2(hA, wh1[k],   z2a);
                z2b = ffma2(hB, wh1[k+8], z2b);
                n2a = ffma2(hA, wh2[k],   n2a);
                n2b = ffma2(hB, wh2[k+8], n2b);
            }
            float r = fsig(r2a.x + r2a.y + r2b.x + r2b.y);
            float z = fsig(z2a.x + z2a.y + z2b.x + z2b.y);
            float n = ftanh(fmaf(r, n2a.x + n2a.y + n2b.x + n2b.y, xn));
            h = n + z * (h - n);
            feat[(t + u) * 32 + la] = h;
        }
    }
    *nexth = h;
}

__global__ void __launch_bounds__(128) k_gru(
    const float* __restrict__ obs, const float* __restrict__ rnn,
    const float* __restrict__ eAW, const float* __restrict__ eAb,
    const float* __restrict__ eMW, const float* __restrict__ eMb,
    const float* __restrict__ aWih, const float* __restrict__ aWhh,
    const float* __restrict__ abih, const float* __restrict__ abhh,
    const float* __restrict__ mWih, const float* __restrict__ mWhh,
    const float* __restrict__ mbih, const float* __restrict__ mbhh,
    float* __restrict__ next_h)
{
    int w  = blockIdx.x * 4 + (threadIdx.x >> 5);
    int la = threadIdx.x & 31;
    if (w < Bq) {
        int b = w;
        float h = rnn[b * 96 + la];
        gru_warp<7>(obs + (size_t)b * Tq * 15, 8, eAW, eAb, aWih, abih, aWhh, abhh,
                    h, g_air + (size_t)b * Tq * 32, next_h + b * 96 + la, la);
    } else {
        int i = w - Bq;
        int b = (i < Bq) ? i : i - Bq;
        int xoff = (i < Bq) ? 0 : 4;
        float h = rnn[(i >> 1) * 96 + 32 + 32 * (i & 1) + la];
        float* feat = (i < Bq) ? (g_m1 + (size_t)i * Tq * 32)
                               : (g_m2 + (size_t)(i - Bq) * Tq * 32);
        gru_warp<4>(obs + (size_t)b * Tq * 15, xoff, eMW, eMb, mWih, mbih, mWhh, mbhh,
                    h, feat, next_h + (i >> 1) * 96 + 32 + 32 * (i & 1) + la, la);
    }
}

// ================= attention + fusion (R6, unchanged) =================
__global__ void __launch_bounds__(256) k_attn(
    const float* __restrict__ obs,
    const float* __restrict__ Win, const float* __restrict__ bin,
    const float* __restrict__ Wout, const float* __restrict__ bout)
{
    __shared__ float Ws[96 * 32];
    __shared__ float Wo[32 * 32];
    __shared__ float bs[96], bo[32];
    int t = threadIdx.x;
    for (int i = t; i < 96 * 32; i += 256) Ws[i] = Win[i];
    for (int i = t; i < 32 * 32; i += 256) Wo[i] = Wout[i];
    if (t < 96) bs[t] = bin[t];
    if (t < 32) bo[t] = bout[t];
    __syncthreads();

    int warp = blockIdx.x * 8 + (t >> 5);
    int la = t & 31;
    int n = warp * 32 + la;

    float4 A[8], M1[8], M2[8];
    const float4* ap = (const float4*)(g_air + (size_t)n * 32);
    const float4* p1 = (const float4*)(g_m1 + (size_t)n * 32);
    const float4* p2 = (const float4*)(g_m2 + (size_t)n * 32);
    #pragma unroll
    for (int i = 0; i < 8; i++) { A[i] = ap[i]; M1[i] = p1[i]; M2[i] = p2[i]; }

    const float* op = obs + (size_t)n * 15;
    float o0=op[0],o1=op[1],o2=op[2],o3=op[3],o4=op[4],o5=op[5],o6=op[6],o7=op[7];
    const float T1 = 1.001e-5f, T0 = 1e-8f;
    bool mk0 = (fabsf(o0-1.f)<=T1) && (fabsf(o1)<=T0) && (fabsf(o2-1.f)<=T1) && (fabsf(o3)<=T0);
    bool mk1 = (fabsf(o4-1.f)<=T1) && (fabsf(o5)<=T0) && (fabsf(o6-1.f)<=T1) && (fabsf(o7)<=T0);

    float q[32];
    #pragma unroll
    for (int c = 0; c < 32; c++) {
        float2 a = make_float2(bs[c], 0.f);
        const float4* w = (const float4*)(Ws + c * 32);
        #pragma unroll
        for (int k = 0; k < 8; k++) a = dot4_2(A[k], w[k], a);
        q[c] = a.x + a.y;
    }
    float s1[2] = {0.f, 0.f}, s2[2] = {0.f, 0.f};
    #pragma unroll
    for (int c = 0; c < 32; c++) {
        const float4* w = (const float4*)(Ws + (32 + c) * 32);
        float2 k1 = make_float2(bs[32 + c], 0.f), k2 = make_float2(0.f, 0.f);
        #pragma unroll
        for (int k = 0; k < 8; k++) { k1 = dot4_2(M1[k], w[k], k1); k2 = dot4_2(M2[k], w[k], k2); }
        int hh = c >> 4;
        s1[hh] = fmaf(q[c], k1.x + k1.y, s1[hh]);
        s2[hh] = fmaf(q[c], k2.x + k2.y + bs[32 + c], s2[hh]);
    }
    float w1[2], w2[2];
    #pragma unroll
    for (int hh = 0; hh < 2; hh++) {
        float a = s1[hh] * 0.25f + (mk0 ? -1e9f : 0.f);
        float b = s2[hh] * 0.25f + (mk1 ? -1e9f : 0.f);
        float m = fmaxf(a, b);
        float e1 = __expf(a - m), e2 = __expf(b - m);
        float inv = __fdividef(1.0f, e1 + e2);
        w1[hh] = e1 * inv; w2[hh] = e2 * inv;
    }
    float ctx[32];
    #pragma unroll
    for (int c = 0; c < 32; c++) {
        const float4* w = (const float4*)(Ws + (64 + c) * 32);
        float2 v1 = make_float2(bs[64 + c], 0.f), v2 = make_float2(0.f, 0.f);
        #pragma unroll
        for (int k = 0; k < 8; k++) { v1 = dot4_2(M1[k], w[k], v1); v2 = dot4_2(M2[k], w[k], v2); }
        int hh = c >> 4;
        ctx[c] = w1[hh] * (v1.x + v1.y) + w2[hh] * (v2.x + v2.y + bs[64 + c]);
    }
    bool allm = mk0 && mk1;
    float at[32];
    #pragma unroll
    for (int o = 0; o < 32; o++) {
        float2 a = make_float2(bo[o], 0.f);
        const float4* w = (const float4*)(Wo + o * 32);
        #pragma unroll
        for (int c4 = 0; c4 < 8; c4++) {
            float4 cv = make_float4(ctx[4*c4], ctx[4*c4+1], ctx[4*c4+2], ctx[4*c4+3]);
            a = dot4_2(cv, w[c4], a);
        }
        at[o] = allm ? 0.0f : (a.x + a.y);
    }
    float4* fr = (float4*)(g_fusion + (size_t)n * 64);
    #pragma unroll
    for (int i = 0; i < 8; i++) fr[i] = A[i];
    #pragma unroll
    for (int i = 0; i < 8; i++)
        fr[8 + i] = make_float4(at[4*i], at[4*i+1], at[4*i+2], at[4*i+3]);
}

// ======= HMMA MLP: M=64/CTA, 2 CTAs/SM (R7, unchanged) =======
#define SM_B0  0
#define SM_B1  1024
#define SM_OW  2048
#define SM_A1H 3072
#define SM_A1L 36864
#define SM_WB  70656
#define SM_RED 70656
#define SM_TOT 111616
#define SM_A0H 3072
#define SM_A0L 11264
#define SM_W0H 19456
#define SM_W0L 52224
#define PA1 528
#define PW1 80

__global__ void __launch_bounds__(256, 2) k_mlp_h(
    const float* __restrict__ b0, const float* __restrict__ b1,
    const float* __restrict__ oW, const float* __restrict__ ob,
    float* __restrict__ val)
{
    extern __shared__ char smem[];
    uint32_t smb = smem_u32(smem);
    int tid = threadIdx.x, wid = tid >> 5, lane = tid & 31;
    int g = lane >> 2, tq = lane & 3;
    int row0 = blockIdx.x * 64;
    int n0w = wid * 32;

    float* b0s = (float*)(smem + SM_B0);
    float* b1s = (float*)(smem + SM_B1);
    float* ows = (float*)(smem + SM_OW);
    b0s[tid] = b0[tid]; b1s[tid] = b1[tid]; ows[tid] = oW[tid];

    int aro = lane & 15;
    int aco = (lane >> 1) & 8;
    int bro = lane & 7;
    int bco = lane & 8;

    #pragma unroll
    for (int q = 0; q < 16; q++) {
        int id = tid + 256 * q;
        int part = id >> 11;
        int u = id & 2047;
        int nn = u >> 3, j = u & 7;
        uint32_t dst = smb + (part ? SM_W0L : SM_W0H) + SWZ((uint32_t)(nn * 128 + j * 16));
        const __nv_bfloat16* src = (part ? g_W0l : g_W0h) + nn * 64 + j * 8;
        cpa16(dst, src);
    }
    CPA_COMMIT();
    {
        const float4* Fg = (const float4*)g_fusion + (size_t)row0 * 16;
        #pragma unroll
        for (int q = 0; q < 4; q++) {
            int id = tid + 256 * q;
            int r = id >> 4, c4 = id & 15;
            float4 v = Fg[id];
            __nv_bfloat162 h0 = split_hi(v.x, v.y), l0 = split_lo(v.x, v.y, h0);
            __nv_bfloat162 h1 = split_hi(v.z, v.w), l1 = split_lo(v.z, v.w, h1);
            uint32_t o0 = SWZ((uint32_t)(r * 128 + c4 * 8));
            uint32_t o1 = SWZ((uint32_t)(r * 128 + c4 * 8 + 4));
            *(__nv_bfloat162*)(smem + SM_A0H + o0) = h0;
            *(__nv_bfloat162*)(smem + SM_A0H + o1) = h1;
            *(__nv_bfloat162*)(smem + SM_A0L + o0) = l0;
            *(__nv_bfloat162*)(smem + SM_A0L + o1) = l1;
        }
    }
    asm volatile("cp.async.wait_group 0;" ::: "memory");
    __syncthreads();

    float acc[4][4][4];
    #pragma unroll
    for (int m = 0; m < 4; m++)
        #pragma unroll
        for (int nt = 0; nt < 4; nt++)
            #pragma unroll
            for (int r = 0; r < 4; r++) acc[m][nt][r] = 0.f;
    #pragma unroll 1
    for (int k16 = 0; k16 < 4; k16++) {
        int kc = k16 * 16;
        uint32_t bh[4][2], bl[4][2];
        #pragma unroll
        for (int nt = 0; nt < 4; nt++) {
            uint32_t ba = SWZ((uint32_t)((n0w + 8 * nt + bro) * 128 + (kc + bco) * 2));
            ldsm2(bh[nt], smb + SM_W0H + ba);
            ldsm2(bl[nt], smb + SM_W0L + ba);
        }
        #pragma unroll
        for (int m = 0; m < 4; m++) {
            uint32_t ah[4], al[4];
            uint32_t aa = SWZ((uint32_t)((m * 16 + aro) * 128 + (kc + aco) * 2));
            ldsm4(ah, smb + SM_A0H + aa);
            ldsm4(al, smb + SM_A0L + aa);
            #pragma unroll
            for (int nt = 0; nt < 4; nt++) {
                mma16816(acc[m][nt], ah, bh[nt]);
                mma16816(acc[m][nt], ah, bl[nt]);
                mma16816(acc[m][nt], al, bh[nt]);
            }
        }
    }
    __syncthreads();

    #pragma unroll
    for (int q = 0; q < 8; q++) {
        int id = tid + 256 * q;
        int part = id >> 10;
        int u = id & 1023;
        int r = u >> 2, j = u & 3;
        const __nv_bfloat16* src = (part ? g_W1l : g_W1h) + r * 256 + j * 8;
        cpa16(smb + SM_WB + part * 20480 + r * PW1 + j * 16, src);
    }
    CPA_COMMIT();

    #pragma unroll
    for (int m = 0; m < 4; m++)
        #pragma unroll
        for (int nt = 0; nt < 4; nt++) {
            int c0 = n0w + 8 * nt + 2 * tq;
            float v0 = acc[m][nt][0] + b0s[c0];
            float v1 = acc[m][nt][1] + b0s[c0 + 1];
            float v2 = acc[m][nt][2] + b0s[c0];
            float v3 = acc[m][nt][3] + b0s[c0 + 1];
            v0 = v0 > 0.f ? v0 : 0.01f * v0;
            v1 = v1 > 0.f ? v1 : 0.01f * v1;
            v2 = v2 > 0.f ? v2 : 0.01f * v2;
            v3 = v3 > 0.f ? v3 : 0.01f * v3;
            int r0 = 16 * m + g, r1 = r0 + 8;
            __nv_bfloat162 h01 = split_hi(v0, v1), l01 = split_lo(v0, v1, h01);
            __nv_bfloat162 h23 = split_hi(v2, v3), l23 = split_lo(v2, v3, h23);
            *(__nv_bfloat162*)(smem + SM_A1H + r0 * PA1 + c0 * 2) = h01;
            *(__nv_bfloat162*)(smem + SM_A1L + r0 * PA1 + c0 * 2) = l01;
            *(__nv_bfloat162*)(smem + SM_A1H + r1 * PA1 + c0 * 2) = h23;
            *(__nv_bfloat162*)(smem + SM_A1L + r1 * PA1 + c0 * 2) = l23;
        }

    float a2[4][4][4];
    #pragma unroll
    for (int m = 0; m < 4; m++)
        #pragma unroll
        for (int nt = 0; nt < 4; nt++)
            #pragma unroll
            for (int r = 0; r < 4; r++) a2[m][nt][r] = 0.f;
    #pragma unroll 1
    for (int c = 0; c < 8; c++) {
        asm volatile("cp.async.wait_group 0;" ::: "memory");
        __syncthreads();
        uint32_t wb = smb + SM_WB;
        uint32_t bh0[4][2], bl0[4][2], bh1[4][2], bl1[4][2];
        #pragma unroll
        for (int nt = 0; nt < 4; nt++) {
            uint32_t ba0 = (uint32_t)((n0w + 8 * nt + bro) * PW1 + (bco) * 2);
            uint32_t ba1 = ba0 + 32;
            ldsm2(bh0[nt], wb + ba0);
            ldsm2(bl0[nt], wb + 20480 + ba0);
            ldsm2(bh1[nt], wb + ba1);
            ldsm2(bl1[nt], wb + 20480 + ba1);
        }
        __syncthreads();
        if (c + 1 < 8) {
            #pragma unroll
            for (int q = 0; q < 8; q++) {
                int id = tid + 256 * q;
                int part = id >> 10;
                int u = id & 1023;
                int r = u >> 2, j = u & 3;
                const __nv_bfloat16* src = (part ? g_W1l : g_W1h) + r * 256 + (c + 1) * 32 + j * 8;
                cpa16(smb + SM_WB + part * 20480 + r * PW1 + j * 16, src);
            }
            CPA_COMMIT();
        }
        #pragma unroll
        for (int m = 0; m < 4; m++) {
            uint32_t ah[4], al[4];
            uint32_t aa = (uint32_t)((m * 16 + aro) * PA1 + (c * 32 + aco) * 2);
            ldsm4(ah, smb + SM_A1H + aa);
            ldsm4(al, smb + SM_A1L + aa);
            #pragma unroll
            for (int nt = 0; nt < 4; nt++) {
                mma16816(a2[m][nt], ah, bh0[nt]);
                mma16816(a2[m][nt], ah, bl0[nt]);
                mma16816(a2[m][nt], al, bh0[nt]);
            }
            uint32_t aa1 = aa + 32;
            ldsm4(ah, smb + SM_A1H + aa1);
            ldsm4(al, smb + SM_A1L + aa1);
            #pragma unroll
            for (int nt = 0; nt < 4; nt++) {
                mma16816(a2[m][nt], ah, bh1[nt]);
                mma16816(a2[m][nt], ah, bl1[nt]);
                mma16816(a2[m][nt], al, bh1[nt]);
            }
        }
    }

    float* red = (float*)(smem + SM_RED);
    float p[4][2];
    #pragma unroll
    for (int m = 0; m < 4; m++) { p[m][0] = 0.f; p[m][1] = 0.f; }
    #pragma unroll
    for (int m = 0; m < 4; m++)
        #pragma unroll
        for (int nt = 0; nt < 4; nt++) {
            int c0 = n0w + 8 * nt + 2 * tq;
            float w0v = ows[c0], w1v = ows[c0 + 1];
            float bb0 = b1s[c0], bb1 = b1s[c0 + 1];
            float v0 = a2[m][nt][0] + bb0;
            float v1 = a2[m][nt][1] + bb1;
            float v2 = a2[m][nt][2] + bb0;
            float v3 = a2[m][nt][3] + bb1;
            v0 = v0 > 0.f ? v0 : 0.01f * v0;
            v1 = v1 > 0.f ? v1 : 0.01f * v1;
            v2 = v2 > 0.f ? v2 : 0.01f * v2;
            v3 = v3 > 0.f ? v3 : 0.01f * v3;
            p[m][0] = fmaf(v0, w0v, p[m][0]);
            p[m][0] = fmaf(v1, w1v, p[m][0]);
            p[m][1] = fmaf(v2, w0v, p[m][1]);
            p[m][1] = fmaf(v3, w1v, p[m][1]);
        }
    #pragma unroll
    for (int off = 1; off <= 2; off <<= 1)
        #pragma unroll
        for (int m = 0; m < 4; m++) {
            p[m][0] += __shfl_xor_sync(0xffffffffu, p[m][0], off);
            p[m][1] += __shfl_xor_sync(0xffffffffu, p[m][1], off);
        }
    if (tq == 0) {
        #pragma unroll
        for (int m = 0; m < 4; m++) {
            red[wid * 64 + 16 * m + g]     = p[m][0];
            red[wid * 64 + 16 * m + g + 8] = p[m][1];
        }
    }
    __syncthreads();
    if (tid < 64) {
        float s = __ldg(ob);
        #pragma unroll
        for (int w8 = 0; w8 < 8; w8++) s += red[w8 * 64 + tid];
        val[row0 + tid] = s;
    }
}

extern "C" void kernel_launch(void* const* d_in, const int* in_sizes, int n_in,
                              void* d_out, int out_size) {
    const float* obs   = (const float*)d_in[0];
    const float* rnn   = (const float*)d_in[1];
    const float* eAW   = (const float*)d_in[2];
    const float* eAb   = (const float*)d_in[3];
    const float* eMW   = (const float*)d_in[4];
    const float* eMb   = (const float*)d_in[5];
    const float* aWih  = (const float*)d_in[6];
    const float* aWhh  = (const float*)d_in[7];
    const float* abih  = (const float*)d_in[8];
    const float* abhh  = (const float*)d_in[9];
    const float* mWih  = (const float*)d_in[10];
    const float* mWhh  = (const float*)d_in[11];
    const float* mbih  = (const float*)d_in[12];
    const float* mbhh  = (const float*)d_in[13];
    const float* Win   = (const float*)d_in[14];
    const float* bin   = (const float*)d_in[15];
    const float* Wout  = (const float*)d_in[16];
    const float* bout  = (const float*)d_in[17];
    const float* W0    = (const float*)d_in[18];
    const float* b0    = (const float*)d_in[19];
    const float* W1    = (const float*)d_in[20];
    const float* b1    = (const float*)d_in[21];
    const float* oW    = (const float*)d_in[22];
    const float* ob    = (const float*)d_in[23];

    float* out_val = (float*)d_out;
    float* out_h   = (float*)d_out + Nq;

    k_pack<<<320, 256>>>(W0, W1);
    k_gru<<<(Bq + 2 * Bq) / 4, 128>>>(obs, rnn, eAW, eAb, eMW, eMb,
                                      aWih, aWhh, abih, abhh,
                                      mWih, mWhh, mbih, mbhh, out_h);
    k_attn<<<Nq / 32 / 8, 256>>>(obs, Win, bin, Wout, bout);
    cudaFuncSetAttribute(k_mlp_h, cudaFuncAttributeMaxDynamicSharedMemorySize, SM_TOT);
    k_mlp_h<<<Nq / 64, 256, SM_TOT>>>(b0, b1, oW, ob, out_val);
}

// round 9
// speedup vs baseline: 2.7010x; 1.0039x over previous
#include <cuda_runtime.h>
#include <cuda_bf16.h>
#include <cstdint>

#define Bq 2048
#define Tq 128
#define Nq (Bq*Tq)

// ---------------- scratch (no allocations allowed) ----------------
__device__ float g_air[(size_t)Nq * 32];
__device__ float g_m1 [(size_t)Nq * 32];
__device__ float g_m2 [(size_t)Nq * 32];
__device__ float g_fusion[(size_t)Nq * 64];
// prepacked bf16 hi/lo MLP weights, row-major [n][k]
__device__ __nv_bfloat16 g_W0h[256 * 64];
__device__ __nv_bfloat16 g_W0l[256 * 64];
__device__ __nv_bfloat16 g_W1h[256 * 256];
__device__ __nv_bfloat16 g_W1l[256 * 256];
// GRU tensor-core prepack: B-fragments, biases, X A-fragments
__device__ uint2  g_gB[2 * 36 * 2 * 32];            // [ty][pair][part][lane] -> 2 regs
__device__ float  g_gBias[2 * 128];
__device__ uint4  g_gX[(size_t)384 * 128 * 32 * 2]; // [(group*128+t)*32+lane]*2+part

__device__ __forceinline__ float fsig(float x) {
    return __fdividef(1.0f, 1.0f + __expf(-x));
}
__device__ __forceinline__ float ftanh(float x) {
    x = fminf(fmaxf(x, -12.0f), 12.0f);
    float e = __expf(-2.0f * x);
    return __fdividef(1.0f - e, 1.0f + e);
}

// packed 2xfp32 FMA
union F2U { float2 f; unsigned long long u; };
__device__ __forceinline__ float2 ffma2(float2 a, float2 b, float2 c) {
    F2U A, B, C, D;
    A.f = a; B.f = b; C.f = c;
    asm("fma.rn.f32x2 %0, %1, %2, %3;" : "=l"(D.u) : "l"(A.u), "l"(B.u), "l"(C.u));
    return D.f;
}
__device__ __forceinline__ float2 dot4_2(float4 a, float4 b, float2 acc) {
    acc = ffma2(make_float2(a.x, a.y), make_float2(b.x, b.y), acc);
    acc = ffma2(make_float2(a.z, a.w), make_float2(b.z, b.w), acc);
    return acc;
}

// ---------------- mma.sync / cp.async helpers ----------------
__device__ __forceinline__ uint32_t smem_u32(const void* p) {
    uint32_t a;
    asm("{ .reg .u64 t; cvta.to.shared.u64 t, %1; cvt.u32.u64 %0, t; }" : "=r"(a) : "l"(p));
    return a;
}
__device__ __forceinline__ void ldsm4(uint32_t* a, uint32_t addr) {
    asm volatile("ldmatrix.sync.aligned.m8n8.x4.shared.b16 {%0,%1,%2,%3}, [%4];"
        : "=r"(a[0]), "=r"(a[1]), "=r"(a[2]), "=r"(a[3]) : "r"(addr));
}
__device__ __forceinline__ void ldsm2(uint32_t* b, uint32_t addr) {
    asm volatile("ldmatrix.sync.aligned.m8n8.x2.shared.b16 {%0,%1}, [%2];"
        : "=r"(b[0]), "=r"(b[1]) : "r"(addr));
}
__device__ __forceinline__ void mma16816(float* c, const uint32_t* a, const uint32_t* b) {
    asm volatile("mma.sync.aligned.m16n8k16.row.col.f32.bf16.bf16.f32 "
        "{%0,%1,%2,%3}, {%4,%5,%6,%7}, {%8,%9}, {%0,%1,%2,%3};"
        : "+f"(c[0]), "+f"(c[1]), "+f"(c[2]), "+f"(c[3])
        : "r"(a[0]), "r"(a[1]), "r"(a[2]), "r"(a[3]), "r"(b[0]), "r"(b[1]));
}
__device__ __forceinline__ void cpa16(uint32_t dst, const void* src) {
    asm volatile("cp.async.cg.shared.global [%0], [%1], 16;" :: "r"(dst), "l"(src));
}
#define CPA_COMMIT() asm volatile("cp.async.commit_group;" ::: "memory")
#define SWZ(x) ((x) ^ (((x) >> 3) & 0x70))

__device__ __forceinline__ __nv_bfloat162 split_hi(float a, float b) {
    __nv_bfloat162 h; h.x = __float2bfloat16(a); h.y = __float2bfloat16(b); return h;
}
__device__ __forceinline__ __nv_bfloat162 split_lo(float a, float b, __nv_bfloat162 h) {
    __nv_bfloat162 l;
    l.x = __float2bfloat16(a - __bfloat162float(h.x));
    l.y = __float2bfloat16(b - __bfloat162float(h.y));
    return l;
}
__device__ __forceinline__ uint32_t bf2u(__nv_bfloat162 v) {
    return *reinterpret_cast<uint32_t*>(&v);
}

// GRU tile-pair tables: (nt, kt). nt 0-7: r,z (all 3 kt); 8-11: hn (kt 0,1); 12-15: xn (kt 2)
#define GRU_PNT {0,0,0,1,1,1,2,2,2,3,3,3,4,4,4,5,5,5,6,6,6,7,7,7, 8,8,9,9,10,10,11,11, 12,13,14,15}
#define GRU_PKT {0,1,2,0,1,2,0,1,2,0,1,2,0,1,2,0,1,2,0,1,2,0,1,2, 0,1,0,1,0,1,0,1, 2,2,2,2}

// ================= MLP weight prepack =================
__global__ void k_pack(const float* __restrict__ W0, const float* __restrict__ W1) {
    int i = blockIdx.x * 256 + threadIdx.x;
    if (i < 16384) {
        float w = W0[i];
        __nv_bfloat16 h = __float2bfloat16(w);
        g_W0h[i] = h;
        g_W0l[i] = __float2bfloat16(w - __bfloat162float(h));
    } else if (i < 16384 + 65536) {
        int j = i - 16384;
        float w = W1[j];
        __nv_bfloat16 h = __float2bfloat16(w);
        g_W1h[j] = h;
        g_W1l[j] = __float2bfloat16(w - __bfloat162float(h));
    }
}

// ================= GRU weight/bias prepack =================
// B matrix [k=48][n=128]: cols 0-31 r, 32-63 z, 64-95 hn, 96-127 xn.
// rows 0-31 = h (Whh), rows 32-47 = x features (Wc = Wih@encW), zeros elsewhere.
__device__ __forceinline__ float gru_bval(
    int k, int n, const float* Whh, const float* Wih, const float* encW, int KIN)
{
    int blk = n >> 5, j = n & 31;
    if (k < 32) {
        if (blk == 3) return 0.f;
        return Whh[(blk * 32 + j) * 32 + k];
    }
    int f = k - 32;
    if (f >= KIN || blk == 2) return 0.f;
    int row = (blk == 3) ? 64 + j : blk * 32 + j;
    float s = 0.f;
    #pragma unroll
    for (int m = 0; m < 32; m++) s = fmaf(Wih[row * 32 + m], encW[m * KIN + f], s);
    return s;
}

__global__ void k_packg_w(
    const float* __restrict__ aWih, const float* __restrict__ aWhh,
    const float* __restrict__ abih, const float* __restrict__ abhh,
    const float* __restrict__ eAW,  const float* __restrict__ eAb,
    const float* __restrict__ mWih, const float* __restrict__ mWhh,
    const float* __restrict__ mbih, const float* __restrict__ mbhh,
    const float* __restrict__ eMW,  const float* __restrict__ eMb)
{
    const int PNT[36] = GRU_PNT;
    const int PKT[36] = GRU_PKT;
    int tid = blockIdx.x * 256 + threadIdx.x;
    if (tid < 2304) {   // B fragments: 2 types x 36 pairs x 32 lanes
        int lane = tid & 31;
        int p = (tid >> 5) % 36;
        int ty = tid / (36 * 32);
        const float* Whh = ty ? mWhh : aWhh;
        const float* Wih = ty ? mWih : aWih;
        const float* eW  = ty ? eMW  : eAW;
        int KIN = ty ? 4 : 7;
        int g = lane >> 2, tq = lane & 3;
        int n = PNT[p] * 8 + g;
        uint32_t rh[2], rl[2];
        #pragma unroll
        for (int r = 0; r < 2; r++) {
            int k0 = PKT[p] * 16 + tq * 2 + r * 8;
            float v0 = gru_bval(k0,     n, Whh, Wih, eW, KIN);
            float v1 = gru_bval(k0 + 1, n, Whh, Wih, eW, KIN);
            __nv_bfloat162 hh = split_hi(v0, v1);
            __nv_bfloat162 ll = split_lo(v0, v1, hh);
            rh[r] = bf2u(hh); rl[r] = bf2u(ll);
        }
        int base = (ty * 72 + p * 2) * 32 + lane;
        g_gB[base]      = make_uint2(rh[0], rh[1]);
        g_gB[base + 32] = make_uint2(rl[0], rl[1]);
    } else if (tid < 2304 + 256) {   // biases
        int u = tid - 2304;
        int ty = u >> 7, n = u & 127;
        const float* Wih = ty ? mWih : aWih;
        const float* bih = ty ? mbih : abih;
        const float* bhh = ty ? mbhh : abhh;
        const float* eB  = ty ? eMb  : eAb;
        int blk = n >> 5, j = n & 31;
        float b;
        if (blk == 2) {
            b = bhh[64 + j];
        } else {
            int row = (blk == 3) ? 64 + j : blk * 32 + j;
            float bc = bih[row];
            #pragma unroll
            for (int m = 0; m < 32; m++) bc = fmaf(Wih[row * 32 + m], eB[m], bc);
            b = (blk < 2) ? bc + bhh[row] : bc;
        }
        g_gBias[ty * 128 + n] = b;
    }
}

// X A-fragment prepack: per (group, t, lane) 4 hi + 4 lo regs.
__global__ void k_packg_x(const float* __restrict__ obs) {
    int tid = blockIdx.x * 256 + threadIdx.x;   // 0 .. 1572863
    int lane = tid & 31;
    int s = tid >> 5;
    int t = s & 127;
    int gr = s >> 7;                            // 0..383
    int g = lane >> 2, tq = lane & 3;

    int KIN, xoff; const float* base;
    int b0;
    if (gr < 128) { KIN = 7; xoff = 8; b0 = gr * 16; }
    else {
        int gi = gr - 128;
        KIN = 4;
        xoff = (gi < 128) ? 0 : 4;
        b0 = (gi < 128) ? gi * 16 : (gi - 128) * 16;
    }
    base = obs;
    // regs: r0=(g, 2tq..), r1=(g+8, 2tq..), r2=(g, 2tq+8..), r3=(g+8, 2tq+8..)
    uint32_t hr[4], lr[4];
    #pragma unroll
    for (int r = 0; r < 4; r++) {
        int row = g + 8 * (r & 1);
        int k0 = tq * 2 + (r >> 1) * 8;
        float v0 = 0.f, v1 = 0.f;
        if (k0 < KIN)
            v0 = base[(size_t)(b0 + row) * Tq * 15 + t * 15 + xoff + k0];
        if (k0 + 1 < KIN)
            v1 = base[(size_t)(b0 + row) * Tq * 15 + t * 15 + xoff + k0 + 1];
        __nv_bfloat162 hh = split_hi(v0, v1);
        __nv_bfloat162 ll = split_lo(v0, v1, hh);
        hr[r] = bf2u(hh); lr[r] = bf2u(ll);
    }
    size_t idx = ((size_t)(gr * 128 + t) * 32 + lane) * 2;
    g_gX[idx]     = make_uint4(hr[0], hr[1], hr[2], hr[3]);
    g_gX[idx + 1] = make_uint4(lr[0], lr[1], lr[2], lr[3]);
}

// ================= GRU: tensor-core recurrence, warp = 16 batch lanes ======
__global__ void __launch_bounds__(128) k_gru_tc(
    const float* __restrict__ rnn, float* __restrict__ next_h)
{
    const int PNT[36] = GRU_PNT;
    const int PKT[36] = GRU_PKT;
    int wid = threadIdx.x >> 5, lane = threadIdx.x & 31;
    int w = blockIdx.x * 4 + wid;               // 0..383
    int g = lane >> 2, tq = lane & 3;

    int ty; float* featb; int ib; bool is_air = (w < 128);
    if (is_air) { ty = 0; featb = g_air; ib = w * 16; }
    else {
        ty = 1;
        int gi = w - 128;
        if (gi < 128) { featb = g_m1; ib = gi * 16; }
        else          { featb = g_m2; ib = (gi - 128) * 16; }
    }
    int gi = w - 128;                            // valid for m only

    // h0 fp32: hv[nt][j]; col = nt*8+2tq+(j&1), row = g+8*(j>>1)
    float hv[4][4];
    #pragma unroll
    for (int nt = 0; nt < 4; nt++) {
        int col = nt * 8 + 2 * tq;
        #pragma unroll
        for (int rh = 0; rh < 2; rh++) {
            int row = g + 8 * rh;
            const float* src;
            if (is_air) src = rnn + (size_t)(w * 16 + row) * 96 + col;
            else {
                int i = gi * 16 + row;
                src = rnn + (size_t)(i >> 1) * 96 + 32 + 32 * (i & 1) + col;
            }
            float2 v = *(const float2*)src;
            hv[nt][rh * 2]     = v.x;
            hv[nt][rh * 2 + 1] = v.y;
        }
    }
    // biases (per lane's columns)
    float bias[16][2];
    #pragma unroll
    for (int nt = 0; nt < 16; nt++) {
        float2 v = *(const float2*)(g_gBias + ty * 128 + nt * 8 + 2 * tq);
        bias[nt][0] = v.x; bias[nt][1] = v.y;
    }
    // initial H A-frags
    uint32_t Ah[2][4], Al[2][4];
    #pragma unroll
    for (int nt = 0; nt < 4; nt++) {
        int kt = nt >> 1;
        __nv_bfloat162 h01 = split_hi(hv[nt][0], hv[nt][1]);
        __nv_bfloat162 l01 = split_lo(hv[nt][0], hv[nt][1], h01);
        __nv_bfloat162 h23 = split_hi(hv[nt][2], hv[nt][3]);
        __nv_bfloat162 l23 = split_lo(hv[nt][2], hv[nt][3], h23);
        int o = (nt & 1) ? 2 : 0;
        Ah[kt][o] = bf2u(h01); Ah[kt][o + 1] = bf2u(h23);
        Al[kt][o] = bf2u(l01); Al[kt][o + 1] = bf2u(l23);
    }

    const uint2* gBb = g_gB + ty * 72 * 32 + lane;
    const uint4* gXb = g_gX + ((size_t)w * 128) * 32 * 2 + lane * 2;
    // per-row feat base offsets
    float* fr0 = featb + (size_t)(ib + g)     * Tq * 32 + 2 * tq;
    float* fr1 = featb + (size_t)(ib + g + 8) * Tq * 32 + 2 * tq;

    #pragma unroll 1
    for (int t = 0; t < Tq; t++) {
        uint4 xh4 = gXb[(size_t)t * 64];
        uint4 xl4 = gXb[(size_t)t * 64 + 1];
        uint32_t Xh[4] = {xh4.x, xh4.y, xh4.z, xh4.w};
        uint32_t Xl[4] = {xl4.x, xl4.y, xl4.z, xl4.w};
        float C[16][4];
        #pragma unroll
        for (int nt = 0; nt < 16; nt++) {
            C[nt][0] = bias[nt][0]; C[nt][1] = bias[nt][1];
            C[nt][2] = bias[nt][0]; C[nt][3] = bias[nt][1];
        }
        #pragma unroll
        for (int p = 0; p < 36; p++) {
            int nt = PNT[p], kt = PKT[p];
            uint2 bh = gBb[(p * 2) * 32];
            uint2 bl = gBb[(p * 2 + 1) * 32];
            const uint32_t* ah = (kt == 2) ? Xh : Ah[kt];
            const uint32_t* al = (kt == 2) ? Xl : Al[kt];
            mma16816(C[nt], ah, (const uint32_t*)&bh);
            mma16816(C[nt], ah, (const uint32_t*)&bl);
            mma16816(C[nt], al, (const uint32_t*)&bh);
        }
        // epilogue: activations + h update
        #pragma unroll
        for (int nt = 0; nt < 4; nt++) {
            #pragma unroll
            for (int j = 0; j < 4; j++) {
                float r = fsig(C[nt][j]);
                float z = fsig(C[nt + 4][j]);
                float n = ftanh(fmaf(r, C[nt + 8][j], C[nt + 12][j]));
                hv[nt][j] = n + z * (hv[nt][j] - n);
            }
            // store feat
            *(float2*)(fr0 + (size_t)t * 32 + nt * 8) = make_float2(hv[nt][0], hv[nt][1]);
            *(float2*)(fr1 + (size_t)t * 32 + nt * 8) = make_float2(hv[nt][2], hv[nt][3]);
            // rebuild H A-frags
            int kt = nt >> 1;
            __nv_bfloat162 h01 = split_hi(hv[nt][0], hv[nt][1]);
            __nv_bfloat162 l01 = split_lo(hv[nt][0], hv[nt][1], h01);
            __nv_bfloat162 h23 = split_hi(hv[nt][2], hv[nt][3]);
            __nv_bfloat162 l23 = split_lo(hv[nt][2], hv[nt][3], h23);
            int o = (nt & 1) ? 2 : 0;
            Ah[kt][o] = bf2u(h01); Ah[kt][o + 1] = bf2u(h23);
            Al[kt][o] = bf2u(l01); Al[kt][o + 1] = bf2u(l23);
        }
    }
    // store next_h
    #pragma unroll
    for (int nt = 0; nt < 4; nt++) {
        int col = nt * 8 + 2 * tq;
        #pragma unroll
        for (int rh = 0; rh < 2; rh++) {
            int row = g + 8 * rh;
            float2 v = make_float2(hv[nt][rh * 2], hv[nt][rh * 2 + 1]);
            float* dst;
            if (is_air) dst = next_h + (size_t)(w * 16 + row) * 96 + col;
            else {
                int i = gi * 16 + row;
                dst = next_h + (size_t)(i >> 1) * 96 + 32 + 32 * (i & 1) + col;
            }
            *(float2*)dst = v;
        }
    }
}

// ================= attention + fusion (unchanged) =================
__global__ void __launch_bounds__(256) k_attn(
    const float* __restrict__ obs,
    const float* __restrict__ Win, const float* __restrict__ bin,
    const float* __restrict__ Wout, const float* __restrict__ bout)
{
    __shared__ float Ws[96 * 32];
    __shared__ float Wo[32 * 32];
    __shared__ float bs[96], bo[32];
    int t = threadIdx.x;
    for (int i = t; i < 96 * 32; i += 256) Ws[i] = Win[i];
    for (int i = t; i < 32 * 32; i += 256) Wo[i] = Wout[i];
    if (t < 96) bs[t] = bin[t];
    if (t < 32) bo[t] = bout[t];
    __syncthreads();

    int warp = blockIdx.x * 8 + (t >> 5);
    int la = t & 31;
    int n = warp * 32 + la;

    float4 A[8], M1[8], M2[8];
    const float4* ap = (const float4*)(g_air + (size_t)n * 32);
    const float4* p1 = (const float4*)(g_m1 + (size_t)n * 32);
    const float4* p2 = (const float4*)(g_m2 + (size_t)n * 32);
    #pragma unroll
    for (int i = 0; i < 8; i++) { A[i] = ap[i]; M1[i] = p1[i]; M2[i] = p2[i]; }

    const float* op = obs + (size_t)n * 15;
    float o0=op[0],o1=op[1],o2=op[2],o3=op[3],o4=op[4],o5=op[5],o6=op[6],o7=op[7];
    const float T1 = 1.001e-5f, T0 = 1e-8f;
    bool mk0 = (fabsf(o0-1.f)<=T1) && (fabsf(o1)<=T0) && (fabsf(o2-1.f)<=T1) && (fabsf(o3)<=T0);
    bool mk1 = (fabsf(o4-1.f)<=T1) && (fabsf(o5)<=T0) && (fabsf(o6-1.f)<=T1) && (fabsf(o7)<=T0);

    float q[32];
    #pragma unroll
    for (int c = 0; c < 32; c++) {
        float2 a = make_float2(bs[c], 0.f);
        const float4* w = (const float4*)(Ws + c * 32);
        #pragma unroll
        for (int k = 0; k < 8; k++) a = dot4_2(A[k], w[k], a);
        q[c] = a.x + a.y;
    }
    float s1[2] = {0.f, 0.f}, s2[2] = {0.f, 0.f};
    #pragma unroll
    for (int c = 0; c < 32; c++) {
        const float4* w = (const float4*)(Ws + (32 + c) * 32);
        float2 k1 = make_float2(bs[32 + c], 0.f), k2 = make_float2(0.f, 0.f);
        #pragma unroll
        for (int k = 0; k < 8; k++) { k1 = dot4_2(M1[k], w[k], k1); k2 = dot4_2(M2[k], w[k], k2); }
        int hh = c >> 4;
        s1[hh] = fmaf(q[c], k1.x + k1.y, s1[hh]);
        s2[hh] = fmaf(q[c], k2.x + k2.y + bs[32 + c], s2[hh]);
    }
    float w1[2], w2[2];
    #pragma unroll
    for (int hh = 0; hh < 2; hh++) {
        float a = s1[hh] * 0.25f + (mk0 ? -1e9f : 0.f);
        float b = s2[hh] * 0.25f + (mk1 ? -1e9f : 0.f);
        float m = fmaxf(a, b);
        float e1 = __expf(a - m), e2 = __expf(b - m);
        float inv = __fdividef(1.0f, e1 + e2);
        w1[hh] = e1 * inv; w2[hh] = e2 * inv;
    }
    float ctx[32];
    #pragma unroll
    for (int c = 0; c < 32; c++) {
        const float4* w = (const float4*)(Ws + (64 + c) * 32);
        float2 v1 = make_float2(bs[64 + c], 0.f), v2 = make_float2(0.f, 0.f);
        #pragma unroll
        for (int k = 0; k < 8; k++) { v1 = dot4_2(M1[k], w[k], v1); v2 = dot4_2(M2[k], w[k], v2); }
        int hh = c >> 4;
        ctx[c] = w1[hh] * (v1.x + v1.y) + w2[hh] * (v2.x + v2.y + bs[64 + c]);
    }
    bool allm = mk0 && mk1;
    float at[32];
    #pragma unroll
    for (int o = 0; o < 32; o++) {
        float2 a = make_float2(bo[o], 0.f);
        const float4* w = (const float4*)(Wo + o * 32);
        #pragma unroll
        for (int c4 = 0; c4 < 8; c4++) {
            float4 cv = make_float4(ctx[4*c4], ctx[4*c4+1], ctx[4*c4+2], ctx[4*c4+3]);
            a = dot4_2(cv, w[c4], a);
        }
        at[o] = allm ? 0.0f : (a.x + a.y);
    }
    float4* fr = (float4*)(g_fusion + (size_t)n * 64);
    #pragma unroll
    for (int i = 0; i < 8; i++) fr[i] = A[i];
    #pragma unroll
    for (int i = 0; i < 8; i++)
        fr[8 + i] = make_float4(at[4*i], at[4*i+1], at[4*i+2], at[4*i+3]);
}

// ======= HMMA MLP: M=64/CTA, 2 CTAs/SM (unchanged) =======
#define SM_B0  0
#define SM_B1  1024
#define SM_OW  2048
#define SM_A1H 3072
#define SM_A1L 36864
#define SM_WB  70656
#define SM_RED 70656
#define SM_TOT 111616
#define SM_A0H 3072
#define SM_A0L 11264
#define SM_W0H 19456
#define SM_W0L 52224
#define PA1 528
#define PW1 80

__global__ void __launch_bounds__(256, 2) k_mlp_h(
    const float* __restrict__ b0, const float* __restrict__ b1,
    const float* __restrict__ oW, const float* __restrict__ ob,
    float* __restrict__ val)
{
    extern __shared__ char smem[];
    uint32_t smb = smem_u32(smem);
    int tid = threadIdx.x, wid = tid >> 5, lane = tid & 31;
    int g = lane >> 2, tq = lane & 3;
    int row0 = blockIdx.x * 64;
    int n0w = wid * 32;

    float* b0s = (float*)(smem + SM_B0);
    float* b1s = (float*)(smem + SM_B1);
    float* ows = (float*)(smem + SM_OW);
    b0s[tid] = b0[tid]; b1s[tid] = b1[tid]; ows[tid] = oW[tid];

    int aro = lane & 15;
    int aco = (lane >> 1) & 8;
    int bro = lane & 7;
    int bco = lane & 8;

    #pragma unroll
    for (int q = 0; q < 16; q++) {
        int id = tid + 256 * q;
        int part = id >> 11;
        int u = id & 2047;
        int nn = u >> 3, j = u & 7;
        uint32_t dst = smb + (part ? SM_W0L : SM_W0H) + SWZ((uint32_t)(nn * 128 + j * 16));
        const __nv_bfloat16* src = (part ? g_W0l : g_W0h) + nn * 64 + j * 8;
        cpa16(dst, src);
    }
    CPA_COMMIT();
    {
        const float4* Fg = (const float4*)g_fusion + (size_t)row0 * 16;
        #pragma unroll
        for (int q = 0; q < 4; q++) {
            int id = tid + 256 * q;
            int r = id >> 4, c4 = id & 15;
            float4 v = Fg[id];
            __nv_bfloat162 h0 = split_hi(v.x, v.y), l0 = split_lo(v.x, v.y, h0);
            __nv_bfloat162 h1 = split_hi(v.z, v.w), l1 = split_lo(v.z, v.w, h1);
            uint32_t o0 = SWZ((uint32_t)(r * 128 + c4 * 8));
            uint32_t o1 = SWZ((uint32_t)(r * 128 + c4 * 8 + 4));
            *(__nv_bfloat162*)(smem + SM_A0H + o0) = h0;
            *(__nv_bfloat162*)(smem + SM_A0H + o1) = h1;
            *(__nv_bfloat162*)(smem + SM_A0L + o0) = l0;
            *(__nv_bfloat162*)(smem + SM_A0L + o1) = l1;
        }
    }
    asm volatile("cp.async.wait_group 0;" ::: "memory");
    __syncthreads();

    float acc[4][4][4];
    #pragma unroll
    for (int m = 0; m < 4; m++)
        #pragma unroll
        for (int nt = 0; nt < 4; nt++)
            #pragma unroll
            for (int r = 0; r < 4; r++) acc[m][nt][r] = 0.f;
    #pragma unroll 1
    for (int k16 = 0; k16 < 4; k16++) {
        int kc = k16 * 16;
        uint32_t bh[4][2], bl[4][2];
        #pragma unroll
        for (int nt = 0; nt < 4; nt++) {
            uint32_t ba = SWZ((uint32_t)((n0w + 8 * nt + bro) * 128 + (kc + bco) * 2));
            ldsm2(bh[nt], smb + SM_W0H + ba);
            ldsm2(bl[nt], smb + SM_W0L + ba);
        }
        #pragma unroll
        for (int m = 0; m < 4; m++) {
            uint32_t ah[4], al[4];
            uint32_t aa = SWZ((uint32_t)((m * 16 + aro) * 128 + (kc + aco) * 2));
            ldsm4(ah, smb + SM_A0H + aa);
            ldsm4(al, smb + SM_A0L + aa);
            #pragma unroll
            for (int nt = 0; nt < 4; nt++) {
                mma16816(acc[m][nt], ah, bh[nt]);
                mma16816(acc[m][nt], ah, bl[nt]);
                mma16816(acc[m][nt], al, bh[nt]);
            }
        }
    }
    __syncthreads();

    #pragma unroll
    for (int q = 0; q < 8; q++) {
        int id = tid + 256 * q;
        int part = id >> 10;
        int u = id & 1023;
        int r = u >> 2, j = u & 3;
        const __nv_bfloat16* src = (part ? g_W1l : g_W1h) + r * 256 + j * 8;
        cpa16(smb + SM_WB + part * 20480 + r * PW1 + j * 16, src);
    }
    CPA_COMMIT();

    #pragma unroll
    for (int m = 0; m < 4; m++)
        #pragma unroll
        for (int nt = 0; nt < 4; nt++) {
            int c0 = n0w + 8 * nt + 2 * tq;
            float v0 = acc[m][nt][0] + b0s[c0];
            float v1 = acc[m][nt][1] + b0s[c0 + 1];
            float v2 = acc[m][nt][2] + b0s[c0];
            float v3 = acc[m][nt][3] + b0s[c0 + 1];
            v0 = v0 > 0.f ? v0 : 0.01f * v0;
            v1 = v1 > 0.f ? v1 : 0.01f * v1;
            v2 = v2 > 0.f ? v2 : 0.01f * v2;
            v3 = v3 > 0.f ? v3 : 0.01f * v3;
            int r0 = 16 * m + g, r1 = r0 + 8;
            __nv_bfloat162 h01 = split_hi(v0, v1), l01 = split_lo(v0, v1, h01);
            __nv_bfloat162 h23 = split_hi(v2, v3), l23 = split_lo(v2, v3, h23);
            *(__nv_bfloat162*)(smem + SM_A1H + r0 * PA1 + c0 * 2) = h01;
            *(__nv_bfloat162*)(smem + SM_A1L + r0 * PA1 + c0 * 2) = l01;
            *(__nv_bfloat162*)(smem + SM_A1H + r1 * PA1 + c0 * 2) = h23;
            *(__nv_bfloat162*)(smem + SM_A1L + r1 * PA1 + c0 * 2) = l23;
        }

    float a2[4][4][4];
    #pragma unroll
    for (int m = 0; m < 4; m++)
        #pragma unroll
        for (int nt = 0; nt < 4; nt++)
            #pragma unroll
            for (int r = 0; r < 4; r++) a2[m][nt][r] = 0.f;
    #pragma unroll 1
    for (int c = 0; c < 8; c++) {
        asm volatile("cp.async.wait_group 0;" ::: "memory");
        __syncthreads();
        uint32_t wb = smb + SM_WB;
        uint32_t bh0[4][2], bl0[4][2], bh1[4][2], bl1[4][2];
        #pragma unroll
        for (int nt = 0; nt < 4; nt++) {
            uint32_t ba0 = (uint32_t)((n0w + 8 * nt + bro) * PW1 + (bco) * 2);
            uint32_t ba1 = ba0 + 32;
            ldsm2(bh0[nt], wb + ba0);
            ldsm2(bl0[nt], wb + 20480 + ba0);
            ldsm2(bh1[nt], wb + ba1);
            ldsm2(bl1[nt], wb + 20480 + ba1);
        }
        __syncthreads();
        if (c + 1 < 8) {
            #pragma unroll
            for (int q = 0; q < 8; q++) {
                int id = tid + 256 * q;
                int part = id >> 10;
                int u = id & 1023;
                int r = u >> 2, j = u & 3;
                const __nv_bfloat16* src = (part ? g_W1l : g_W1h) + r * 256 + (c + 1) * 32 + j * 8;
                cpa16(smb + SM_WB + part * 20480 + r * PW1 + j * 16, src);
            }
            CPA_COMMIT();
        }
        #pragma unroll
        for (int m = 0; m < 4; m++) {
            uint32_t ah[4], al[4];
            uint32_t aa = (uint32_t)((m * 16 + aro) * PA1 + (c * 32 + aco) * 2);
            ldsm4(ah, smb + SM_A1H + aa);
            ldsm4(al, smb + SM_A1L + aa);
            #pragma unroll
            for (int nt = 0; nt < 4; nt++) {
                mma16816(a2[m][nt], ah, bh0[nt]);
                mma16816(a2[m][nt], ah, bl0[nt]);
                mma16816(a2[m][nt], al, bh0[nt]);
            }
            uint32_t aa1 = aa + 32;
            ldsm4(ah, smb + SM_A1H + aa1);
            ldsm4(al, smb + SM_A1L + aa1);
            #pragma unroll
            for (int nt = 0; nt < 4; nt++) {
                mma16816(a2[m][nt], ah, bh1[nt]);
                mma16816(a2[m][nt], ah, bl1[nt]);
                mma16816(a2[m][nt], al, bh1[nt]);
            }
        }
    }

    float* red = (float*)(smem + SM_RED);
    float p[4][2];
    #pragma unroll
    for (int m = 0; m < 4; m++) { p[m][0] = 0.f; p[m][1] = 0.f; }
    #pragma unroll
    for (int m = 0; m < 4; m++)
        #pragma unroll
        for (int nt = 0; nt < 4; nt++) {
            int c0 = n0w + 8 * nt + 2 * tq;
            float w0v = ows[c0], w1v = ows[c0 + 1];
            float bb0 = b1s[c0], bb1 = b1s[c0 + 1];
            float v0 = a2[m][nt][0] + bb0;
            float v1 = a2[m][nt][1] + bb1;
            float v2 = a2[m][nt][2] + bb0;
            float v3 = a2[m][nt][3] + bb1;
            v0 = v0 > 0.f ? v0 : 0.01f * v0;
            v1 = v1 > 0.f ? v1 : 0.01f * v1;
            v2 = v2 > 0.f ? v2 : 0.01f * v2;
            v3 = v3 > 0.f ? v3 : 0.01f * v3;
            p[m][0] = fmaf(v0, w0v, p[m][0]);
            p[m][0] = fmaf(v1, w1v, p[m][0]);
            p[m][1] = fmaf(v2, w0v, p[m][1]);
            p[m][1] = fmaf(v3, w1v, p[m][1]);
        }
    #pragma unroll
    for (int off = 1; off <= 2; off <<= 1)
        #pragma unroll
        for (int m = 0; m < 4; m++) {
            p[m][0] += __shfl_xor_sync(0xffffffffu, p[m][0], off);
            p[m][1] += __shfl_xor_sync(0xffffffffu, p[m][1], off);
        }
    if (tq == 0) {
        #pragma unroll
        for (int m = 0; m < 4; m++) {
            red[wid * 64 + 16 * m + g]     = p[m][0];
            red[wid * 64 + 16 * m + g + 8] = p[m][1];
        }
    }
    __syncthreads();
    if (tid < 64) {
        float s = __ldg(ob);
        #pragma unroll
        for (int w8 = 0; w8 < 8; w8++) s += red[w8 * 64 + tid];
        val[row0 + tid] = s;
    }
}

extern "C" void kernel_launch(void* const* d_in, const int* in_sizes, int n_in,
                              void* d_out, int out_size) {
    const float* obs   = (const float*)d_in[0];
    const float* rnn   = (const float*)d_in[1];
    const float* eAW   = (const float*)d_in[2];
    const float* eAb   = (const float*)d_in[3];
    const float* eMW   = (const float*)d_in[4];
    const float* eMb   = (const float*)d_in[5];
    const float* aWih  = (const float*)d_in[6];
    const float* aWhh  = (const float*)d_in[7];
    const float* abih  = (const float*)d_in[8];
    const float* abhh  = (const float*)d_in[9];
    const float* mWih  = (const float*)d_in[10];
    const float* mWhh  = (const float*)d_in[11];
    const float* mbih  = (const float*)d_in[12];
    const float* mbhh  = (const float*)d_in[13];
    const float* Win   = (const float*)d_in[14];
    const float* bin   = (const float*)d_in[15];
    const float* Wout  = (const float*)d_in[16];
    const float* bout  = (const float*)d_in[17];
    const float* W0    = (const float*)d_in[18];
    const float* b0    = (const float*)d_in[19];
    const float* W1    = (const float*)d_in[20];
    const float* b1    = (const float*)d_in[21];
    const float* oW    = (const float*)d_in[22];
    const float* ob    = (const float*)d_in[23];

    float* out_val = (float*)d_out;
    float* out_h   = (float*)d_out + Nq;

    k_pack<<<320, 256>>>(W0, W1);
    k_packg_w<<<10, 256>>>(aWih, aWhh, abih, abhh, eAW, eAb,
                           mWih, mWhh, mbih, mbhh, eMW, eMb);
    k_packg_x<<<6144, 256>>>(obs);
    k_gru_tc<<<96, 128>>>(rnn, out_h);
    k_attn<<<Nq / 32 / 8, 256>>>(obs, Win, bin, Wout, bout);
    cudaFuncSetAttribute(k_mlp_h, cudaFuncAttributeMaxDynamicSharedMemorySize, SM_TOT);
    k_mlp_h<<<Nq / 64, 256, SM_TOT>>>(b0, b1, oW, ob, out_val);
}

// round 10
// speedup vs baseline: 2.8328x; 1.0488x over previous
#include <cuda_runtime.h>
#include <cuda_bf16.h>
#include <cstdint>

#define Bq 2048
#define Tq 128
#define Nq (Bq*Tq)

// ---------------- scratch (no allocations allowed) ----------------
__device__ float g_air[(size_t)Nq * 32];
__device__ float g_m1 [(size_t)Nq * 32];
__device__ float g_m2 [(size_t)Nq * 32];
__device__ float g_fusion[(size_t)Nq * 64];
// prepacked bf16 hi/lo MLP weights, row-major [n][k]
__device__ __nv_bfloat16 g_W0h[256 * 64];
__device__ __nv_bfloat16 g_W0l[256 * 64];
__device__ __nv_bfloat16 g_W1h[256 * 256];
__device__ __nv_bfloat16 g_W1l[256 * 256];
// GRU tensor-core prepack: B-fragments, biases, X A-fragments
__device__ uint2  g_gB[2 * 36 * 2 * 32];            // [ty][pair][part][lane] -> 2 regs
__device__ float  g_gBias[2 * 128];
__device__ uint4  g_gX[(size_t)384 * 128 * 32 * 2]; // [(group*128+t)*32+lane]*2+part

__device__ __forceinline__ float tanhap(float x) {
    float y;
    asm("tanh.approx.f32 %0, %1;" : "=f"(y) : "f"(x));
    return y;
}
__device__ __forceinline__ float fsig(float x) {           // sigmoid via tanh
    return fmaf(0.5f, tanhap(0.5f * x), 0.5f);
}
__device__ __forceinline__ float fsig_exact(float x) {
    return __fdividef(1.0f, 1.0f + __expf(-x));
}

// packed 2xfp32 FMA
union F2U { float2 f; unsigned long long u; };
__device__ __forceinline__ float2 ffma2(float2 a, float2 b, float2 c) {
    F2U A, B, C, D;
    A.f = a; B.f = b; C.f = c;
    asm("fma.rn.f32x2 %0, %1, %2, %3;" : "=l"(D.u) : "l"(A.u), "l"(B.u), "l"(C.u));
    return D.f;
}
__device__ __forceinline__ float2 dot4_2(float4 a, float4 b, float2 acc) {
    acc = ffma2(make_float2(a.x, a.y), make_float2(b.x, b.y), acc);
    acc = ffma2(make_float2(a.z, a.w), make_float2(b.z, b.w), acc);
    return acc;
}

// ---------------- mma.sync / cp.async helpers ----------------
__device__ __forceinline__ uint32_t smem_u32(const void* p) {
    uint32_t a;
    asm("{ .reg .u64 t; cvta.to.shared.u64 t, %1; cvt.u32.u64 %0, t; }" : "=r"(a) : "l"(p));
    return a;
}
__device__ __forceinline__ void ldsm4(uint32_t* a, uint32_t addr) {
    asm volatile("ldmatrix.sync.aligned.m8n8.x4.shared.b16 {%0,%1,%2,%3}, [%4];"
        : "=r"(a[0]), "=r"(a[1]), "=r"(a[2]), "=r"(a[3]) : "r"(addr));
}
__device__ __forceinline__ void ldsm2(uint32_t* b, uint32_t addr) {
    asm volatile("ldmatrix.sync.aligned.m8n8.x2.shared.b16 {%0,%1}, [%2];"
        : "=r"(b[0]), "=r"(b[1]) : "r"(addr));
}
__device__ __forceinline__ void mma16816(float* c, const uint32_t* a, const uint32_t* b) {
    asm volatile("mma.sync.aligned.m16n8k16.row.col.f32.bf16.bf16.f32 "
        "{%0,%1,%2,%3}, {%4,%5,%6,%7}, {%8,%9}, {%0,%1,%2,%3};"
        : "+f"(c[0]), "+f"(c[1]), "+f"(c[2]), "+f"(c[3])
        : "r"(a[0]), "r"(a[1]), "r"(a[2]), "r"(a[3]), "r"(b[0]), "r"(b[1]));
}
__device__ __forceinline__ void cpa16(uint32_t dst, const void* src) {
    asm volatile("cp.async.cg.shared.global [%0], [%1], 16;" :: "r"(dst), "l"(src));
}
#define CPA_COMMIT() asm volatile("cp.async.commit_group;" ::: "memory")
#define SWZ(x) ((x) ^ (((x) >> 3) & 0x70))

__device__ __forceinline__ __nv_bfloat162 split_hi(float a, float b) {
    __nv_bfloat162 h; h.x = __float2bfloat16(a); h.y = __float2bfloat16(b); return h;
}
__device__ __forceinline__ __nv_bfloat162 split_lo(float a, float b, __nv_bfloat162 h) {
    __nv_bfloat162 l;
    l.x = __float2bfloat16(a - __bfloat162float(h.x));
    l.y = __float2bfloat16(b - __bfloat162float(h.y));
    return l;
}
__device__ __forceinline__ uint32_t bf2u(__nv_bfloat162 v) {
    return *reinterpret_cast<uint32_t*>(&v);
}

// GRU tile-pair tables, kt-OUTER ordering so consecutive MMAs hit different
// accumulators (12 independent chains per kt block).
// nt 0-7: r,z; nt 8-11: hn (h only); nt 12-15: xn (x only).
#define GRU_PNT {0,1,2,3,4,5,6,7,8,9,10,11, 0,1,2,3,4,5,6,7,8,9,10,11, 0,1,2,3,4,5,6,7,12,13,14,15}
#define GRU_PKT {0,0,0,0,0,0,0,0,0,0,0,0,  1,1,1,1,1,1,1,1,1,1,1,1,   2,2,2,2,2,2,2,2,2,2,2,2}

// ================= MLP weight prepack =================
__global__ void k_pack(const float* __restrict__ W0, const float* __restrict__ W1) {
    int i = blockIdx.x * 256 + threadIdx.x;
    if (i < 16384) {
        float w = W0[i];
        __nv_bfloat16 h = __float2bfloat16(w);
        g_W0h[i] = h;
        g_W0l[i] = __float2bfloat16(w - __bfloat162float(h));
    } else if (i < 16384 + 65536) {
        int j = i - 16384;
        float w = W1[j];
        __nv_bfloat16 h = __float2bfloat16(w);
        g_W1h[j] = h;
        g_W1l[j] = __float2bfloat16(w - __bfloat162float(h));
    }
}

// ================= GRU weight/bias prepack =================
// B matrix [k=48][n=128]: cols 0-31 r, 32-63 z, 64-95 hn, 96-127 xn.
// rows 0-31 = h (Whh), rows 32-47 = x features (Wc = Wih@encW), zeros elsewhere.
__device__ __forceinline__ float gru_bval(
    int k, int n, const float* Whh, const float* Wih, const float* encW, int KIN)
{
    int blk = n >> 5, j = n & 31;
    if (k < 32) {
        if (blk == 3) return 0.f;
        return Whh[(blk * 32 + j) * 32 + k];
    }
    int f = k - 32;
    if (f >= KIN || blk == 2) return 0.f;
    int row = (blk == 3) ? 64 + j : blk * 32 + j;
    float s = 0.f;
    #pragma unroll
    for (int m = 0; m < 32; m++) s = fmaf(Wih[row * 32 + m], encW[m * KIN + f], s);
    return s;
}

__global__ void k_packg_w(
    const float* __restrict__ aWih, const float* __restrict__ aWhh,
    const float* __restrict__ abih, const float* __restrict__ abhh,
    const float* __restrict__ eAW,  const float* __restrict__ eAb,
    const float* __restrict__ mWih, const float* __restrict__ mWhh,
    const float* __restrict__ mbih, const float* __restrict__ mbhh,
    const float* __restrict__ eMW,  const float* __restrict__ eMb)
{
    const int PNT[36] = GRU_PNT;
    const int PKT[36] = GRU_PKT;
    int tid = blockIdx.x * 256 + threadIdx.x;
    if (tid < 2304) {   // B fragments: 2 types x 36 pairs x 32 lanes
        int lane = tid & 31;
        int p = (tid >> 5) % 36;
        int ty = tid / (36 * 32);
        const float* Whh = ty ? mWhh : aWhh;
        const float* Wih = ty ? mWih : aWih;
        const float* eW  = ty ? eMW  : eAW;
        int KIN = ty ? 4 : 7;
        int g = lane >> 2, tq = lane & 3;
        int n = PNT[p] * 8 + g;
        uint32_t rh[2], rl[2];
        #pragma unroll
        for (int r = 0; r < 2; r++) {
            int k0 = PKT[p] * 16 + tq * 2 + r * 8;
            float v0 = gru_bval(k0,     n, Whh, Wih, eW, KIN);
            float v1 = gru_bval(k0 + 1, n, Whh, Wih, eW, KIN);
            __nv_bfloat162 hh = split_hi(v0, v1);
            __nv_bfloat162 ll = split_lo(v0, v1, hh);
            rh[r] = bf2u(hh); rl[r] = bf2u(ll);
        }
        int base = (ty * 72 + p * 2) * 32 + lane;
        g_gB[base]      = make_uint2(rh[0], rh[1]);
        g_gB[base + 32] = make_uint2(rl[0], rl[1]);
    } else if (tid < 2304 + 256) {   // biases
        int u = tid - 2304;
        int ty = u >> 7, n = u & 127;
        const float* Wih = ty ? mWih : aWih;
        const float* bih = ty ? mbih : abih;
        const float* bhh = ty ? mbhh : abhh;
        const float* eB  = ty ? eMb  : eAb;
        int blk = n >> 5, j = n & 31;
        float b;
        if (blk == 2) {
            b = bhh[64 + j];
        } else {
            int row = (blk == 3) ? 64 + j : blk * 32 + j;
            float bc = bih[row];
            #pragma unroll
            for (int m = 0; m < 32; m++) bc = fmaf(Wih[row * 32 + m], eB[m], bc);
            b = (blk < 2) ? bc + bhh[row] : bc;
        }
        g_gBias[ty * 128 + n] = b;
    }
}

// X A-fragment prepack: per (group, t, lane) 4 hi + 4 lo regs.
__global__ void k_packg_x(const float* __restrict__ obs) {
    int tid = blockIdx.x * 256 + threadIdx.x;   // 0 .. 1572863
    int lane = tid & 31;
    int s = tid >> 5;
    int t = s & 127;
    int gr = s >> 7;                            // 0..383
    int g = lane >> 2, tq = lane & 3;

    int KIN, xoff;
    int b0;
    if (gr < 128) { KIN = 7; xoff = 8; b0 = gr * 16; }
    else {
        int gi = gr - 128;
        KIN = 4;
        xoff = (gi < 128) ? 0 : 4;
        b0 = (gi < 128) ? gi * 16 : (gi - 128) * 16;
    }
    uint32_t hr[4], lr[4];
    #pragma unroll
    for (int r = 0; r < 4; r++) {
        int row = g + 8 * (r & 1);
        int k0 = tq * 2 + (r >> 1) * 8;
        float v0 = 0.f, v1 = 0.f;
        if (k0 < KIN)
            v0 = obs[(size_t)(b0 + row) * Tq * 15 + t * 15 + xoff + k0];
        if (k0 + 1 < KIN)
            v1 = obs[(size_t)(b0 + row) * Tq * 15 + t * 15 + xoff + k0 + 1];
        __nv_bfloat162 hh = split_hi(v0, v1);
        __nv_bfloat162 ll = split_lo(v0, v1, hh);
        hr[r] = bf2u(hh); lr[r] = bf2u(ll);
    }
    size_t idx = ((size_t)(gr * 128 + t) * 32 + lane) * 2;
    g_gX[idx]     = make_uint4(hr[0], hr[1], hr[2], hr[3]);
    g_gX[idx + 1] = make_uint4(lr[0], lr[1], lr[2], lr[3]);
}

// ================= GRU: tensor-core recurrence, 1 warp per CTA ============
__global__ void __launch_bounds__(32) k_gru_tc(
    const float* __restrict__ rnn, float* __restrict__ next_h)
{
    const int PNT[36] = GRU_PNT;
    const int PKT[36] = GRU_PKT;
    int lane = threadIdx.x & 31;
    int w = blockIdx.x;                          // 0..383
    int g = lane >> 2, tq = lane & 3;

    int ty; float* featb; int ib; bool is_air = (w < 128);
    if (is_air) { ty = 0; featb = g_air; ib = w * 16; }
    else {
        ty = 1;
        int gi = w - 128;
        if (gi < 128) { featb = g_m1; ib = gi * 16; }
        else          { featb = g_m2; ib = (gi - 128) * 16; }
    }
    int gi = w - 128;

    float hv[4][4];
    #pragma unroll
    for (int nt = 0; nt < 4; nt++) {
        int col = nt * 8 + 2 * tq;
        #pragma unroll
        for (int rh = 0; rh < 2; rh++) {
            int row = g + 8 * rh;
            const float* src;
            if (is_air) src = rnn + (size_t)(w * 16 + row) * 96 + col;
            else {
                int i = gi * 16 + row;
                src = rnn + (size_t)(i >> 1) * 96 + 32 + 32 * (i & 1) + col;
            }
            float2 v = *(const float2*)src;
            hv[nt][rh * 2]     = v.x;
            hv[nt][rh * 2 + 1] = v.y;
        }
    }
    float bias[16][2];
    #pragma unroll
    for (int nt = 0; nt < 16; nt++) {
        float2 v = *(const float2*)(g_gBias + ty * 128 + nt * 8 + 2 * tq);
        bias[nt][0] = v.x; bias[nt][1] = v.y;
    }
    uint32_t Ah[2][4], Al[2][4];
    #pragma unroll
    for (int nt = 0; nt < 4; nt++) {
        int kt = nt >> 1;
        __nv_bfloat162 h01 = split_hi(hv[nt][0], hv[nt][1]);
        __nv_bfloat162 l01 = split_lo(hv[nt][0], hv[nt][1], h01);
        __nv_bfloat162 h23 = split_hi(hv[nt][2], hv[nt][3]);
        __nv_bfloat162 l23 = split_lo(hv[nt][2], hv[nt][3], h23);
        int o = (nt & 1) ? 2 : 0;
        Ah[kt][o] = bf2u(h01); Ah[kt][o + 1] = bf2u(h23);
        Al[kt][o] = bf2u(l01); Al[kt][o + 1] = bf2u(l23);
    }

    const uint2* gBb = g_gB + ty * 72 * 32 + lane;
    const uint4* gXb = g_gX + ((size_t)w * 128) * 32 * 2 + lane * 2;
    float* fr0 = featb + (size_t)(ib + g)     * Tq * 32 + 2 * tq;
    float* fr1 = featb + (size_t)(ib + g + 8) * Tq * 32 + 2 * tq;

    // X double-buffer: cur holds step t, nxt loads t+1 during MMAs
    uint4 xh_cur = gXb[0], xl_cur = gXb[1];

    #pragma unroll 1
    for (int t = 0; t < Tq; t++) {
        // issue next step's loads early (latency hidden under MMAs+epilogue)
        int tn = (t + 1 < Tq) ? t + 1 : t;
        uint4 xh_nxt = gXb[(size_t)tn * 64];
        uint4 xl_nxt = gXb[(size_t)tn * 64 + 1];

        uint32_t Xh[4] = {xh_cur.x, xh_cur.y, xh_cur.z, xh_cur.w};
        uint32_t Xl[4] = {xl_cur.x, xl_cur.y, xl_cur.z, xl_cur.w};
        float C[16][4];
        #pragma unroll
        for (int nt = 0; nt < 16; nt++) {
            C[nt][0] = bias[nt][0]; C[nt][1] = bias[nt][1];
            C[nt][2] = bias[nt][0]; C[nt][3] = bias[nt][1];
        }
        #pragma unroll
        for (int p = 0; p < 36; p++) {
            int nt = PNT[p], kt = PKT[p];
            uint2 bh = gBb[(p * 2) * 32];
            uint2 bl = gBb[(p * 2 + 1) * 32];
            const uint32_t* ah = (kt == 2) ? Xh : Ah[kt];
            const uint32_t* al = (kt == 2) ? Xl : Al[kt];
            mma16816(C[nt], ah, (const uint32_t*)&bh);
            mma16816(C[nt], ah, (const uint32_t*)&bl);
            mma16816(C[nt], al, (const uint32_t*)&bh);
        }
        #pragma unroll
        for (int nt = 0; nt < 4; nt++) {
            #pragma unroll
            for (int j = 0; j < 4; j++) {
                float r = fsig(C[nt][j]);
                float z = fsig(C[nt + 4][j]);
                float n = tanhap(fmaf(r, C[nt + 8][j], C[nt + 12][j]));
                hv[nt][j] = n + z * (hv[nt][j] - n);
            }
            *(float2*)(fr0 + (size_t)t * 32 + nt * 8) = make_float2(hv[nt][0], hv[nt][1]);
            *(float2*)(fr1 + (size_t)t * 32 + nt * 8) = make_float2(hv[nt][2], hv[nt][3]);
            int kt = nt >> 1;
            __nv_bfloat162 h01 = split_hi(hv[nt][0], hv[nt][1]);
            __nv_bfloat162 l01 = split_lo(hv[nt][0], hv[nt][1], h01);
            __nv_bfloat162 h23 = split_hi(hv[nt][2], hv[nt][3]);
            __nv_bfloat162 l23 = split_lo(hv[nt][2], hv[nt][3], h23);
            int o = (nt & 1) ? 2 : 0;
            Ah[kt][o] = bf2u(h01); Ah[kt][o + 1] = bf2u(h23);
            Al[kt][o] = bf2u(l01); Al[kt][o + 1] = bf2u(l23);
        }
        xh_cur = xh_nxt; xl_cur = xl_nxt;
    }
    #pragma unroll
    for (int nt = 0; nt < 4; nt++) {
        int col = nt * 8 + 2 * tq;
        #pragma unroll
        for (int rh = 0; rh < 2; rh++) {
            int row = g + 8 * rh;
            float2 v = make_float2(hv[nt][rh * 2], hv[nt][rh * 2 + 1]);
            float* dst;
            if (is_air) dst = next_h + (size_t)(w * 16 + row) * 96 + col;
            else {
                int i = gi * 16 + row;
                dst = next_h + (size_t)(i >> 1) * 96 + 32 + 32 * (i & 1) + col;
            }
            *(float2*)dst = v;
        }
    }
}

// ================= attention + fusion (unchanged, exact sigmoid kept) ======
__global__ void __launch_bounds__(256) k_attn(
    const float* __restrict__ obs,
    const float* __restrict__ Win, const float* __restrict__ bin,
    const float* __restrict__ Wout, const float* __restrict__ bout)
{
    __shared__ float Ws[96 * 32];
    __shared__ float Wo[32 * 32];
    __shared__ float bs[96], bo[32];
    int t = threadIdx.x;
    for (int i = t; i < 96 * 32; i += 256) Ws[i] = Win[i];
    for (int i = t; i < 32 * 32; i += 256) Wo[i] = Wout[i];
    if (t < 96) bs[t] = bin[t];
    if (t < 32) bo[t] = bout[t];
    __syncthreads();

    int warp = blockIdx.x * 8 + (t >> 5);
    int la = t & 31;
    int n = warp * 32 + la;

    float4 A[8], M1[8], M2[8];
    const float4* ap = (const float4*)(g_air + (size_t)n * 32);
    const float4* p1 = (const float4*)(g_m1 + (size_t)n * 32);
    const float4* p2 = (const float4*)(g_m2 + (size_t)n * 32);
    #pragma unroll
    for (int i = 0; i < 8; i++) { A[i] = ap[i]; M1[i] = p1[i]; M2[i] = p2[i]; }

    const float* op = obs + (size_t)n * 15;
    float o0=op[0],o1=op[1],o2=op[2],o3=op[3],o4=op[4],o5=op[5],o6=op[6],o7=op[7];
    const float T1 = 1.001e-5f, T0 = 1e-8f;
    bool mk0 = (fabsf(o0-1.f)<=T1) && (fabsf(o1)<=T0) && (fabsf(o2-1.f)<=T1) && (fabsf(o3)<=T0);
    bool mk1 = (fabsf(o4-1.f)<=T1) && (fabsf(o5)<=T0) && (fabsf(o6-1.f)<=T1) && (fabsf(o7)<=T0);

    float q[32];
    #pragma unroll
    for (int c = 0; c < 32; c++) {
        float2 a = make_float2(bs[c], 0.f);
        const float4* w = (const float4*)(Ws + c * 32);
        #pragma unroll
        for (int k = 0; k < 8; k++) a = dot4_2(A[k], w[k], a);
        q[c] = a.x + a.y;
    }
    float s1[2] = {0.f, 0.f}, s2[2] = {0.f, 0.f};
    #pragma unroll
    for (int c = 0; c < 32; c++) {
        const float4* w = (const float4*)(Ws + (32 + c) * 32);
        float2 k1 = make_float2(bs[32 + c], 0.f), k2 = make_float2(0.f, 0.f);
        #pragma unroll
        for (int k = 0; k < 8; k++) { k1 = dot4_2(M1[k], w[k], k1); k2 = dot4_2(M2[k], w[k], k2); }
        int hh = c >> 4;
        s1[hh] = fmaf(q[c], k1.x + k1.y, s1[hh]);
        s2[hh] = fmaf(q[c], k2.x + k2.y + bs[32 + c], s2[hh]);
    }
    float w1[2], w2[2];
    #pragma unroll
    for (int hh = 0; hh < 2; hh++) {
        float a = s1[hh] * 0.25f + (mk0 ? -1e9f : 0.f);
        float b = s2[hh] * 0.25f + (mk1 ? -1e9f : 0.f);
        float m = fmaxf(a, b);
        float e1 = __expf(a - m), e2 = __expf(b - m);
        float inv = __fdividef(1.0f, e1 + e2);
        w1[hh] = e1 * inv; w2[hh] = e2 * inv;
    }
    float ctx[32];
    #pragma unroll
    for (int c = 0; c < 32; c++) {
        const float4* w = (const float4*)(Ws + (64 + c) * 32);
        float2 v1 = make_float2(bs[64 + c], 0.f), v2 = make_float2(0.f, 0.f);
        #pragma unroll
        for (int k = 0; k < 8; k++) { v1 = dot4_2(M1[k], w[k], v1); v2 = dot4_2(M2[k], w[k], v2); }
        int hh = c >> 4;
        ctx[c] = w1[hh] * (v1.x + v1.y) + w2[hh] * (v2.x + v2.y + bs[64 + c]);
    }
    bool allm = mk0 && mk1;
    float at[32];
    #pragma unroll
    for (int o = 0; o < 32; o++) {
        float2 a = make_float2(bo[o], 0.f);
        const float4* w = (const float4*)(Wo + o * 32);
        #pragma unroll
        for (int c4 = 0; c4 < 8; c4++) {
            float4 cv = make_float4(ctx[4*c4], ctx[4*c4+1], ctx[4*c4+2], ctx[4*c4+3]);
            a = dot4_2(cv, w[c4], a);
        }
        at[o] = allm ? 0.0f : (a.x + a.y);
    }
    float4* fr = (float4*)(g_fusion + (size_t)n * 64);
    #pragma unroll
    for (int i = 0; i < 8; i++) fr[i] = A[i];
    #pragma unroll
    for (int i = 0; i < 8; i++)
        fr[8 + i] = make_float4(at[4*i], at[4*i+1], at[4*i+2], at[4*i+3]);
}

// ======= HMMA MLP: M=64/CTA, 2 CTAs/SM (unchanged) =======
#define SM_B0  0
#define SM_B1  1024
#define SM_OW  2048
#define SM_A1H 3072
#define SM_A1L 36864
#define SM_WB  70656
#define SM_RED 70656
#define SM_TOT 111616
#define SM_A0H 3072
#define SM_A0L 11264
#define SM_W0H 19456
#define SM_W0L 52224
#define PA1 528
#define PW1 80

__global__ void __launch_bounds__(256, 2) k_mlp_h(
    const float* __restrict__ b0, const float* __restrict__ b1,
    const float* __restrict__ oW, const float* __restrict__ ob,
    float* __restrict__ val)
{
    extern __shared__ char smem[];
    uint32_t smb = smem_u32(smem);
    int tid = threadIdx.x, wid = tid >> 5, lane = tid & 31;
    int g = lane >> 2, tq = lane & 3;
    int row0 = blockIdx.x * 64;
    int n0w = wid * 32;

    float* b0s = (float*)(smem + SM_B0);
    float* b1s = (float*)(smem + SM_B1);
    float* ows = (float*)(smem + SM_OW);
    b0s[tid] = b0[tid]; b1s[tid] = b1[tid]; ows[tid] = oW[tid];

    int aro = lane & 15;
    int aco = (lane >> 1) & 8;
    int bro = lane & 7;
    int bco = lane & 8;

    #pragma unroll
    for (int q = 0; q < 16; q++) {
        int id = tid + 256 * q;
        int part = id >> 11;
        int u = id & 2047;
        int nn = u >> 3, j = u & 7;
        uint32_t dst = smb + (part ? SM_W0L : SM_W0H) + SWZ((uint32_t)(nn * 128 + j * 16));
        const __nv_bfloat16* src = (part ? g_W0l : g_W0h) + nn * 64 + j * 8;
        cpa16(dst, src);
    }
    CPA_COMMIT();
    {
        const float4* Fg = (const float4*)g_fusion + (size_t)row0 * 16;
        #pragma unroll
        for (int q = 0; q < 4; q++) {
            int id = tid + 256 * q;
            int r = id >> 4, c4 = id & 15;
            float4 v = Fg[id];
            __nv_bfloat162 h0 = split_hi(v.x, v.y), l0 = split_lo(v.x, v.y, h0);
            __nv_bfloat162 h1 = split_hi(v.z, v.w), l1 = split_lo(v.z, v.w, h1);
            uint32_t o0 = SWZ((uint32_t)(r * 128 + c4 * 8));
            uint32_t o1 = SWZ((uint32_t)(r * 128 + c4 * 8 + 4));
            *(__nv_bfloat162*)(smem + SM_A0H + o0) = h0;
            *(__nv_bfloat162*)(smem + SM_A0H + o1) = h1;
            *(__nv_bfloat162*)(smem + SM_A0L + o0) = l0;
            *(__nv_bfloat162*)(smem + SM_A0L + o1) = l1;
        }
    }
    asm volatile("cp.async.wait_group 0;" ::: "memory");
    __syncthreads();

    float acc[4][4][4];
    #pragma unroll
    for (int m = 0; m < 4; m++)
        #pragma unroll
        for (int nt = 0; nt < 4; nt++)
            #pragma unroll
            for (int r = 0; r < 4; r++) acc[m][nt][r] = 0.f;
    #pragma unroll 1
    for (int k16 = 0; k16 < 4; k16++) {
        int kc = k16 * 16;
        uint32_t bh[4][2], bl[4][2];
        #pragma unroll
        for (int nt = 0; nt < 4; nt++) {
            uint32_t ba = SWZ((uint32_t)((n0w + 8 * nt + bro) * 128 + (kc + bco) * 2));
            ldsm2(bh[nt], smb + SM_W0H + ba);
            ldsm2(bl[nt], smb + SM_W0L + ba);
        }
        #pragma unroll
        for (int m = 0; m < 4; m++) {
            uint32_t ah[4], al[4];
            uint32_t aa = SWZ((uint32_t)((m * 16 + aro) * 128 + (kc + aco) * 2));
            ldsm4(ah, smb + SM_A0H + aa);
            ldsm4(al, smb + SM_A0L + aa);
            #pragma unroll
            for (int nt = 0; nt < 4; nt++) {
                mma16816(acc[m][nt], ah, bh[nt]);
                mma16816(acc[m][nt], ah, bl[nt]);
                mma16816(acc[m][nt], al, bh[nt]);
            }
        }
    }
    __syncthreads();

    #pragma unroll
    for (int q = 0; q < 8; q++) {
        int id = tid + 256 * q;
        int part = id >> 10;
        int u = id & 1023;
        int r = u >> 2, j = u & 3;
        const __nv_bfloat16* src = (part ? g_W1l : g_W1h) + r * 256 + j * 8;
        cpa16(smb + SM_WB + part * 20480 + r * PW1 + j * 16, src);
    }
    CPA_COMMIT();

    #pragma unroll
    for (int m = 0; m < 4; m++)
        #pragma unroll
        for (int nt = 0; nt < 4; nt++) {
            int c0 = n0w + 8 * nt + 2 * tq;
            float v0 = acc[m][nt][0] + b0s[c0];
            float v1 = acc[m][nt][1] + b0s[c0 + 1];
            float v2 = acc[m][nt][2] + b0s[c0];
            float v3 = acc[m][nt][3] + b0s[c0 + 1];
            v0 = v0 > 0.f ? v0 : 0.01f * v0;
            v1 = v1 > 0.f ? v1 : 0.01f * v1;
            v2 = v2 > 0.f ? v2 : 0.01f * v2;
            v3 = v3 > 0.f ? v3 : 0.01f * v3;
            int r0 = 16 * m + g, r1 = r0 + 8;
            __nv_bfloat162 h01 = split_hi(v0, v1), l01 = split_lo(v0, v1, h01);
            __nv_bfloat162 h23 = split_hi(v2, v3), l23 = split_lo(v2, v3, h23);
            *(__nv_bfloat162*)(smem + SM_A1H + r0 * PA1 + c0 * 2) = h01;
            *(__nv_bfloat162*)(smem + SM_A1L + r0 * PA1 + c0 * 2) = l01;
            *(__nv_bfloat162*)(smem + SM_A1H + r1 * PA1 + c0 * 2) = h23;
            *(__nv_bfloat162*)(smem + SM_A1L + r1 * PA1 + c0 * 2) = l23;
        }

    float a2[4][4][4];
    #pragma unroll
    for (int m = 0; m < 4; m++)
        #pragma unroll
        for (int nt = 0; nt < 4; nt++)
            #pragma unroll
            for (int r = 0; r < 4; r++) a2[m][nt][r] = 0.f;
    #pragma unroll 1
    for (int c = 0; c < 8; c++) {
        asm volatile("cp.async.wait_group 0;" ::: "memory");
        __syncthreads();
        uint32_t wb = smb + SM_WB;
        uint32_t bh0[4][2], bl0[4][2], bh1[4][2], bl1[4][2];
        #pragma unroll
        for (int nt = 0; nt < 4; nt++) {
            uint32_t ba0 = (uint32_t)((n0w + 8 * nt + bro) * PW1 + (bco) * 2);
            uint32_t ba1 = ba0 + 32;
            ldsm2(bh0[nt], wb + ba0);
            ldsm2(bl0[nt], wb + 20480 + ba0);
            ldsm2(bh1[nt], wb + ba1);
            ldsm2(bl1[nt], wb + 20480 + ba1);
        }
        __syncthreads();
        if (c + 1 < 8) {
            #pragma unroll
            for (int q = 0; q < 8; q++) {
                int id = tid + 256 * q;
                int part = id >> 10;
                int u = id & 1023;
                int r = u >> 2, j = u & 3;
                const __nv_bfloat16* src = (part ? g_W1l : g_W1h) + r * 256 + (c + 1) * 32 + j * 8;
                cpa16(smb + SM_WB + part * 20480 + r * PW1 + j * 16, src);
            }
            CPA_COMMIT();
        }
        #pragma unroll
        for (int m = 0; m < 4; m++) {
            uint32_t ah[4], al[4];
            uint32_t aa = (uint32_t)((m * 16 + aro) * PA1 + (c * 32 + aco) * 2);
            ldsm4(ah, smb + SM_A1H + aa);
            ldsm4(al, smb + SM_A1L + aa);
            #pragma unroll
            for (int nt = 0; nt < 4; nt++) {
                mma16816(a2[m][nt], ah, bh0[nt]);
                mma16816(a2[m][nt], ah, bl0[nt]);
                mma16816(a2[m][nt], al, bh0[nt]);
            }
            uint32_t aa1 = aa + 32;
            ldsm4(ah, smb + SM_A1H + aa1);
            ldsm4(al, smb + SM_A1L + aa1);
            #pragma unroll
            for (int nt = 0; nt < 4; nt++) {
                mma16816(a2[m][nt], ah, bh1[nt]);
                mma16816(a2[m][nt], ah, bl1[nt]);
                mma16816(a2[m][nt], al, bh1[nt]);
            }
        }
    }

    float* red = (float*)(smem + SM_RED);
    float p[4][2];
    #pragma unroll
    for (int m = 0; m < 4; m++) { p[m][0] = 0.f; p[m][1] = 0.f; }
    #pragma unroll
    for (int m = 0; m < 4; m++)
        #pragma unroll
        for (int nt = 0; nt < 4; nt++) {
            int c0 = n0w + 8 * nt + 2 * tq;
            float w0v = ows[c0], w1v = ows[c0 + 1];
            float bb0 = b1s[c0], bb1 = b1s[c0 + 1];
            float v0 = a2[m][nt][0] + bb0;
            float v1 = a2[m][nt][1] + bb1;
            float v2 = a2[m][nt][2] + bb0;
            float v3 = a2[m][nt][3] + bb1;
            v0 = v0 > 0.f ? v0 : 0.01f * v0;
            v1 = v1 > 0.f ? v1 : 0.01f * v1;
            v2 = v2 > 0.f ? v2 : 0.01f * v2;
            v3 = v3 > 0.f ? v3 : 0.01f * v3;
            p[m][0] = fmaf(v0, w0v, p[m][0]);
            p[m][0] = fmaf(v1, w1v, p[m][0]);
            p[m][1] = fmaf(v2, w0v, p[m][1]);
            p[m][1] = fmaf(v3, w1v, p[m][1]);
        }
    #pragma unroll
    for (int off = 1; off <= 2; off <<= 1)
        #pragma unroll
        for (int m = 0; m < 4; m++) {
            p[m][0] += __shfl_xor_sync(0xffffffffu, p[m][0], off);
            p[m][1] += __shfl_xor_sync(0xffffffffu, p[m][1], off);
        }
    if (tq == 0) {
        #pragma unroll
        for (int m = 0; m < 4; m++) {
            red[wid * 64 + 16 * m + g]     = p[m][0];
            red[wid * 64 + 16 * m + g + 8] = p[m][1];
        }
    }
    __syncthreads();
    if (tid < 64) {
        float s = __ldg(ob);
        #pragma unroll
        for (int w8 = 0; w8 < 8; w8++) s += red[w8 * 64 + tid];
        val[row0 + tid] = s;
    }
}

extern "C" void kernel_launch(void* const* d_in, const int* in_sizes, int n_in,
                              void* d_out, int out_size) {
    const float* obs   = (const float*)d_in[0];
    const float* rnn   = (const float*)d_in[1];
    const float* eAW   = (const float*)d_in[2];
    const float* eAb   = (const float*)d_in[3];
    const float* eMW   = (const float*)d_in[4];
    const float* eMb   = (const float*)d_in[5];
    const float* aWih  = (const float*)d_in[6];
    const float* aWhh  = (const float*)d_in[7];
    const float* abih  = (const float*)d_in[8];
    const float* abhh  = (const float*)d_in[9];
    const float* mWih  = (const float*)d_in[10];
    const float* mWhh  = (const float*)d_in[11];
    const float* mbih  = (const float*)d_in[12];
    const float* mbhh  = (const float*)d_in[13];
    const float* Win   = (const float*)d_in[14];
    const float* bin   = (const float*)d_in[15];
    const float* Wout  = (const float*)d_in[16];
    const float* bout  = (const float*)d_in[17];
    const float* W0    = (const float*)d_in[18];
    const float* b0    = (const float*)d_in[19];
    const float* W1    = (const float*)d_in[20];
    const float* b1    = (const float*)d_in[21];
    const float* oW    = (const float*)d_in[22];
    const float* ob    = (const float*)d_in[23];

    float* out_val = (float*)d_out;
    float* out_h   = (float*)d_out + Nq;

    k_pack<<<320, 256>>>(W0, W1);
    k_packg_w<<<10, 256>>>(aWih, aWhh, abih, abhh, eAW, eAb,
                           mWih, mWhh, mbih, mbhh, eMW, eMb);
    k_packg_x<<<6144, 256>>>(obs);
    k_gru_tc<<<384, 32>>>(rnn, out_h);
    k_attn<<<Nq / 32 / 8, 256>>>(obs, Win, bin, Wout, bout);
    cudaFuncSetAttribute(k_mlp_h, cudaFuncAttributeMaxDynamicSharedMemorySize, SM_TOT);
    k_mlp_h<<<Nq / 64, 256, SM_TOT>>>(b0, b1, oW, ob, out_val);
}